// round 1
// baseline (speedup 1.0000x reference)
#include <cuda_runtime.h>

#define Bsz 8
#define Ntok 1024
#define Cdim 768
#define Hh 12
#define HD 64
#define BH (Bsz*Hh)
#define SCALE 0.125f

// ---------------- scratch (device globals; no allocations) ----------------
__device__ float g_q[Bsz*Hh*Ntok*HD];                 // [b,h,n,hd]
__device__ float g_k[Bsz*Hh*Ntok*HD];
__device__ float g_v[Bsz*Hh*Ntok*HD];
__device__ float g_attn[(size_t)Bsz*Hh*Ntok*Ntok];    // [b,h,q,k] scores then p
__device__ float g_x[Bsz*Ntok*Cdim];                  // [b,n,c] attention output
__device__ __align__(16) float g_aff[Bsz*Ntok];       // sigmoid gate per (b,k)

// ---------------- QKV projection: out(m,n) = sum_k A[m,k]*W[n,k] ----------
// M=8192, N=768, K=768. blockIdx.z selects q/k/v. Scatter to [b,h,tok,hd].
__global__ void qkv_kernel(const float* __restrict__ xq, const float* __restrict__ xk,
                           const float* __restrict__ xv, const float* __restrict__ Wq,
                           const float* __restrict__ Wk, const float* __restrict__ Wv)
{
    const int z = blockIdx.z;
    const float* A = (z == 0) ? xq : (z == 1) ? xk : xv;
    const float* W = (z == 0) ? Wq : (z == 1) ? Wk : Wv;
    float* out     = (z == 0) ? g_q : (z == 1) ? g_k : g_v;

    __shared__ __align__(16) float As[16][64];
    __shared__ __align__(16) float Ws[16][64];
    const int tid = threadIdx.x, tx = tid & 15, ty = tid >> 4;
    const int row0 = blockIdx.y * 64, col0 = blockIdx.x * 64;
    float acc[4][4] = {};

    for (int k0 = 0; k0 < Cdim; k0 += 16) {
        #pragma unroll
        for (int i = 0; i < 4; i++) {
            int e = tid + i * 256;
            int r = e >> 4, c = e & 15;
            As[c][r] = A[(size_t)(row0 + r) * Cdim + k0 + c];
            Ws[c][r] = W[(size_t)(col0 + r) * Cdim + k0 + c];
        }
        __syncthreads();
        #pragma unroll
        for (int kk = 0; kk < 16; kk++) {
            float4 a = *(const float4*)&As[kk][ty * 4];
            float4 b = *(const float4*)&Ws[kk][tx * 4];
            float av[4] = {a.x, a.y, a.z, a.w};
            float bv[4] = {b.x, b.y, b.z, b.w};
            #pragma unroll
            for (int i = 0; i < 4; i++)
                #pragma unroll
                for (int j = 0; j < 4; j++)
                    acc[i][j] += av[i] * bv[j];
        }
        __syncthreads();
    }
    #pragma unroll
    for (int i = 0; i < 4; i++) {
        int m = row0 + ty * 4 + i;
        int b = m >> 10, tok = m & 1023;
        #pragma unroll
        for (int j = 0; j < 4; j++) {
            int n = col0 + tx * 4 + j;
            int h = n >> 6, hd = n & 63;
            out[(((size_t)(b * Hh + h)) * Ntok + tok) * HD + hd] = acc[i][j];
        }
    }
}

// ---------------- affinity gate: sigmoid(SCALE/H * et[b,:].kproj[b,k,:]) --
__global__ void aff_kernel(const float* __restrict__ et, float* __restrict__ out_aff)
{
    int warp = (blockIdx.x * blockDim.x + threadIdx.x) >> 5;
    int lane = threadIdx.x & 31;
    if (warp >= Bsz * Ntok) return;
    int b = warp >> 10, tok = warp & 1023;
    float s = 0.f;
    for (int c = lane; c < Cdim; c += 32) {
        int h = c >> 6, hd = c & 63;
        s += et[b * Cdim + c] * g_k[(((size_t)b * Hh + h) * Ntok + tok) * HD + hd];
    }
    #pragma unroll
    for (int o = 16; o; o >>= 1) s += __shfl_xor_sync(0xffffffffu, s, o);
    if (lane == 0) {
        float v = 1.f / (1.f + __expf(-(SCALE / Hh) * s));
        g_aff[warp] = v;
        out_aff[warp] = v;
    }
}

// ---------------- per-head scores: S = SCALE * q @ k^T  (1024x1024, K=64) -
__global__ void scores_kernel()
{
    const int z = blockIdx.z;
    const float* A  = g_q + (size_t)z * Ntok * HD;
    const float* Bm = g_k + (size_t)z * Ntok * HD;
    float* out = g_attn + (size_t)z * Ntok * Ntok;

    __shared__ __align__(16) float As[16][64];
    __shared__ __align__(16) float Bs[16][64];
    const int tid = threadIdx.x, tx = tid & 15, ty = tid >> 4;
    const int row0 = blockIdx.y * 64, col0 = blockIdx.x * 64;
    float acc[4][4] = {};

    for (int k0 = 0; k0 < HD; k0 += 16) {
        #pragma unroll
        for (int i = 0; i < 4; i++) {
            int e = tid + i * 256;
            int r = e >> 4, c = e & 15;
            As[c][r] = A[(size_t)(row0 + r) * HD + k0 + c];
            Bs[c][r] = Bm[(size_t)(col0 + r) * HD + k0 + c];
        }
        __syncthreads();
        #pragma unroll
        for (int kk = 0; kk < 16; kk++) {
            float4 a = *(const float4*)&As[kk][ty * 4];
            float4 b = *(const float4*)&Bs[kk][tx * 4];
            float av[4] = {a.x, a.y, a.z, a.w};
            float bv[4] = {b.x, b.y, b.z, b.w};
            #pragma unroll
            for (int i = 0; i < 4; i++)
                #pragma unroll
                for (int j = 0; j < 4; j++)
                    acc[i][j] += av[i] * bv[j];
        }
        __syncthreads();
    }
    #pragma unroll
    for (int i = 0; i < 4; i++)
        #pragma unroll
        for (int j = 0; j < 4; j++)
            out[(size_t)(row0 + ty * 4 + i) * Ntok + col0 + tx * 4 + j] = acc[i][j] * SCALE;
}

// ---------------- attn_save = (1/H) * sum_h attn[b,h,:,:] -----------------
__global__ void attnsave_kernel(float* __restrict__ out_as)
{
    size_t idx = (size_t)blockIdx.x * 256 + threadIdx.x;  // over B*N*N/4
    int k4 = (int)(idx & 255);
    size_t bq = idx >> 8;          // b*1024 + q
    int b = (int)(bq >> 10);
    int q = (int)(bq & 1023);
    float4 s = make_float4(0.f, 0.f, 0.f, 0.f);
    #pragma unroll
    for (int h = 0; h < Hh; h++) {
        const float4* p = (const float4*)(g_attn + ((size_t)(b * Hh + h) * Ntok + q) * Ntok);
        float4 v = p[k4];
        s.x += v.x; s.y += v.y; s.z += v.z; s.w += v.w;
    }
    const float inv = 1.f / Hh;
    s.x *= inv; s.y *= inv; s.z *= inv; s.w *= inv;
    ((float4*)out_as)[bq * 256 + k4] = s;
}

// ---------------- softmax row (length 1024) * aff gate, in place ----------
__global__ void softmax_kernel()
{
    size_t rowid = blockIdx.x;               // z*1024 + q
    int z = (int)(rowid >> 10);
    int b = z / Hh;
    float4* row = (float4*)(g_attn + rowid * (size_t)Ntok);
    int t = threadIdx.x;
    float4 v = row[t];

    __shared__ float shm[8];
    __shared__ float shs[8];
    int lane = t & 31, w = t >> 5;

    float m = fmaxf(fmaxf(v.x, v.y), fmaxf(v.z, v.w));
    #pragma unroll
    for (int o = 16; o; o >>= 1) m = fmaxf(m, __shfl_xor_sync(0xffffffffu, m, o));
    if (lane == 0) shm[w] = m;
    __syncthreads();
    m = shm[0];
    #pragma unroll
    for (int i = 1; i < 8; i++) m = fmaxf(m, shm[i]);

    v.x = __expf(v.x - m); v.y = __expf(v.y - m);
    v.z = __expf(v.z - m); v.w = __expf(v.w - m);
    float s = v.x + v.y + v.z + v.w;
    #pragma unroll
    for (int o = 16; o; o >>= 1) s += __shfl_xor_sync(0xffffffffu, s, o);
    if (lane == 0) shs[w] = s;
    __syncthreads();
    s = shs[0];
    #pragma unroll
    for (int i = 1; i < 8; i++) s += shs[i];
    float inv = 1.f / s;

    const float4* affp = (const float4*)(g_aff + b * Ntok);
    float4 a = affp[t];
    v.x *= inv * a.x; v.y *= inv * a.y; v.z *= inv * a.z; v.w *= inv * a.w;
    row[t] = v;
}

// ---------------- x = p @ v : (1024x1024)@(1024x64) per (b,h) -------------
__global__ void pv_kernel()
{
    const int z = blockIdx.z;
    const int b = z / Hh, h = z % Hh;
    const float* P = g_attn + (size_t)z * Ntok * Ntok;
    const float* V = g_v   + (size_t)z * Ntok * HD;

    __shared__ __align__(16) float Ps[16][64];
    __shared__ __align__(16) float Vs[16][64];
    const int tid = threadIdx.x, tx = tid & 15, ty = tid >> 4;
    const int row0 = blockIdx.y * 64;
    float acc[4][4] = {};

    for (int k0 = 0; k0 < Ntok; k0 += 16) {
        #pragma unroll
        for (int i = 0; i < 4; i++) {
            int e = tid + i * 256;
            { int r = e >> 4, c = e & 15; Ps[c][r] = P[(size_t)(row0 + r) * Ntok + k0 + c]; }
            { int kk = e >> 6, n = e & 63; Vs[kk][n] = V[(size_t)(k0 + kk) * HD + n]; }
        }
        __syncthreads();
        #pragma unroll
        for (int kk = 0; kk < 16; kk++) {
            float4 a = *(const float4*)&Ps[kk][ty * 4];
            float4 v = *(const float4*)&Vs[kk][tx * 4];
            float av[4] = {a.x, a.y, a.z, a.w};
            float bv[4] = {v.x, v.y, v.z, v.w};
            #pragma unroll
            for (int i = 0; i < 4; i++)
                #pragma unroll
                for (int j = 0; j < 4; j++)
                    acc[i][j] += av[i] * bv[j];
        }
        __syncthreads();
    }
    #pragma unroll
    for (int i = 0; i < 4; i++) {
        int m = row0 + ty * 4 + i;
        #pragma unroll
        for (int j = 0; j < 4; j++) {
            int n = tx * 4 + j;
            g_x[((size_t)b * Ntok + m) * Cdim + h * HD + n] = acc[i][j];
        }
    }
}

// ---------------- out = x @ Wp^T + bp : M=8192, N=768, K=768 --------------
__global__ void proj_kernel(const float* __restrict__ Wp, const float* __restrict__ bp,
                            float* __restrict__ out)
{
    __shared__ __align__(16) float As[16][64];
    __shared__ __align__(16) float Ws[16][64];
    const int tid = threadIdx.x, tx = tid & 15, ty = tid >> 4;
    const int row0 = blockIdx.y * 64, col0 = blockIdx.x * 64;
    float acc[4][4] = {};

    for (int k0 = 0; k0 < Cdim; k0 += 16) {
        #pragma unroll
        for (int i = 0; i < 4; i++) {
            int e = tid + i * 256;
            int r = e >> 4, c = e & 15;
            As[c][r] = g_x[(size_t)(row0 + r) * Cdim + k0 + c];
            Ws[c][r] = Wp[(size_t)(col0 + r) * Cdim + k0 + c];
        }
        __syncthreads();
        #pragma unroll
        for (int kk = 0; kk < 16; kk++) {
            float4 a = *(const float4*)&As[kk][ty * 4];
            float4 b = *(const float4*)&Ws[kk][tx * 4];
            float av[4] = {a.x, a.y, a.z, a.w};
            float bv[4] = {b.x, b.y, b.z, b.w};
            #pragma unroll
            for (int i = 0; i < 4; i++)
                #pragma unroll
                for (int j = 0; j < 4; j++)
                    acc[i][j] += av[i] * bv[j];
        }
        __syncthreads();
    }
    #pragma unroll
    for (int i = 0; i < 4; i++) {
        int m = row0 + ty * 4 + i;
        #pragma unroll
        for (int j = 0; j < 4; j++) {
            int n = col0 + tx * 4 + j;
            out[(size_t)m * Cdim + n] = acc[i][j] + bp[n];
        }
    }
}

// ---------------------------------------------------------------------------
extern "C" void kernel_launch(void* const* d_in, const int* in_sizes, int n_in,
                              void* d_out, int out_size)
{
    (void)in_sizes; (void)n_in; (void)out_size;
    const float* xq = (const float*)d_in[0];
    const float* xk = (const float*)d_in[1];
    const float* xv = (const float*)d_in[2];
    const float* et = (const float*)d_in[3];
    const float* Wq = (const float*)d_in[4];
    const float* Wk = (const float*)d_in[5];
    const float* Wv = (const float*)d_in[6];
    const float* Wp = (const float*)d_in[7];
    const float* bp = (const float*)d_in[8];

    float* out      = (float*)d_out;
    float* out_x    = out;                                   // B*N*C   = 6291456
    float* out_as   = out + (size_t)Bsz * Ntok * Cdim;       // B*N*N   = 8388608
    float* out_aff  = out_as + (size_t)Bsz * Ntok * Ntok;    // B*N     = 8192

    qkv_kernel<<<dim3(Cdim / 64, (Bsz * Ntok) / 64, 3), 256>>>(xq, xk, xv, Wq, Wk, Wv);
    aff_kernel<<<(Bsz * Ntok) / 8, 256>>>(et, out_aff);
    scores_kernel<<<dim3(Ntok / 64, Ntok / 64, BH), 256>>>();
    attnsave_kernel<<<(Bsz * Ntok * Ntok / 4) / 256, 256>>>(out_as);
    softmax_kernel<<<BH * Ntok, 256>>>();
    pv_kernel<<<dim3(1, Ntok / 64, BH), 256>>>();
    proj_kernel<<<dim3(Cdim / 64, (Bsz * Ntok) / 64, 1), 256>>>(Wp, bp, out_x);
}

// round 3
// speedup vs baseline: 3.3965x; 3.3965x over previous
#include <cuda_runtime.h>
#include <cuda_bf16.h>
#include <cstdint>

#define Bsz 8
#define Ntok 1024
#define Cdim 768
#define Hh 12
#define HD 64
#define BH (Bsz*Hh)
#define SCALE 0.125f

// ======================= warp MMA helpers (sm_80+ baseline PTX) =============
__device__ __forceinline__ uint32_t smem_to_u32(const void* p) {
    uint32_t a;
    asm("{ .reg .u64 t; cvta.to.shared.u64 t, %1; cvt.u32.u64 %0, t; }" : "=r"(a) : "l"(p));
    return a;
}
#define LDSM4(r, addr) \
    asm volatile("ldmatrix.sync.aligned.m8n8.x4.shared.b16 {%0,%1,%2,%3}, [%4];" \
        : "=r"((r)[0]), "=r"((r)[1]), "=r"((r)[2]), "=r"((r)[3]) : "r"(addr))
#define MMA_BF16(d, a, b) \
    asm volatile("mma.sync.aligned.m16n8k16.row.col.f32.bf16.bf16.f32 " \
        "{%0,%1,%2,%3}, {%4,%5,%6,%7}, {%8,%9}, {%0,%1,%2,%3};" \
        : "+f"((d)[0]), "+f"((d)[1]), "+f"((d)[2]), "+f"((d)[3]) \
        : "r"((a)[0]), "r"((a)[1]), "r"((a)[2]), "r"((a)[3]), "r"((b)[0]), "r"((b)[1]))

// ======================= scratch globals ====================================
__device__ __align__(16) __nv_bfloat16 g_xh[3u * 8192u * 768u];   // xq|xk|xv hi
__device__ __align__(16) __nv_bfloat16 g_xl[3u * 8192u * 768u];
__device__ __align__(16) __nv_bfloat16 g_wh[4u * 768u * 768u];    // Wq|Wk|Wv|Wp hi
__device__ __align__(16) __nv_bfloat16 g_wl[4u * 768u * 768u];
__device__ __align__(16) __nv_bfloat16 g_qh[BH * Ntok * HD];      // [b,h,tok,hd]
__device__ __align__(16) __nv_bfloat16 g_ql[BH * Ntok * HD];
__device__ __align__(16) __nv_bfloat16 g_kh[BH * Ntok * HD];
__device__ __align__(16) __nv_bfloat16 g_kl[BH * Ntok * HD];
__device__ __align__(16) __nv_bfloat16 g_vth[BH * HD * Ntok];     // [b,h,hd,tok]
__device__ __align__(16) __nv_bfloat16 g_vtl[BH * HD * Ntok];
__device__ float g_attn[(size_t)BH * Ntok * Ntok];                // fp32 scores
__device__ __align__(16) __nv_bfloat16 g_ph[(size_t)BH * Ntok * Ntok];
__device__ __align__(16) __nv_bfloat16 g_pl[(size_t)BH * Ntok * Ntok];
__device__ __align__(16) __nv_bfloat16 g_oh[8192u * 768u];        // attention out hi
__device__ __align__(16) __nv_bfloat16 g_ol[8192u * 768u];
__device__ __align__(16) float g_aff[Bsz * Ntok];

// ======================= fp32 -> bf16 hi/lo split ===========================
__global__ void cvt_kernel(const float4* __restrict__ src, __nv_bfloat16* __restrict__ hi,
                           __nv_bfloat16* __restrict__ lo, int n4)
{
    int i = blockIdx.x * 256 + threadIdx.x;
    if (i >= n4) return;
    float4 v = src[i];
    __nv_bfloat16 h0 = __float2bfloat16(v.x), h1 = __float2bfloat16(v.y);
    __nv_bfloat16 h2 = __float2bfloat16(v.z), h3 = __float2bfloat16(v.w);
    __nv_bfloat16 l0 = __float2bfloat16(v.x - __bfloat162float(h0));
    __nv_bfloat16 l1 = __float2bfloat16(v.y - __bfloat162float(h1));
    __nv_bfloat16 l2 = __float2bfloat16(v.z - __bfloat162float(h2));
    __nv_bfloat16 l3 = __float2bfloat16(v.w - __bfloat162float(h3));
    ((__nv_bfloat162*)hi)[i * 2]     = __nv_bfloat162(h0, h1);
    ((__nv_bfloat162*)hi)[i * 2 + 1] = __nv_bfloat162(h2, h3);
    ((__nv_bfloat162*)lo)[i * 2]     = __nv_bfloat162(l0, l1);
    ((__nv_bfloat162*)lo)[i * 2 + 1] = __nv_bfloat162(l2, l3);
}

// ======================= generic mma.sync GEMM ==============================
// C[128, BN] = Ah@Bh^T + Ah@Bl^T + Al@Bh^T.  A [128,K] K-major (lda halves),
// B [BN,K] K-major. Result left in SMEM stage, stride BN+1 floats. 256 thr.
template <int BN>
__device__ __forceinline__ void gemm_to_stage(
    const __nv_bfloat16* __restrict__ Ah, const __nv_bfloat16* __restrict__ Al, int lda,
    const __nv_bfloat16* __restrict__ Bh, const __nv_bfloat16* __restrict__ Bl, int ldb,
    int kTotal, char* smem)
{
    constexpr int SROW = 40;                    // halves per smem row (32 + 8 pad)
    constexpr int A_H0 = 0;
    constexpr int A_L0 = 128 * SROW;            // 5120
    constexpr int B_H0 = 2 * 128 * SROW;        // 10240
    constexpr int B_L0 = B_H0 + BN * SROW;
    constexpr int BUFH = B_H0 + 2 * BN * SROW;  // halves per buffer
    constexpr int WN = BN / 2;                  // warp n extent
    constexpr int NT = BN / 16;                 // n8-tiles per warp
    constexpr int NTP = NT / 2;
    constexpr int NBJ = BN / 64;                // uint4 loads/thread per B matrix

    __nv_bfloat16* sm = (__nv_bfloat16*)smem;
    const uint32_t sbase = smem_to_u32(smem);
    const int tid = threadIdx.x, lane = tid & 31, wid = tid >> 5;
    const int wm = wid & 3, wn = wid >> 2;

    float acc[2][NT][4];
    #pragma unroll
    for (int i = 0; i < 2; i++)
        #pragma unroll
        for (int j = 0; j < NT; j++)
            #pragma unroll
            for (int l = 0; l < 4; l++) acc[i][j][l] = 0.f;

    uint4 ra_h[2], ra_l[2], rb_h[NBJ], rb_l[NBJ];

    auto LDG = [&](int k0) {
        #pragma unroll
        for (int j = 0; j < 2; j++) {
            int i = tid + j * 256, r = i >> 2, c = (i & 3) << 3;
            ra_h[j] = *(const uint4*)(Ah + (size_t)r * lda + k0 + c);
            ra_l[j] = *(const uint4*)(Al + (size_t)r * lda + k0 + c);
        }
        #pragma unroll
        for (int j = 0; j < NBJ; j++) {
            int i = tid + j * 256, r = i >> 2, c = (i & 3) << 3;
            rb_h[j] = *(const uint4*)(Bh + (size_t)r * ldb + k0 + c);
            rb_l[j] = *(const uint4*)(Bl + (size_t)r * ldb + k0 + c);
        }
    };
    auto STS = [&](int buf) {
        __nv_bfloat16* p = sm + buf * BUFH;
        #pragma unroll
        for (int j = 0; j < 2; j++) {
            int i = tid + j * 256, r = i >> 2, c = (i & 3) << 3;
            *(uint4*)(p + A_H0 + r * SROW + c) = ra_h[j];
            *(uint4*)(p + A_L0 + r * SROW + c) = ra_l[j];
        }
        #pragma unroll
        for (int j = 0; j < NBJ; j++) {
            int i = tid + j * 256, r = i >> 2, c = (i & 3) << 3;
            *(uint4*)(p + B_H0 + r * SROW + c) = rb_h[j];
            *(uint4*)(p + B_L0 + r * SROW + c) = rb_l[j];
        }
    };
    auto COMPUTE = [&](int buf) {
        const uint32_t base = sbase + (uint32_t)buf * BUFH * 2;
        #pragma unroll
        for (int ks = 0; ks < 32; ks += 16) {
            uint32_t ah[2][4], al2[2][4];
            const int arow = (lane & 7) + ((lane >> 3) & 1) * 8;
            const int acol = ks + (lane >> 4) * 8;
            #pragma unroll
            for (int mt = 0; mt < 2; mt++) {
                uint32_t off = (uint32_t)((wm * 32 + mt * 16 + arow) * SROW + acol) * 2;
                LDSM4(ah[mt],  base + A_H0 * 2 + off);
                LDSM4(al2[mt], base + A_L0 * 2 + off);
            }
            uint32_t bh[NT][2], bl2[NT][2];
            const int g = lane >> 3;
            const int brow = (g >> 1) * 8 + (lane & 7);
            const int bcol = ks + (g & 1) * 8;
            #pragma unroll
            for (int np = 0; np < NTP; np++) {
                uint32_t off = (uint32_t)((wn * WN + np * 16 + brow) * SROW + bcol) * 2;
                uint32_t t[4];
                LDSM4(t, base + B_H0 * 2 + off);
                bh[2 * np][0] = t[0]; bh[2 * np][1] = t[1];
                bh[2 * np + 1][0] = t[2]; bh[2 * np + 1][1] = t[3];
                LDSM4(t, base + B_L0 * 2 + off);
                bl2[2 * np][0] = t[0]; bl2[2 * np][1] = t[1];
                bl2[2 * np + 1][0] = t[2]; bl2[2 * np + 1][1] = t[3];
            }
            #pragma unroll
            for (int mt = 0; mt < 2; mt++)
                #pragma unroll
                for (int nt = 0; nt < NT; nt++) {
                    MMA_BF16(acc[mt][nt], ah[mt],  bh[nt]);
                    MMA_BF16(acc[mt][nt], ah[mt],  bl2[nt]);
                    MMA_BF16(acc[mt][nt], al2[mt], bh[nt]);
                }
        }
    };

    const int nCh = kTotal >> 5;
    LDG(0);
    STS(0);
    __syncthreads();
    for (int ch = 0; ch < nCh; ch++) {
        if (ch + 1 < nCh) LDG((ch + 1) << 5);
        COMPUTE(ch & 1);
        if (ch + 1 < nCh) STS((ch + 1) & 1);
        __syncthreads();
    }

    // write accumulators to stage (aliases operand smem; last sync done above)
    float* stage = (float*)smem;
    const int gidr = lane >> 2, qid = lane & 3;
    #pragma unroll
    for (int mt = 0; mt < 2; mt++)
        #pragma unroll
        for (int nt = 0; nt < NT; nt++) {
            int row = wm * 32 + mt * 16 + gidr;
            int col = wn * WN + nt * 8 + qid * 2;
            stage[row * (BN + 1) + col]           = acc[mt][nt][0];
            stage[row * (BN + 1) + col + 1]       = acc[mt][nt][1];
            stage[(row + 8) * (BN + 1) + col]     = acc[mt][nt][2];
            stage[(row + 8) * (BN + 1) + col + 1] = acc[mt][nt][3];
        }
    __syncthreads();
}

// ======================= QKV projection =====================================
__global__ void __launch_bounds__(256, 1) qkv_mma()
{
    extern __shared__ char smem[];
    const int z = blockIdx.z;
    const int m0 = blockIdx.y * 128, n0 = blockIdx.x * 128;

    const __nv_bfloat16* Ah = g_xh + (size_t)z * 8192 * 768 + (size_t)m0 * 768;
    const __nv_bfloat16* Al = g_xl + (size_t)z * 8192 * 768 + (size_t)m0 * 768;
    const __nv_bfloat16* Bh = g_wh + (size_t)z * 768 * 768 + (size_t)n0 * 768;
    const __nv_bfloat16* Bl = g_wl + (size_t)z * 768 * 768 + (size_t)n0 * 768;

    gemm_to_stage<128>(Ah, Al, 768, Bh, Bl, 768, 768, smem);
    float* stage = (float*)smem;

    const int tid = threadIdx.x;
    if (z < 2) {
        __nv_bfloat16* dh = (z == 0) ? g_qh : g_kh;
        __nv_bfloat16* dl = (z == 0) ? g_ql : g_kl;
        for (int idx = tid; idx < 128 * 128; idx += 256) {
            int mr = idx >> 7, nc = idx & 127;
            int m = m0 + mr, n = n0 + nc;
            int b = m >> 10, tok = m & 1023, h = n >> 6, hd = n & 63;
            float v = stage[mr * 129 + nc];
            __nv_bfloat16 hi = __float2bfloat16(v);
            __nv_bfloat16 lo = __float2bfloat16(v - __bfloat162float(hi));
            size_t o = (((size_t)(b * Hh + h)) * Ntok + tok) * HD + hd;
            dh[o] = hi; dl[o] = lo;
        }
    } else {
        for (int idx = tid; idx < 128 * 128; idx += 256) {
            int mr = idx & 127, nc = idx >> 7;
            int m = m0 + mr, n = n0 + nc;
            int b = m >> 10, tok = m & 1023, h = n >> 6, hd = n & 63;
            float v = stage[mr * 129 + nc];
            __nv_bfloat16 hi = __float2bfloat16(v);
            __nv_bfloat16 lo = __float2bfloat16(v - __bfloat162float(hi));
            size_t o = (((size_t)(b * Hh + h)) * HD + hd) * Ntok + tok;
            g_vth[o] = hi; g_vtl[o] = lo;
        }
    }
}

// ======================= affinity gate ======================================
__global__ void aff_kernel(const float* __restrict__ et, float* __restrict__ out_aff)
{
    int warp = (blockIdx.x * blockDim.x + threadIdx.x) >> 5;
    int lane = threadIdx.x & 31;
    if (warp >= Bsz * Ntok) return;
    int b = warp >> 10, tok = warp & 1023;
    float s = 0.f;
    for (int c = lane; c < Cdim; c += 32) {
        int h = c >> 6, hd = c & 63;
        size_t o = (((size_t)(b * Hh + h)) * Ntok + tok) * HD + hd;
        float kv = __bfloat162float(g_kh[o]) + __bfloat162float(g_kl[o]);
        s += et[b * Cdim + c] * kv;
    }
    #pragma unroll
    for (int o = 16; o; o >>= 1) s += __shfl_xor_sync(0xffffffffu, s, o);
    if (lane == 0) {
        float v = 1.f / (1.f + __expf(-(SCALE / Hh) * s));
        g_aff[warp] = v;
        out_aff[warp] = v;
    }
}

// ======================= scores =============================================
__global__ void __launch_bounds__(256, 1) scores_mma()
{
    extern __shared__ char smem[];
    const int z = blockIdx.z;
    const int m0 = blockIdx.y * 128, n0 = blockIdx.x * 128;

    const __nv_bfloat16* Ah = g_qh + (size_t)z * Ntok * HD + (size_t)m0 * HD;
    const __nv_bfloat16* Al = g_ql + (size_t)z * Ntok * HD + (size_t)m0 * HD;
    const __nv_bfloat16* Bh = g_kh + (size_t)z * Ntok * HD + (size_t)n0 * HD;
    const __nv_bfloat16* Bl = g_kl + (size_t)z * Ntok * HD + (size_t)n0 * HD;

    gemm_to_stage<128>(Ah, Al, HD, Bh, Bl, HD, HD, smem);
    float* stage = (float*)smem;

    float* out = g_attn + (size_t)z * Ntok * Ntok;
    for (int idx = threadIdx.x; idx < 128 * 128; idx += 256) {
        int mr = idx >> 7, nc = idx & 127;
        out[(size_t)(m0 + mr) * Ntok + n0 + nc] = stage[mr * 129 + nc] * SCALE;
    }
}

// ======================= attn_save ==========================================
__global__ void attnsave_kernel(float* __restrict__ out_as)
{
    size_t idx = (size_t)blockIdx.x * 256 + threadIdx.x;
    int k4 = (int)(idx & 255);
    size_t bq = idx >> 8;
    int b = (int)(bq >> 10);
    float4 s = make_float4(0.f, 0.f, 0.f, 0.f);
    int q = (int)(bq & 1023);
    #pragma unroll
    for (int h = 0; h < Hh; h++) {
        const float4* p = (const float4*)(g_attn + ((size_t)(b * Hh + h) * Ntok + q) * Ntok);
        float4 v = p[k4];
        s.x += v.x; s.y += v.y; s.z += v.z; s.w += v.w;
    }
    const float inv = 1.f / Hh;
    s.x *= inv; s.y *= inv; s.z *= inv; s.w *= inv;
    ((float4*)out_as)[bq * 256 + k4] = s;
}

// ======================= softmax * gate -> p hi/lo ==========================
__global__ void softmax_kernel()
{
    size_t rowid = blockIdx.x;                 // z*1024 + q
    int z = (int)(rowid >> 10);
    int b = z / Hh;
    const float4* row = (const float4*)(g_attn + rowid * (size_t)Ntok);
    int t = threadIdx.x;
    float4 v = row[t];

    __shared__ float shm[8];
    __shared__ float shs[8];
    int lane = t & 31, w = t >> 5;

    float m = fmaxf(fmaxf(v.x, v.y), fmaxf(v.z, v.w));
    #pragma unroll
    for (int o = 16; o; o >>= 1) m = fmaxf(m, __shfl_xor_sync(0xffffffffu, m, o));
    if (lane == 0) shm[w] = m;
    __syncthreads();
    m = shm[0];
    #pragma unroll
    for (int i = 1; i < 8; i++) m = fmaxf(m, shm[i]);

    v.x = __expf(v.x - m); v.y = __expf(v.y - m);
    v.z = __expf(v.z - m); v.w = __expf(v.w - m);
    float s = v.x + v.y + v.z + v.w;
    #pragma unroll
    for (int o = 16; o; o >>= 1) s += __shfl_xor_sync(0xffffffffu, s, o);
    if (lane == 0) shs[w] = s;
    __syncthreads();
    s = shs[0];
    #pragma unroll
    for (int i = 1; i < 8; i++) s += shs[i];
    float inv = 1.f / s;

    const float4* affp = (const float4*)(g_aff + b * Ntok);
    float4 a = affp[t];
    v.x *= inv * a.x; v.y *= inv * a.y; v.z *= inv * a.z; v.w *= inv * a.w;

    __nv_bfloat16 h0 = __float2bfloat16(v.x), h1 = __float2bfloat16(v.y);
    __nv_bfloat16 h2 = __float2bfloat16(v.z), h3 = __float2bfloat16(v.w);
    __nv_bfloat16 l0 = __float2bfloat16(v.x - __bfloat162float(h0));
    __nv_bfloat16 l1 = __float2bfloat16(v.y - __bfloat162float(h1));
    __nv_bfloat16 l2 = __float2bfloat16(v.z - __bfloat162float(h2));
    __nv_bfloat16 l3 = __float2bfloat16(v.w - __bfloat162float(h3));
    __nv_bfloat162* ph = (__nv_bfloat162*)(g_ph + rowid * (size_t)Ntok);
    __nv_bfloat162* pl = (__nv_bfloat162*)(g_pl + rowid * (size_t)Ntok);
    ph[t * 2]     = __nv_bfloat162(h0, h1);
    ph[t * 2 + 1] = __nv_bfloat162(h2, h3);
    pl[t * 2]     = __nv_bfloat162(l0, l1);
    pl[t * 2 + 1] = __nv_bfloat162(l2, l3);
}

// ======================= PV =================================================
__global__ void __launch_bounds__(256, 1) pv_mma()
{
    extern __shared__ char smem[];
    const int z = blockIdx.z;
    const int m0 = blockIdx.y * 128;
    const int b = z / Hh, h = z % Hh;

    const __nv_bfloat16* Ah = g_ph + (size_t)z * Ntok * Ntok + (size_t)m0 * Ntok;
    const __nv_bfloat16* Al = g_pl + (size_t)z * Ntok * Ntok + (size_t)m0 * Ntok;
    const __nv_bfloat16* Bh = g_vth + (size_t)z * HD * Ntok;
    const __nv_bfloat16* Bl = g_vtl + (size_t)z * HD * Ntok;

    gemm_to_stage<64>(Ah, Al, Ntok, Bh, Bl, Ntok, Ntok, smem);
    float* stage = (float*)smem;

    for (int idx = threadIdx.x; idx < 128 * 64; idx += 256) {
        int mr = idx >> 6, nc = idx & 63;
        int m = m0 + mr;
        float v = stage[mr * 65 + nc];
        __nv_bfloat16 hi = __float2bfloat16(v);
        __nv_bfloat16 lo = __float2bfloat16(v - __bfloat162float(hi));
        size_t o = ((size_t)b * Ntok + m) * Cdim + h * HD + nc;
        g_oh[o] = hi; g_ol[o] = lo;
    }
}

// ======================= output projection ==================================
__global__ void __launch_bounds__(256, 1) proj_mma(const float* __restrict__ bp,
                                                   float* __restrict__ out)
{
    extern __shared__ char smem[];
    const int m0 = blockIdx.y * 128, n0 = blockIdx.x * 128;

    const __nv_bfloat16* Ah = g_oh + (size_t)m0 * 768;
    const __nv_bfloat16* Al = g_ol + (size_t)m0 * 768;
    const __nv_bfloat16* Bh = g_wh + (size_t)3 * 768 * 768 + (size_t)n0 * 768;
    const __nv_bfloat16* Bl = g_wl + (size_t)3 * 768 * 768 + (size_t)n0 * 768;

    gemm_to_stage<128>(Ah, Al, 768, Bh, Bl, 768, 768, smem);
    float* stage = (float*)smem;

    for (int idx = threadIdx.x; idx < 128 * 128; idx += 256) {
        int mr = idx >> 7, nc = idx & 127;
        int n = n0 + nc;
        out[(size_t)(m0 + mr) * Cdim + n] = stage[mr * 129 + nc] + bp[n];
    }
}

// ============================================================================
extern "C" void kernel_launch(void* const* d_in, const int* in_sizes, int n_in,
                              void* d_out, int out_size)
{
    (void)in_sizes; (void)n_in; (void)out_size;
    const float* xq = (const float*)d_in[0];
    const float* xk = (const float*)d_in[1];
    const float* xv = (const float*)d_in[2];
    const float* et = (const float*)d_in[3];
    const float* Wq = (const float*)d_in[4];
    const float* Wk = (const float*)d_in[5];
    const float* Wv = (const float*)d_in[6];
    const float* Wp = (const float*)d_in[7];
    const float* bp = (const float*)d_in[8];

    float* out     = (float*)d_out;
    float* out_x   = out;
    float* out_as  = out + (size_t)Bsz * Ntok * Cdim;
    float* out_aff = out_as + (size_t)Bsz * Ntok * Ntok;

    // smem: BN=128 kernels need max(2 bufs = 81920B, stage 66048B) = 81920
    //       BN=64 (pv)  needs max(61440, 33280) = 61440
    const int SMEM_BIG = 81920, SMEM_PV = 61440;
    cudaFuncSetAttribute(qkv_mma,    cudaFuncAttributeMaxDynamicSharedMemorySize, SMEM_BIG);
    cudaFuncSetAttribute(scores_mma, cudaFuncAttributeMaxDynamicSharedMemorySize, SMEM_BIG);
    cudaFuncSetAttribute(pv_mma,     cudaFuncAttributeMaxDynamicSharedMemorySize, SMEM_PV);
    cudaFuncSetAttribute(proj_mma,   cudaFuncAttributeMaxDynamicSharedMemorySize, SMEM_BIG);

    __nv_bfloat16 *xh, *xl, *wh, *wl;
    cudaGetSymbolAddress((void**)&xh, g_xh);
    cudaGetSymbolAddress((void**)&xl, g_xl);
    cudaGetSymbolAddress((void**)&wh, g_wh);
    cudaGetSymbolAddress((void**)&wl, g_wl);

    const int NX = 8192 * 768, NW = 768 * 768;
    cvt_kernel<<<(NX / 4 + 255) / 256, 256>>>((const float4*)xq, xh + 0 * (size_t)NX, xl + 0 * (size_t)NX, NX / 4);
    cvt_kernel<<<(NX / 4 + 255) / 256, 256>>>((const float4*)xk, xh + 1 * (size_t)NX, xl + 1 * (size_t)NX, NX / 4);
    cvt_kernel<<<(NX / 4 + 255) / 256, 256>>>((const float4*)xv, xh + 2 * (size_t)NX, xl + 2 * (size_t)NX, NX / 4);
    cvt_kernel<<<(NW / 4 + 255) / 256, 256>>>((const float4*)Wq, wh + 0 * (size_t)NW, wl + 0 * (size_t)NW, NW / 4);
    cvt_kernel<<<(NW / 4 + 255) / 256, 256>>>((const float4*)Wk, wh + 1 * (size_t)NW, wl + 1 * (size_t)NW, NW / 4);
    cvt_kernel<<<(NW / 4 + 255) / 256, 256>>>((const float4*)Wv, wh + 2 * (size_t)NW, wl + 2 * (size_t)NW, NW / 4);
    cvt_kernel<<<(NW / 4 + 255) / 256, 256>>>((const float4*)Wp, wh + 3 * (size_t)NW, wl + 3 * (size_t)NW, NW / 4);

    qkv_mma<<<dim3(6, 64, 3), 256, SMEM_BIG>>>();
    aff_kernel<<<(Bsz * Ntok) / 8, 256>>>(et, out_aff);
    scores_mma<<<dim3(8, 8, BH), 256, SMEM_BIG>>>();
    attnsave_kernel<<<(Bsz * Ntok * Ntok / 4) / 256, 256>>>(out_as);
    softmax_kernel<<<BH * Ntok, 256>>>();
    pv_mma<<<dim3(1, 8, BH), 256, SMEM_PV>>>();
    proj_mma<<<dim3(6, 64, 1), 256, SMEM_BIG>>>(bp, out_x);
}

// round 4
// speedup vs baseline: 3.3968x; 1.0001x over previous
#include <cuda_runtime.h>
#include <cuda_bf16.h>
#include <cstdint>

#define Bsz 8
#define Ntok 1024
#define Cdim 768
#define Hh 12
#define HD 64
#define BH (Bsz*Hh)
#define SCALE 0.125f

// ======================= warp MMA helpers (sm_80+ baseline PTX) =============
__device__ __forceinline__ uint32_t smem_to_u32(const void* p) {
    uint32_t a;
    asm("{ .reg .u64 t; cvta.to.shared.u64 t, %1; cvt.u32.u64 %0, t; }" : "=r"(a) : "l"(p));
    return a;
}
#define LDSM4(r, addr) \
    asm volatile("ldmatrix.sync.aligned.m8n8.x4.shared.b16 {%0,%1,%2,%3}, [%4];" \
        : "=r"((r)[0]), "=r"((r)[1]), "=r"((r)[2]), "=r"((r)[3]) : "r"(addr))
#define MMA_BF16(d, a, b) \
    asm volatile("mma.sync.aligned.m16n8k16.row.col.f32.bf16.bf16.f32 " \
        "{%0,%1,%2,%3}, {%4,%5,%6,%7}, {%8,%9}, {%0,%1,%2,%3};" \
        : "+f"((d)[0]), "+f"((d)[1]), "+f"((d)[2]), "+f"((d)[3]) \
        : "r"((a)[0]), "r"((a)[1]), "r"((a)[2]), "r"((a)[3]), "r"((b)[0]), "r"((b)[1]))

// ======================= scratch globals ====================================
__device__ __align__(16) __nv_bfloat16 g_xh[3u * 8192u * 768u];   // xq|xk|xv hi
__device__ __align__(16) __nv_bfloat16 g_xl[3u * 8192u * 768u];
__device__ __align__(16) __nv_bfloat16 g_wh[4u * 768u * 768u];    // Wq|Wk|Wv|Wp hi
__device__ __align__(16) __nv_bfloat16 g_wl[4u * 768u * 768u];
__device__ __align__(16) __nv_bfloat16 g_qh[BH * Ntok * HD];      // [b,h,tok,hd]
__device__ __align__(16) __nv_bfloat16 g_ql[BH * Ntok * HD];
__device__ __align__(16) __nv_bfloat16 g_kh[BH * Ntok * HD];
__device__ __align__(16) __nv_bfloat16 g_kl[BH * Ntok * HD];
__device__ __align__(16) __nv_bfloat16 g_vth[BH * HD * Ntok];     // [b,h,hd,tok]
__device__ __align__(16) __nv_bfloat16 g_vtl[BH * HD * Ntok];
__device__ float g_attn[(size_t)BH * Ntok * Ntok];                // fp32 scores
__device__ __align__(16) __nv_bfloat16 g_oh[8192u * 768u];        // attention out hi
__device__ __align__(16) __nv_bfloat16 g_ol[8192u * 768u];
__device__ __align__(16) float g_aff[Bsz * Ntok];

// ======================= fp32 -> bf16 hi/lo split ===========================
__global__ void cvt_kernel(const float4* __restrict__ src, __nv_bfloat16* __restrict__ hi,
                           __nv_bfloat16* __restrict__ lo, int n4)
{
    int i = blockIdx.x * 256 + threadIdx.x;
    if (i >= n4) return;
    float4 v = src[i];
    __nv_bfloat16 h0 = __float2bfloat16(v.x), h1 = __float2bfloat16(v.y);
    __nv_bfloat16 h2 = __float2bfloat16(v.z), h3 = __float2bfloat16(v.w);
    __nv_bfloat16 l0 = __float2bfloat16(v.x - __bfloat162float(h0));
    __nv_bfloat16 l1 = __float2bfloat16(v.y - __bfloat162float(h1));
    __nv_bfloat16 l2 = __float2bfloat16(v.z - __bfloat162float(h2));
    __nv_bfloat16 l3 = __float2bfloat16(v.w - __bfloat162float(h3));
    ((__nv_bfloat162*)hi)[i * 2]     = __nv_bfloat162(h0, h1);
    ((__nv_bfloat162*)hi)[i * 2 + 1] = __nv_bfloat162(h2, h3);
    ((__nv_bfloat162*)lo)[i * 2]     = __nv_bfloat162(l0, l1);
    ((__nv_bfloat162*)lo)[i * 2 + 1] = __nv_bfloat162(l2, l3);
}

// ======================= generic mma.sync GEMM ==============================
// C[128, BN] = Ah@Bh^T + Ah@Bl^T + Al@Bh^T.  A [128,K] K-major, B [BN,K].
// Result left in SMEM stage, stride BN+1 floats. 256 threads.
template <int BN>
__device__ __forceinline__ void gemm_to_stage(
    const __nv_bfloat16* __restrict__ Ah, const __nv_bfloat16* __restrict__ Al, int lda,
    const __nv_bfloat16* __restrict__ Bh, const __nv_bfloat16* __restrict__ Bl, int ldb,
    int kTotal, char* smem)
{
    constexpr int SROW = 40;                    // halves per smem row (32 + 8 pad)
    constexpr int A_H0 = 0;
    constexpr int A_L0 = 128 * SROW;
    constexpr int B_H0 = 2 * 128 * SROW;
    constexpr int B_L0 = B_H0 + BN * SROW;
    constexpr int BUFH = B_H0 + 2 * BN * SROW;
    constexpr int WN = BN / 2;
    constexpr int NT = BN / 16;
    constexpr int NTP = NT / 2;
    constexpr int NBJ = BN / 64;

    __nv_bfloat16* sm = (__nv_bfloat16*)smem;
    const uint32_t sbase = smem_to_u32(smem);
    const int tid = threadIdx.x, lane = tid & 31, wid = tid >> 5;
    const int wm = wid & 3, wn = wid >> 2;

    float acc[2][NT][4];
    #pragma unroll
    for (int i = 0; i < 2; i++)
        #pragma unroll
        for (int j = 0; j < NT; j++)
            #pragma unroll
            for (int l = 0; l < 4; l++) acc[i][j][l] = 0.f;

    uint4 ra_h[2], ra_l[2], rb_h[NBJ], rb_l[NBJ];

    auto LDG = [&](int k0) {
        #pragma unroll
        for (int j = 0; j < 2; j++) {
            int i = tid + j * 256, r = i >> 2, c = (i & 3) << 3;
            ra_h[j] = *(const uint4*)(Ah + (size_t)r * lda + k0 + c);
            ra_l[j] = *(const uint4*)(Al + (size_t)r * lda + k0 + c);
        }
        #pragma unroll
        for (int j = 0; j < NBJ; j++) {
            int i = tid + j * 256, r = i >> 2, c = (i & 3) << 3;
            rb_h[j] = *(const uint4*)(Bh + (size_t)r * ldb + k0 + c);
            rb_l[j] = *(const uint4*)(Bl + (size_t)r * ldb + k0 + c);
        }
    };
    auto STS = [&](int buf) {
        __nv_bfloat16* p = sm + buf * BUFH;
        #pragma unroll
        for (int j = 0; j < 2; j++) {
            int i = tid + j * 256, r = i >> 2, c = (i & 3) << 3;
            *(uint4*)(p + A_H0 + r * SROW + c) = ra_h[j];
            *(uint4*)(p + A_L0 + r * SROW + c) = ra_l[j];
        }
        #pragma unroll
        for (int j = 0; j < NBJ; j++) {
            int i = tid + j * 256, r = i >> 2, c = (i & 3) << 3;
            *(uint4*)(p + B_H0 + r * SROW + c) = rb_h[j];
            *(uint4*)(p + B_L0 + r * SROW + c) = rb_l[j];
        }
    };
    auto COMPUTE = [&](int buf) {
        const uint32_t base = sbase + (uint32_t)buf * BUFH * 2;
        #pragma unroll
        for (int ks = 0; ks < 32; ks += 16) {
            uint32_t ah[2][4], al2[2][4];
            const int arow = (lane & 7) + ((lane >> 3) & 1) * 8;
            const int acol = ks + (lane >> 4) * 8;
            #pragma unroll
            for (int mt = 0; mt < 2; mt++) {
                uint32_t off = (uint32_t)((wm * 32 + mt * 16 + arow) * SROW + acol) * 2;
                LDSM4(ah[mt],  base + A_H0 * 2 + off);
                LDSM4(al2[mt], base + A_L0 * 2 + off);
            }
            uint32_t bh[NT][2], bl2[NT][2];
            const int g = lane >> 3;
            const int brow = (g >> 1) * 8 + (lane & 7);
            const int bcol = ks + (g & 1) * 8;
            #pragma unroll
            for (int np = 0; np < NTP; np++) {
                uint32_t off = (uint32_t)((wn * WN + np * 16 + brow) * SROW + bcol) * 2;
                uint32_t t[4];
                LDSM4(t, base + B_H0 * 2 + off);
                bh[2 * np][0] = t[0]; bh[2 * np][1] = t[1];
                bh[2 * np + 1][0] = t[2]; bh[2 * np + 1][1] = t[3];
                LDSM4(t, base + B_L0 * 2 + off);
                bl2[2 * np][0] = t[0]; bl2[2 * np][1] = t[1];
                bl2[2 * np + 1][0] = t[2]; bl2[2 * np + 1][1] = t[3];
            }
            #pragma unroll
            for (int mt = 0; mt < 2; mt++)
                #pragma unroll
                for (int nt = 0; nt < NT; nt++) {
                    MMA_BF16(acc[mt][nt], ah[mt],  bh[nt]);
                    MMA_BF16(acc[mt][nt], ah[mt],  bl2[nt]);
                    MMA_BF16(acc[mt][nt], al2[mt], bh[nt]);
                }
        }
    };

    const int nCh = kTotal >> 5;
    LDG(0);
    STS(0);
    __syncthreads();
    for (int ch = 0; ch < nCh; ch++) {
        if (ch + 1 < nCh) LDG((ch + 1) << 5);
        COMPUTE(ch & 1);
        if (ch + 1 < nCh) STS((ch + 1) & 1);
        __syncthreads();
    }

    float* stage = (float*)smem;
    const int gidr = lane >> 2, qid = lane & 3;
    #pragma unroll
    for (int mt = 0; mt < 2; mt++)
        #pragma unroll
        for (int nt = 0; nt < NT; nt++) {
            int row = wm * 32 + mt * 16 + gidr;
            int col = wn * WN + nt * 8 + qid * 2;
            stage[row * (BN + 1) + col]           = acc[mt][nt][0];
            stage[row * (BN + 1) + col + 1]       = acc[mt][nt][1];
            stage[(row + 8) * (BN + 1) + col]     = acc[mt][nt][2];
            stage[(row + 8) * (BN + 1) + col + 1] = acc[mt][nt][3];
        }
    __syncthreads();
}

// ======================= QKV projection =====================================
__global__ void __launch_bounds__(256, 1) qkv_mma()
{
    extern __shared__ char smem[];
    const int z = blockIdx.z;
    const int m0 = blockIdx.y * 128, n0 = blockIdx.x * 128;

    const __nv_bfloat16* Ah = g_xh + (size_t)z * 8192 * 768 + (size_t)m0 * 768;
    const __nv_bfloat16* Al = g_xl + (size_t)z * 8192 * 768 + (size_t)m0 * 768;
    const __nv_bfloat16* Bh = g_wh + (size_t)z * 768 * 768 + (size_t)n0 * 768;
    const __nv_bfloat16* Bl = g_wl + (size_t)z * 768 * 768 + (size_t)n0 * 768;

    gemm_to_stage<128>(Ah, Al, 768, Bh, Bl, 768, 768, smem);
    float* stage = (float*)smem;

    const int tid = threadIdx.x;
    if (z < 2) {
        __nv_bfloat16* dh = (z == 0) ? g_qh : g_kh;
        __nv_bfloat16* dl = (z == 0) ? g_ql : g_kl;
        for (int idx = tid; idx < 128 * 128; idx += 256) {
            int mr = idx >> 7, nc = idx & 127;
            int m = m0 + mr, n = n0 + nc;
            int b = m >> 10, tok = m & 1023, h = n >> 6, hd = n & 63;
            float v = stage[mr * 129 + nc];
            __nv_bfloat16 hi = __float2bfloat16(v);
            __nv_bfloat16 lo = __float2bfloat16(v - __bfloat162float(hi));
            size_t o = (((size_t)(b * Hh + h)) * Ntok + tok) * HD + hd;
            dh[o] = hi; dl[o] = lo;
        }
    } else {
        for (int idx = tid; idx < 128 * 128; idx += 256) {
            int mr = idx & 127, nc = idx >> 7;
            int m = m0 + mr, n = n0 + nc;
            int b = m >> 10, tok = m & 1023, h = n >> 6, hd = n & 63;
            float v = stage[mr * 129 + nc];
            __nv_bfloat16 hi = __float2bfloat16(v);
            __nv_bfloat16 lo = __float2bfloat16(v - __bfloat162float(hi));
            size_t o = (((size_t)(b * Hh + h)) * HD + hd) * Ntok + tok;
            g_vth[o] = hi; g_vtl[o] = lo;
        }
    }
}

// ======================= affinity gate ======================================
__global__ void aff_kernel(const float* __restrict__ et, float* __restrict__ out_aff)
{
    int warp = (blockIdx.x * blockDim.x + threadIdx.x) >> 5;
    int lane = threadIdx.x & 31;
    if (warp >= Bsz * Ntok) return;
    int b = warp >> 10, tok = warp & 1023;
    float s = 0.f;
    for (int c = lane; c < Cdim; c += 32) {
        int h = c >> 6, hd = c & 63;
        size_t o = (((size_t)(b * Hh + h)) * Ntok + tok) * HD + hd;
        float kv = __bfloat162float(g_kh[o]) + __bfloat162float(g_kl[o]);
        s += et[b * Cdim + c] * kv;
    }
    #pragma unroll
    for (int o = 16; o; o >>= 1) s += __shfl_xor_sync(0xffffffffu, s, o);
    if (lane == 0) {
        float v = 1.f / (1.f + __expf(-(SCALE / Hh) * s));
        g_aff[warp] = v;
        out_aff[warp] = v;
    }
}

// ======================= scores =============================================
__global__ void __launch_bounds__(256, 1) scores_mma()
{
    extern __shared__ char smem[];
    const int z = blockIdx.z;
    const int m0 = blockIdx.y * 128, n0 = blockIdx.x * 128;

    const __nv_bfloat16* Ah = g_qh + (size_t)z * Ntok * HD + (size_t)m0 * HD;
    const __nv_bfloat16* Al = g_ql + (size_t)z * Ntok * HD + (size_t)m0 * HD;
    const __nv_bfloat16* Bh = g_kh + (size_t)z * Ntok * HD + (size_t)n0 * HD;
    const __nv_bfloat16* Bl = g_kl + (size_t)z * Ntok * HD + (size_t)n0 * HD;

    gemm_to_stage<128>(Ah, Al, HD, Bh, Bl, HD, HD, smem);
    float* stage = (float*)smem;

    float* out = g_attn + (size_t)z * Ntok * Ntok;
    for (int idx = threadIdx.x; idx < 128 * 128; idx += 256) {
        int mr = idx >> 7, nc = idx & 127;
        out[(size_t)(m0 + mr) * Ntok + n0 + nc] = stage[mr * 129 + nc] * SCALE;
    }
}

// ======================= attn_save ==========================================
__global__ void attnsave_kernel(float* __restrict__ out_as)
{
    size_t idx = (size_t)blockIdx.x * 256 + threadIdx.x;
    int k4 = (int)(idx & 255);
    size_t bq = idx >> 8;
    int b = (int)(bq >> 10);
    float4 s = make_float4(0.f, 0.f, 0.f, 0.f);
    int q = (int)(bq & 1023);
    #pragma unroll
    for (int h = 0; h < Hh; h++) {
        const float4* p = (const float4*)(g_attn + ((size_t)(b * Hh + h) * Ntok + q) * Ntok);
        float4 v = p[k4];
        s.x += v.x; s.y += v.y; s.z += v.z; s.w += v.w;
    }
    const float inv = 1.f / Hh;
    s.x *= inv; s.y *= inv; s.z *= inv; s.w *= inv;
    ((float4*)out_as)[bq * 256 + k4] = s;
}

// ======================= fused softmax + PV =================================
// Per CTA: 128 q-rows x full 1024 k for one (b,h). Reads fp32 scores, computes
// e=exp(S) inline (scores are small; no max needed), gates with aff on the
// numerator, MMAs against V^T, normalizes by row-sum of e in the epilogue.
__global__ void __launch_bounds__(256, 1) pv_fused()
{
    extern __shared__ char smem[];
    constexpr int SR = 136;                       // halves per smem row (128+8)
    constexpr uint32_t AH0 = 0;
    constexpr uint32_t AL0 = 128u * SR * 2u;      // byte offsets
    constexpr uint32_t BH0 = 2u * 128u * SR * 2u;
    constexpr uint32_t BL0 = BH0 + 64u * SR * 2u;
    constexpr uint32_t RS0 = BL0 + 64u * SR * 2u; // rowsum floats

    __nv_bfloat16* Ah_s = (__nv_bfloat16*)(smem + AH0);
    __nv_bfloat16* Al_s = (__nv_bfloat16*)(smem + AL0);
    __nv_bfloat16* Bh_s = (__nv_bfloat16*)(smem + BH0);
    __nv_bfloat16* Bl_s = (__nv_bfloat16*)(smem + BL0);
    float* rowsum_s = (float*)(smem + RS0);
    const uint32_t sbase = smem_to_u32(smem);

    const int z = blockIdx.z;
    const int m0 = blockIdx.y * 128;
    const int b = z / Hh, h = z % Hh;
    const int tid = threadIdx.x, lane = tid & 31, wid = tid >> 5;
    const int wm = wid & 3, wn = wid >> 2;        // wn in {0,1}

    const float* Srow = g_attn + (size_t)z * Ntok * Ntok + (size_t)m0 * Ntok;
    const __nv_bfloat16* Vh = g_vth + (size_t)z * HD * Ntok;
    const __nv_bfloat16* Vl = g_vtl + (size_t)z * HD * Ntok;
    const float* aff = g_aff + b * Ntok;

    float acc[2][4][4];
    #pragma unroll
    for (int i = 0; i < 2; i++)
        #pragma unroll
        for (int j = 0; j < 4; j++)
            #pragma unroll
            for (int l = 0; l < 4; l++) acc[i][j][l] = 0.f;
    float rowAcc = 0.f;
    const int frow = tid >> 1;                    // fill row (0..127)
    const int fcol = (tid & 1) * 64;              // fill col base

    for (int ch = 0; ch < 8; ch++) {
        const int k0 = ch * 128;
        // ---- A operand: exp(S)*aff, hi/lo split ----
        const float4* s4 = (const float4*)(Srow + (size_t)frow * Ntok + k0 + fcol);
        const float4* a4 = (const float4*)(aff + k0 + fcol);
        float rs = 0.f;
        #pragma unroll
        for (int j = 0; j < 16; j++) {
            float4 s = s4[j];
            float4 a = a4[j];
            float e0 = __expf(s.x), e1 = __expf(s.y), e2 = __expf(s.z), e3 = __expf(s.w);
            rs += (e0 + e1) + (e2 + e3);
            float p0 = e0 * a.x, p1 = e1 * a.y, p2 = e2 * a.z, p3 = e3 * a.w;
            __nv_bfloat16 h0 = __float2bfloat16(p0), h1 = __float2bfloat16(p1);
            __nv_bfloat16 h2 = __float2bfloat16(p2), h3 = __float2bfloat16(p3);
            __nv_bfloat16 l0 = __float2bfloat16(p0 - __bfloat162float(h0));
            __nv_bfloat16 l1 = __float2bfloat16(p1 - __bfloat162float(h1));
            __nv_bfloat16 l2 = __float2bfloat16(p2 - __bfloat162float(h2));
            __nv_bfloat16 l3 = __float2bfloat16(p3 - __bfloat162float(h3));
            int off = frow * SR + fcol + j * 4;
            *(__nv_bfloat162*)(Ah_s + off)     = __nv_bfloat162(h0, h1);
            *(__nv_bfloat162*)(Ah_s + off + 2) = __nv_bfloat162(h2, h3);
            *(__nv_bfloat162*)(Al_s + off)     = __nv_bfloat162(l0, l1);
            *(__nv_bfloat162*)(Al_s + off + 2) = __nv_bfloat162(l2, l3);
        }
        rs += __shfl_xor_sync(0xffffffffu, rs, 1);
        rowAcc += rs;
        // ---- B operand: V^T tile [64 d x 128 k] ----
        #pragma unroll
        for (int j = 0; j < 4; j++) {
            int i = tid + j * 256;
            int r = i >> 4, c = (i & 15) * 8;
            *(uint4*)(Bh_s + r * SR + c) = *(const uint4*)(Vh + (size_t)r * Ntok + k0 + c);
            *(uint4*)(Bl_s + r * SR + c) = *(const uint4*)(Vl + (size_t)r * Ntok + k0 + c);
        }
        __syncthreads();
        // ---- MMA over this 128-k chunk ----
        #pragma unroll
        for (int ks = 0; ks < 128; ks += 16) {
            uint32_t ah[2][4], al2[2][4];
            const int arow = (lane & 7) + ((lane >> 3) & 1) * 8;
            const int acol = ks + (lane >> 4) * 8;
            #pragma unroll
            for (int mt = 0; mt < 2; mt++) {
                uint32_t off = (uint32_t)((wm * 32 + mt * 16 + arow) * SR + acol) * 2;
                LDSM4(ah[mt],  sbase + AH0 + off);
                LDSM4(al2[mt], sbase + AL0 + off);
            }
            uint32_t bh[4][2], bl2[4][2];
            const int g = lane >> 3;
            const int brow = (g >> 1) * 8 + (lane & 7);
            const int bcol = ks + (g & 1) * 8;
            #pragma unroll
            for (int np = 0; np < 2; np++) {
                uint32_t off = (uint32_t)((wn * 32 + np * 16 + brow) * SR + bcol) * 2;
                uint32_t t[4];
                LDSM4(t, sbase + BH0 + off);
                bh[2 * np][0] = t[0]; bh[2 * np][1] = t[1];
                bh[2 * np + 1][0] = t[2]; bh[2 * np + 1][1] = t[3];
                LDSM4(t, sbase + BL0 + off);
                bl2[2 * np][0] = t[0]; bl2[2 * np][1] = t[1];
                bl2[2 * np + 1][0] = t[2]; bl2[2 * np + 1][1] = t[3];
            }
            #pragma unroll
            for (int mt = 0; mt < 2; mt++)
                #pragma unroll
                for (int nt = 0; nt < 4; nt++) {
                    MMA_BF16(acc[mt][nt], ah[mt],  bh[nt]);
                    MMA_BF16(acc[mt][nt], ah[mt],  bl2[nt]);
                    MMA_BF16(acc[mt][nt], al2[mt], bh[nt]);
                }
        }
        __syncthreads();
    }
    if ((tid & 1) == 0) rowsum_s[frow] = rowAcc;
    __syncthreads();

    // ---- epilogue: normalize, split, scatter ----
    const int gidr = lane >> 2, qid = lane & 3;
    #pragma unroll
    for (int mt = 0; mt < 2; mt++) {
        int row = wm * 32 + mt * 16 + gidr;
        float inv0 = 1.f / rowsum_s[row];
        float inv8 = 1.f / rowsum_s[row + 8];
        #pragma unroll
        for (int nt = 0; nt < 4; nt++) {
            int col = wn * 32 + nt * 8 + qid * 2;
            float x0 = acc[mt][nt][0] * inv0, x1 = acc[mt][nt][1] * inv0;
            float x2 = acc[mt][nt][2] * inv8, x3 = acc[mt][nt][3] * inv8;
            __nv_bfloat16 h0 = __float2bfloat16(x0), h1 = __float2bfloat16(x1);
            __nv_bfloat16 h2 = __float2bfloat16(x2), h3 = __float2bfloat16(x3);
            __nv_bfloat16 l0 = __float2bfloat16(x0 - __bfloat162float(h0));
            __nv_bfloat16 l1 = __float2bfloat16(x1 - __bfloat162float(h1));
            __nv_bfloat16 l2 = __float2bfloat16(x2 - __bfloat162float(h2));
            __nv_bfloat16 l3 = __float2bfloat16(x3 - __bfloat162float(h3));
            size_t o0 = ((size_t)b * Ntok + m0 + row) * Cdim + h * HD + col;
            size_t o8 = o0 + 8u * Cdim;
            *(__nv_bfloat162*)(g_oh + o0) = __nv_bfloat162(h0, h1);
            *(__nv_bfloat162*)(g_ol + o0) = __nv_bfloat162(l0, l1);
            *(__nv_bfloat162*)(g_oh + o8) = __nv_bfloat162(h2, h3);
            *(__nv_bfloat162*)(g_ol + o8) = __nv_bfloat162(l2, l3);
        }
    }
}

// ======================= output projection ==================================
__global__ void __launch_bounds__(256, 1) proj_mma(const float* __restrict__ bp,
                                                   float* __restrict__ out)
{
    extern __shared__ char smem[];
    const int m0 = blockIdx.y * 128, n0 = blockIdx.x * 128;

    const __nv_bfloat16* Ah = g_oh + (size_t)m0 * 768;
    const __nv_bfloat16* Al = g_ol + (size_t)m0 * 768;
    const __nv_bfloat16* Bh = g_wh + (size_t)3 * 768 * 768 + (size_t)n0 * 768;
    const __nv_bfloat16* Bl = g_wl + (size_t)3 * 768 * 768 + (size_t)n0 * 768;

    gemm_to_stage<128>(Ah, Al, 768, Bh, Bl, 768, 768, smem);
    float* stage = (float*)smem;

    for (int idx = threadIdx.x; idx < 128 * 128; idx += 256) {
        int mr = idx >> 7, nc = idx & 127;
        int n = n0 + nc;
        out[(size_t)(m0 + mr) * Cdim + n] = stage[mr * 129 + nc] + bp[n];
    }
}

// ============================================================================
extern "C" void kernel_launch(void* const* d_in, const int* in_sizes, int n_in,
                              void* d_out, int out_size)
{
    (void)in_sizes; (void)n_in; (void)out_size;
    const float* xq = (const float*)d_in[0];
    const float* xk = (const float*)d_in[1];
    const float* xv = (const float*)d_in[2];
    const float* et = (const float*)d_in[3];
    const float* Wq = (const float*)d_in[4];
    const float* Wk = (const float*)d_in[5];
    const float* Wv = (const float*)d_in[6];
    const float* Wp = (const float*)d_in[7];
    const float* bp = (const float*)d_in[8];

    float* out     = (float*)d_out;
    float* out_x   = out;
    float* out_as  = out + (size_t)Bsz * Ntok * Cdim;
    float* out_aff = out_as + (size_t)Bsz * Ntok * Ntok;

    const int SMEM_BIG = 81920;
    // pv_fused: A 128*136*2*2 + B 64*136*2*2 + rowsum 512 = 104448 + 512
    const int SMEM_PVF = 104960;
    cudaFuncSetAttribute(qkv_mma,    cudaFuncAttributeMaxDynamicSharedMemorySize, SMEM_BIG);
    cudaFuncSetAttribute(scores_mma, cudaFuncAttributeMaxDynamicSharedMemorySize, SMEM_BIG);
    cudaFuncSetAttribute(pv_fused,   cudaFuncAttributeMaxDynamicSharedMemorySize, SMEM_PVF);
    cudaFuncSetAttribute(proj_mma,   cudaFuncAttributeMaxDynamicSharedMemorySize, SMEM_BIG);

    __nv_bfloat16 *xh, *xl, *wh, *wl;
    cudaGetSymbolAddress((void**)&xh, g_xh);
    cudaGetSymbolAddress((void**)&xl, g_xl);
    cudaGetSymbolAddress((void**)&wh, g_wh);
    cudaGetSymbolAddress((void**)&wl, g_wl);

    const int NX = 8192 * 768, NW = 768 * 768;
    cvt_kernel<<<(NX / 4 + 255) / 256, 256>>>((const float4*)xq, xh + 0 * (size_t)NX, xl + 0 * (size_t)NX, NX / 4);
    cvt_kernel<<<(NX / 4 + 255) / 256, 256>>>((const float4*)xk, xh + 1 * (size_t)NX, xl + 1 * (size_t)NX, NX / 4);
    cvt_kernel<<<(NX / 4 + 255) / 256, 256>>>((const float4*)xv, xh + 2 * (size_t)NX, xl + 2 * (size_t)NX, NX / 4);
    cvt_kernel<<<(NW / 4 + 255) / 256, 256>>>((const float4*)Wq, wh + 0 * (size_t)NW, wl + 0 * (size_t)NW, NW / 4);
    cvt_kernel<<<(NW / 4 + 255) / 256, 256>>>((const float4*)Wk, wh + 1 * (size_t)NW, wl + 1 * (size_t)NW, NW / 4);
    cvt_kernel<<<(NW / 4 + 255) / 256, 256>>>((const float4*)Wv, wh + 2 * (size_t)NW, wl + 2 * (size_t)NW, NW / 4);
    cvt_kernel<<<(NW / 4 + 255) / 256, 256>>>((const float4*)Wp, wh + 3 * (size_t)NW, wl + 3 * (size_t)NW, NW / 4);

    qkv_mma<<<dim3(6, 64, 3), 256, SMEM_BIG>>>();
    aff_kernel<<<(Bsz * Ntok) / 8, 256>>>(et, out_aff);
    scores_mma<<<dim3(8, 8, BH), 256, SMEM_BIG>>>();
    attnsave_kernel<<<(Bsz * Ntok * Ntok / 4) / 256, 256>>>(out_as);
    pv_fused<<<dim3(1, 8, BH), 256, SMEM_PVF>>>();
    proj_mma<<<dim3(6, 64, 1), 256, SMEM_BIG>>>(bp, out_x);
}

// round 5
// speedup vs baseline: 3.7789x; 1.1125x over previous
#include <cuda_runtime.h>
#include <cuda_bf16.h>
#include <cstdint>

#define Bsz 8
#define Ntok 1024
#define Cdim 768
#define Hh 12
#define HD 64
#define BH (Bsz*Hh)
#define SCALE 0.125f

// ======================= PTX helpers (sm_80+ baseline) ======================
__device__ __forceinline__ uint32_t smem_to_u32(const void* p) {
    uint32_t a;
    asm("{ .reg .u64 t; cvta.to.shared.u64 t, %1; cvt.u32.u64 %0, t; }" : "=r"(a) : "l"(p));
    return a;
}
#define LDSM4(r, addr) \
    asm volatile("ldmatrix.sync.aligned.m8n8.x4.shared.b16 {%0,%1,%2,%3}, [%4];" \
        : "=r"((r)[0]), "=r"((r)[1]), "=r"((r)[2]), "=r"((r)[3]) : "r"(addr))
#define MMA_BF16(d, a, b) \
    asm volatile("mma.sync.aligned.m16n8k16.row.col.f32.bf16.bf16.f32 " \
        "{%0,%1,%2,%3}, {%4,%5,%6,%7}, {%8,%9}, {%0,%1,%2,%3};" \
        : "+f"((d)[0]), "+f"((d)[1]), "+f"((d)[2]), "+f"((d)[3]) \
        : "r"((a)[0]), "r"((a)[1]), "r"((a)[2]), "r"((a)[3]), "r"((b)[0]), "r"((b)[1]))
#define CP16(dst_u32, src_ptr) \
    asm volatile("cp.async.cg.shared.global [%0], [%1], 16;" :: "r"(dst_u32), "l"(src_ptr))
#define CP_COMMIT() asm volatile("cp.async.commit_group;")
#define CP_WAIT(n)  asm volatile("cp.async.wait_group %0;" :: "n"(n))

// ======================= scratch globals ====================================
__device__ __align__(16) __nv_bfloat16 g_xh[3u * 8192u * 768u];
__device__ __align__(16) __nv_bfloat16 g_xl[3u * 8192u * 768u];
__device__ __align__(16) __nv_bfloat16 g_wh[4u * 768u * 768u];
__device__ __align__(16) __nv_bfloat16 g_wl[4u * 768u * 768u];
__device__ __align__(16) __nv_bfloat16 g_qh[BH * Ntok * HD];
__device__ __align__(16) __nv_bfloat16 g_ql[BH * Ntok * HD];
__device__ __align__(16) __nv_bfloat16 g_kh[BH * Ntok * HD];
__device__ __align__(16) __nv_bfloat16 g_kl[BH * Ntok * HD];
__device__ __align__(16) __nv_bfloat16 g_vth[BH * HD * Ntok];   // [b,h,hd,tok]
__device__ __align__(16) __nv_bfloat16 g_vtl[BH * HD * Ntok];
__device__ float g_attn[(size_t)BH * Ntok * Ntok];
__device__ __align__(16) __nv_bfloat16 g_oh[8192u * 768u];
__device__ __align__(16) __nv_bfloat16 g_ol[8192u * 768u];
__device__ __align__(16) float g_aff[Bsz * Ntok];

// ======================= fp32 -> bf16 hi/lo split (batched) =================
__device__ __forceinline__ void split4(float4 v, __nv_bfloat162* hi2, __nv_bfloat162* lo2)
{
    __nv_bfloat16 h0 = __float2bfloat16(v.x), h1 = __float2bfloat16(v.y);
    __nv_bfloat16 h2 = __float2bfloat16(v.z), h3 = __float2bfloat16(v.w);
    __nv_bfloat16 l0 = __float2bfloat16(v.x - __bfloat162float(h0));
    __nv_bfloat16 l1 = __float2bfloat16(v.y - __bfloat162float(h1));
    __nv_bfloat16 l2 = __float2bfloat16(v.z - __bfloat162float(h2));
    __nv_bfloat16 l3 = __float2bfloat16(v.w - __bfloat162float(h3));
    hi2[0] = __nv_bfloat162(h0, h1); hi2[1] = __nv_bfloat162(h2, h3);
    lo2[0] = __nv_bfloat162(l0, l1); lo2[1] = __nv_bfloat162(l2, l3);
}

__global__ void cvtX_kernel(const float4* __restrict__ s0, const float4* __restrict__ s1,
                            const float4* __restrict__ s2, int n4)
{
    int i = blockIdx.x * 256 + threadIdx.x;
    if (i >= n4) return;
    int z = blockIdx.z;
    const float4* src = (z == 0) ? s0 : (z == 1) ? s1 : s2;
    size_t off = (size_t)z * n4 + i;
    split4(src[i], (__nv_bfloat162*)g_xh + off * 2, (__nv_bfloat162*)g_xl + off * 2);
}
__global__ void cvtW_kernel(const float4* __restrict__ s0, const float4* __restrict__ s1,
                            const float4* __restrict__ s2, const float4* __restrict__ s3, int n4)
{
    int i = blockIdx.x * 256 + threadIdx.x;
    if (i >= n4) return;
    int z = blockIdx.z;
    const float4* src = (z == 0) ? s0 : (z == 1) ? s1 : (z == 2) ? s2 : s3;
    size_t off = (size_t)z * n4 + i;
    split4(src[i], (__nv_bfloat162*)g_wh + off * 2, (__nv_bfloat162*)g_wl + off * 2);
}

// ======================= generic mma.sync GEMM (cp.async) ===================
// C[128, BN] = Ah@Bh^T + Ah@Bl^T + Al@Bh^T. Result in SMEM stage, stride BN+1.
template <int BN>
__device__ __forceinline__ void gemm_to_stage(
    const __nv_bfloat16* __restrict__ Ah, const __nv_bfloat16* __restrict__ Al, int lda,
    const __nv_bfloat16* __restrict__ Bh, const __nv_bfloat16* __restrict__ Bl, int ldb,
    int kTotal, char* smem)
{
    constexpr int SROW = 40;
    constexpr int A_H0 = 0;
    constexpr int A_L0 = 128 * SROW;
    constexpr int B_H0 = 2 * 128 * SROW;
    constexpr int B_L0 = B_H0 + BN * SROW;
    constexpr int BUFH = B_H0 + 2 * BN * SROW;
    constexpr int WN = BN / 2;
    constexpr int NT = BN / 16;
    constexpr int NTP = NT / 2;
    constexpr int NBJ = BN / 64;

    const uint32_t sbase = smem_to_u32(smem);
    const int tid = threadIdx.x, lane = tid & 31, wid = tid >> 5;
    const int wm = wid & 3, wn = wid >> 2;

    float acc[2][NT][4];
    #pragma unroll
    for (int i = 0; i < 2; i++)
        #pragma unroll
        for (int j = 0; j < NT; j++)
            #pragma unroll
            for (int l = 0; l < 4; l++) acc[i][j][l] = 0.f;

    auto CPA = [&](int buf, int k0) {
        uint32_t p = sbase + (uint32_t)buf * BUFH * 2u;
        #pragma unroll
        for (int j = 0; j < 2; j++) {
            int i = tid + j * 256, r = i >> 2, c = (i & 3) << 3;
            CP16(p + (A_H0 + r * SROW + c) * 2, Ah + (size_t)r * lda + k0 + c);
            CP16(p + (A_L0 + r * SROW + c) * 2, Al + (size_t)r * lda + k0 + c);
        }
        #pragma unroll
        for (int j = 0; j < NBJ; j++) {
            int i = tid + j * 256, r = i >> 2, c = (i & 3) << 3;
            CP16(p + (B_H0 + r * SROW + c) * 2, Bh + (size_t)r * ldb + k0 + c);
            CP16(p + (B_L0 + r * SROW + c) * 2, Bl + (size_t)r * ldb + k0 + c);
        }
        CP_COMMIT();
    };
    auto COMPUTE = [&](int buf) {
        const uint32_t base = sbase + (uint32_t)buf * BUFH * 2;
        #pragma unroll
        for (int ks = 0; ks < 32; ks += 16) {
            uint32_t ah[2][4], al2[2][4];
            const int arow = (lane & 7) + ((lane >> 3) & 1) * 8;
            const int acol = ks + (lane >> 4) * 8;
            #pragma unroll
            for (int mt = 0; mt < 2; mt++) {
                uint32_t off = (uint32_t)((wm * 32 + mt * 16 + arow) * SROW + acol) * 2;
                LDSM4(ah[mt],  base + A_H0 * 2 + off);
                LDSM4(al2[mt], base + A_L0 * 2 + off);
            }
            uint32_t bh[NT][2], bl2[NT][2];
            const int g = lane >> 3;
            const int brow = (g >> 1) * 8 + (lane & 7);
            const int bcol = ks + (g & 1) * 8;
            #pragma unroll
            for (int np = 0; np < NTP; np++) {
                uint32_t off = (uint32_t)((wn * WN + np * 16 + brow) * SROW + bcol) * 2;
                uint32_t t[4];
                LDSM4(t, base + B_H0 * 2 + off);
                bh[2 * np][0] = t[0]; bh[2 * np][1] = t[1];
                bh[2 * np + 1][0] = t[2]; bh[2 * np + 1][1] = t[3];
                LDSM4(t, base + B_L0 * 2 + off);
                bl2[2 * np][0] = t[0]; bl2[2 * np][1] = t[1];
                bl2[2 * np + 1][0] = t[2]; bl2[2 * np + 1][1] = t[3];
            }
            #pragma unroll
            for (int mt = 0; mt < 2; mt++)
                #pragma unroll
                for (int nt = 0; nt < NT; nt++) {
                    MMA_BF16(acc[mt][nt], ah[mt],  bh[nt]);
                    MMA_BF16(acc[mt][nt], ah[mt],  bl2[nt]);
                    MMA_BF16(acc[mt][nt], al2[mt], bh[nt]);
                }
        }
    };

    const int nCh = kTotal >> 5;
    CPA(0, 0);
    for (int ch = 0; ch < nCh; ch++) {
        if (ch + 1 < nCh) { CPA((ch + 1) & 1, (ch + 1) << 5); CP_WAIT(1); }
        else              { CP_WAIT(0); }
        __syncthreads();
        COMPUTE(ch & 1);
        __syncthreads();
    }

    float* stage = (float*)smem;
    const int gidr = lane >> 2, qid = lane & 3;
    #pragma unroll
    for (int mt = 0; mt < 2; mt++)
        #pragma unroll
        for (int nt = 0; nt < NT; nt++) {
            int row = wm * 32 + mt * 16 + gidr;
            int col = wn * WN + nt * 8 + qid * 2;
            stage[row * (BN + 1) + col]           = acc[mt][nt][0];
            stage[row * (BN + 1) + col + 1]       = acc[mt][nt][1];
            stage[(row + 8) * (BN + 1) + col]     = acc[mt][nt][2];
            stage[(row + 8) * (BN + 1) + col + 1] = acc[mt][nt][3];
        }
    __syncthreads();
}

// ======================= QKV projection =====================================
__global__ void __launch_bounds__(256, 2) qkv_mma()
{
    extern __shared__ char smem[];
    const int z = blockIdx.z;
    const int m0 = blockIdx.y * 128, n0 = blockIdx.x * 128;

    const __nv_bfloat16* Ah = g_xh + (size_t)z * 8192 * 768 + (size_t)m0 * 768;
    const __nv_bfloat16* Al = g_xl + (size_t)z * 8192 * 768 + (size_t)m0 * 768;
    const __nv_bfloat16* Bh = g_wh + (size_t)z * 768 * 768 + (size_t)n0 * 768;
    const __nv_bfloat16* Bl = g_wl + (size_t)z * 768 * 768 + (size_t)n0 * 768;

    gemm_to_stage<128>(Ah, Al, 768, Bh, Bl, 768, 768, smem);
    float* stage = (float*)smem;

    const int tid = threadIdx.x;
    if (z < 2) {
        __nv_bfloat16* dh = (z == 0) ? g_qh : g_kh;
        __nv_bfloat16* dl = (z == 0) ? g_ql : g_kl;
        for (int idx = tid; idx < 128 * 128; idx += 256) {
            int mr = idx >> 7, nc = idx & 127;
            int m = m0 + mr, n = n0 + nc;
            int b = m >> 10, tok = m & 1023, h = n >> 6, hd = n & 63;
            float v = stage[mr * 129 + nc];
            __nv_bfloat16 hi = __float2bfloat16(v);
            __nv_bfloat16 lo = __float2bfloat16(v - __bfloat162float(hi));
            size_t o = (((size_t)(b * Hh + h)) * Ntok + tok) * HD + hd;
            dh[o] = hi; dl[o] = lo;
        }
    } else {
        for (int idx = tid; idx < 128 * 128; idx += 256) {
            int mr = idx & 127, nc = idx >> 7;
            int m = m0 + mr, n = n0 + nc;
            int b = m >> 10, tok = m & 1023, h = n >> 6, hd = n & 63;
            float v = stage[mr * 129 + nc];
            __nv_bfloat16 hi = __float2bfloat16(v);
            __nv_bfloat16 lo = __float2bfloat16(v - __bfloat162float(hi));
            size_t o = (((size_t)(b * Hh + h)) * HD + hd) * Ntok + tok;
            g_vth[o] = hi; g_vtl[o] = lo;
        }
    }
}

// ======================= affinity gate ======================================
__global__ void aff_kernel(const float* __restrict__ et, float* __restrict__ out_aff)
{
    int warp = (blockIdx.x * blockDim.x + threadIdx.x) >> 5;
    int lane = threadIdx.x & 31;
    if (warp >= Bsz * Ntok) return;
    int b = warp >> 10, tok = warp & 1023;
    float s = 0.f;
    for (int c = lane; c < Cdim; c += 32) {
        int h = c >> 6, hd = c & 63;
        size_t o = (((size_t)(b * Hh + h)) * Ntok + tok) * HD + hd;
        float kv = __bfloat162float(g_kh[o]) + __bfloat162float(g_kl[o]);
        s += et[b * Cdim + c] * kv;
    }
    #pragma unroll
    for (int o = 16; o; o >>= 1) s += __shfl_xor_sync(0xffffffffu, s, o);
    if (lane == 0) {
        float v = 1.f / (1.f + __expf(-(SCALE / Hh) * s));
        g_aff[warp] = v;
        out_aff[warp] = v;
    }
}

// ======================= scores =============================================
__global__ void __launch_bounds__(256, 2) scores_mma()
{
    extern __shared__ char smem[];
    const int z = blockIdx.z;
    const int m0 = blockIdx.y * 128, n0 = blockIdx.x * 128;

    const __nv_bfloat16* Ah = g_qh + (size_t)z * Ntok * HD + (size_t)m0 * HD;
    const __nv_bfloat16* Al = g_ql + (size_t)z * Ntok * HD + (size_t)m0 * HD;
    const __nv_bfloat16* Bh = g_kh + (size_t)z * Ntok * HD + (size_t)n0 * HD;
    const __nv_bfloat16* Bl = g_kl + (size_t)z * Ntok * HD + (size_t)n0 * HD;

    gemm_to_stage<128>(Ah, Al, HD, Bh, Bl, HD, HD, smem);
    float* stage = (float*)smem;

    float* out = g_attn + (size_t)z * Ntok * Ntok;
    for (int idx = threadIdx.x; idx < 128 * 128; idx += 256) {
        int mr = idx >> 7, nc = idx & 127;
        out[(size_t)(m0 + mr) * Ntok + n0 + nc] = stage[mr * 129 + nc] * SCALE;
    }
}

// ======================= attn_save ==========================================
__global__ void attnsave_kernel(float* __restrict__ out_as)
{
    size_t idx = (size_t)blockIdx.x * 256 + threadIdx.x;
    int k4 = (int)(idx & 255);
    size_t bq = idx >> 8;
    int b = (int)(bq >> 10);
    float4 s = make_float4(0.f, 0.f, 0.f, 0.f);
    int q = (int)(bq & 1023);
    #pragma unroll
    for (int h = 0; h < Hh; h++) {
        const float4* p = (const float4*)(g_attn + ((size_t)(b * Hh + h) * Ntok + q) * Ntok);
        float4 v = p[k4];
        s.x += v.x; s.y += v.y; s.z += v.z; s.w += v.w;
    }
    const float inv = 1.f / Hh;
    s.x *= inv; s.y *= inv; s.z *= inv; s.w *= inv;
    ((float4*)out_as)[bq * 256 + k4] = s;
}

// ======================= fused softmax + PV (BM=64) =========================
__global__ void __launch_bounds__(256, 2) pv_fused()
{
    extern __shared__ char smem[];
    constexpr int SR = 136;
    constexpr uint32_t AH0 = 0;
    constexpr uint32_t AL0 = 64u * SR * 2u;        // 17408
    constexpr uint32_t BH0 = 2u * 64u * SR * 2u;   // 34816
    constexpr uint32_t BL0 = BH0 + 64u * SR * 2u;  // 52224
    constexpr uint32_t RS0 = BL0 + 64u * SR * 2u;  // 69632

    __nv_bfloat16* Ah_s = (__nv_bfloat16*)(smem + AH0);
    __nv_bfloat16* Al_s = (__nv_bfloat16*)(smem + AL0);
    float* rowsum_s = (float*)(smem + RS0);
    const uint32_t sbase = smem_to_u32(smem);

    const int z = blockIdx.z;
    const int m0 = blockIdx.y * 64;
    const int b = z / Hh, h = z % Hh;
    const int tid = threadIdx.x, lane = tid & 31, wid = tid >> 5;
    const int wm = wid & 1, wn = wid >> 1;         // wn in 0..3

    const float* Srow = g_attn + (size_t)z * Ntok * Ntok + (size_t)m0 * Ntok;
    const __nv_bfloat16* Vh = g_vth + (size_t)z * HD * Ntok;
    const __nv_bfloat16* Vl = g_vtl + (size_t)z * HD * Ntok;
    const float* aff = g_aff + b * Ntok;

    float acc[2][2][4];
    #pragma unroll
    for (int i = 0; i < 2; i++)
        #pragma unroll
        for (int j = 0; j < 2; j++)
            #pragma unroll
            for (int l = 0; l < 4; l++) acc[i][j][l] = 0.f;
    float rowAcc = 0.f;
    const int frow = tid >> 2;                     // 0..63
    const int fcol = (tid & 3) * 32;

    for (int ch = 0; ch < 8; ch++) {
        const int k0 = ch * 128;
        // B tiles via cp.async (overlaps A-fill compute below)
        #pragma unroll
        for (int j = 0; j < 4; j++) {
            int i = tid + j * 256;
            int r = i >> 4, c = (i & 15) * 8;
            CP16(sbase + BH0 + (uint32_t)(r * SR + c) * 2, Vh + (size_t)r * Ntok + k0 + c);
            CP16(sbase + BL0 + (uint32_t)(r * SR + c) * 2, Vl + (size_t)r * Ntok + k0 + c);
        }
        CP_COMMIT();
        // A operand: exp(S)*aff, hi/lo split
        const float4* s4 = (const float4*)(Srow + (size_t)frow * Ntok + k0 + fcol);
        const float4* a4 = (const float4*)(aff + k0 + fcol);
        float rs = 0.f;
        #pragma unroll
        for (int j = 0; j < 8; j++) {
            float4 s = s4[j];
            float4 a = a4[j];
            float e0 = __expf(s.x), e1 = __expf(s.y), e2 = __expf(s.z), e3 = __expf(s.w);
            rs += (e0 + e1) + (e2 + e3);
            float4 p = make_float4(e0 * a.x, e1 * a.y, e2 * a.z, e3 * a.w);
            int off = frow * SR + fcol + j * 4;
            split4(p, (__nv_bfloat162*)(Ah_s + off), (__nv_bfloat162*)(Al_s + off));
        }
        rs += __shfl_xor_sync(0xffffffffu, rs, 1);
        rs += __shfl_xor_sync(0xffffffffu, rs, 2);
        rowAcc += rs;
        CP_WAIT(0);
        __syncthreads();
        // MMA over this 128-k chunk
        #pragma unroll
        for (int ks = 0; ks < 128; ks += 16) {
            uint32_t ah[2][4], al2[2][4];
            const int arow = (lane & 7) + ((lane >> 3) & 1) * 8;
            const int acol = ks + (lane >> 4) * 8;
            #pragma unroll
            for (int mt = 0; mt < 2; mt++) {
                uint32_t off = (uint32_t)((wm * 32 + mt * 16 + arow) * SR + acol) * 2;
                LDSM4(ah[mt],  sbase + AH0 + off);
                LDSM4(al2[mt], sbase + AL0 + off);
            }
            uint32_t bh[2][2], bl2[2][2];
            const int g = lane >> 3;
            const int brow = (g >> 1) * 8 + (lane & 7);
            const int bcol = ks + (g & 1) * 8;
            {
                uint32_t off = (uint32_t)((wn * 16 + brow) * SR + bcol) * 2;
                uint32_t t[4];
                LDSM4(t, sbase + BH0 + off);
                bh[0][0] = t[0]; bh[0][1] = t[1]; bh[1][0] = t[2]; bh[1][1] = t[3];
                LDSM4(t, sbase + BL0 + off);
                bl2[0][0] = t[0]; bl2[0][1] = t[1]; bl2[1][0] = t[2]; bl2[1][1] = t[3];
            }
            #pragma unroll
            for (int mt = 0; mt < 2; mt++)
                #pragma unroll
                for (int nt = 0; nt < 2; nt++) {
                    MMA_BF16(acc[mt][nt], ah[mt],  bh[nt]);
                    MMA_BF16(acc[mt][nt], ah[mt],  bl2[nt]);
                    MMA_BF16(acc[mt][nt], al2[mt], bh[nt]);
                }
        }
        __syncthreads();
    }
    if ((tid & 3) == 0) rowsum_s[frow] = rowAcc;
    __syncthreads();

    // epilogue: normalize, split, scatter
    const int gidr = lane >> 2, qid = lane & 3;
    #pragma unroll
    for (int mt = 0; mt < 2; mt++) {
        int row = wm * 32 + mt * 16 + gidr;
        float inv0 = 1.f / rowsum_s[row];
        float inv8 = 1.f / rowsum_s[row + 8];
        #pragma unroll
        for (int nt = 0; nt < 2; nt++) {
            int col = wn * 16 + nt * 8 + qid * 2;
            float x0 = acc[mt][nt][0] * inv0, x1 = acc[mt][nt][1] * inv0;
            float x2 = acc[mt][nt][2] * inv8, x3 = acc[mt][nt][3] * inv8;
            __nv_bfloat16 h0 = __float2bfloat16(x0), h1 = __float2bfloat16(x1);
            __nv_bfloat16 h2 = __float2bfloat16(x2), h3 = __float2bfloat16(x3);
            __nv_bfloat16 l0 = __float2bfloat16(x0 - __bfloat162float(h0));
            __nv_bfloat16 l1 = __float2bfloat16(x1 - __bfloat162float(h1));
            __nv_bfloat16 l2 = __float2bfloat16(x2 - __bfloat162float(h2));
            __nv_bfloat16 l3 = __float2bfloat16(x3 - __bfloat162float(h3));
            size_t o0 = ((size_t)b * Ntok + m0 + row) * Cdim + h * HD + col;
            size_t o8 = o0 + 8u * Cdim;
            *(__nv_bfloat162*)(g_oh + o0) = __nv_bfloat162(h0, h1);
            *(__nv_bfloat162*)(g_ol + o0) = __nv_bfloat162(l0, l1);
            *(__nv_bfloat162*)(g_oh + o8) = __nv_bfloat162(h2, h3);
            *(__nv_bfloat162*)(g_ol + o8) = __nv_bfloat162(l2, l3);
        }
    }
}

// ======================= output projection ==================================
__global__ void __launch_bounds__(256, 2) proj_mma(const float* __restrict__ bp,
                                                   float* __restrict__ out)
{
    extern __shared__ char smem[];
    const int m0 = blockIdx.y * 128, n0 = blockIdx.x * 128;

    const __nv_bfloat16* Ah = g_oh + (size_t)m0 * 768;
    const __nv_bfloat16* Al = g_ol + (size_t)m0 * 768;
    const __nv_bfloat16* Bh = g_wh + (size_t)3 * 768 * 768 + (size_t)n0 * 768;
    const __nv_bfloat16* Bl = g_wl + (size_t)3 * 768 * 768 + (size_t)n0 * 768;

    gemm_to_stage<128>(Ah, Al, 768, Bh, Bl, 768, 768, smem);
    float* stage = (float*)smem;

    for (int idx = threadIdx.x; idx < 128 * 128; idx += 256) {
        int mr = idx >> 7, nc = idx & 127;
        int n = n0 + nc;
        out[(size_t)(m0 + mr) * Cdim + n] = stage[mr * 129 + nc] + bp[n];
    }
}

// ============================================================================
extern "C" void kernel_launch(void* const* d_in, const int* in_sizes, int n_in,
                              void* d_out, int out_size)
{
    (void)in_sizes; (void)n_in; (void)out_size;
    const float* xq = (const float*)d_in[0];
    const float* xk = (const float*)d_in[1];
    const float* xv = (const float*)d_in[2];
    const float* et = (const float*)d_in[3];
    const float* Wq = (const float*)d_in[4];
    const float* Wk = (const float*)d_in[5];
    const float* Wv = (const float*)d_in[6];
    const float* Wp = (const float*)d_in[7];
    const float* bp = (const float*)d_in[8];

    float* out     = (float*)d_out;
    float* out_x   = out;
    float* out_as  = out + (size_t)Bsz * Ntok * Cdim;
    float* out_aff = out_as + (size_t)Bsz * Ntok * Ntok;

    const int SMEM_BIG = 81920;
    const int SMEM_PVF = 69888;
    cudaFuncSetAttribute(qkv_mma,    cudaFuncAttributeMaxDynamicSharedMemorySize, SMEM_BIG);
    cudaFuncSetAttribute(scores_mma, cudaFuncAttributeMaxDynamicSharedMemorySize, SMEM_BIG);
    cudaFuncSetAttribute(pv_fused,   cudaFuncAttributeMaxDynamicSharedMemorySize, SMEM_PVF);
    cudaFuncSetAttribute(proj_mma,   cudaFuncAttributeMaxDynamicSharedMemorySize, SMEM_BIG);

    const int NX4 = 8192 * 768 / 4, NW4 = 768 * 768 / 4;
    cvtX_kernel<<<dim3((NX4 + 255) / 256, 1, 3), 256>>>((const float4*)xq, (const float4*)xk,
                                                        (const float4*)xv, NX4);
    cvtW_kernel<<<dim3((NW4 + 255) / 256, 1, 4), 256>>>((const float4*)Wq, (const float4*)Wk,
                                                        (const float4*)Wv, (const float4*)Wp, NW4);

    qkv_mma<<<dim3(6, 64, 3), 256, SMEM_BIG>>>();
    aff_kernel<<<(Bsz * Ntok) / 8, 256>>>(et, out_aff);
    scores_mma<<<dim3(8, 8, BH), 256, SMEM_BIG>>>();
    attnsave_kernel<<<(Bsz * Ntok * Ntok / 4) / 256, 256>>>(out_as);
    pv_fused<<<dim3(1, 16, BH), 256, SMEM_PVF>>>();
    proj_mma<<<dim3(6, 64, 1), 256, SMEM_BIG>>>(bp, out_x);
}

// round 6
// speedup vs baseline: 3.7902x; 1.0030x over previous
#include <cuda_runtime.h>
#include <cuda_bf16.h>
#include <cstdint>

#define Bsz 8
#define Ntok 1024
#define Cdim 768
#define Hh 12
#define HD 64
#define BH (Bsz*Hh)
#define SCALE 0.125f

// ======================= PTX helpers (sm_80+ baseline) ======================
__device__ __forceinline__ uint32_t smem_to_u32(const void* p) {
    uint32_t a;
    asm("{ .reg .u64 t; cvta.to.shared.u64 t, %1; cvt.u32.u64 %0, t; }" : "=r"(a) : "l"(p));
    return a;
}
#define LDSM4(r, addr) \
    asm volatile("ldmatrix.sync.aligned.m8n8.x4.shared.b16 {%0,%1,%2,%3}, [%4];" \
        : "=r"((r)[0]), "=r"((r)[1]), "=r"((r)[2]), "=r"((r)[3]) : "r"(addr))
#define MMA_BF16(d, a, b) \
    asm volatile("mma.sync.aligned.m16n8k16.row.col.f32.bf16.bf16.f32 " \
        "{%0,%1,%2,%3}, {%4,%5,%6,%7}, {%8,%9}, {%0,%1,%2,%3};" \
        : "+f"((d)[0]), "+f"((d)[1]), "+f"((d)[2]), "+f"((d)[3]) \
        : "r"((a)[0]), "r"((a)[1]), "r"((a)[2]), "r"((a)[3]), "r"((b)[0]), "r"((b)[1]))
#define CP16(dst_u32, src_ptr) \
    asm volatile("cp.async.cg.shared.global [%0], [%1], 16;" :: "r"(dst_u32), "l"(src_ptr))
#define CP_COMMIT() asm volatile("cp.async.commit_group;")
#define CP_WAIT(n)  asm volatile("cp.async.wait_group %0;" :: "n"(n))

// ======================= scratch globals ====================================
__device__ __align__(16) __nv_bfloat16 g_xh[3u * 8192u * 768u];
__device__ __align__(16) __nv_bfloat16 g_xl[3u * 8192u * 768u];
__device__ __align__(16) __nv_bfloat16 g_wh[4u * 768u * 768u];
__device__ __align__(16) __nv_bfloat16 g_wl[4u * 768u * 768u];
__device__ __align__(16) __nv_bfloat16 g_qh[BH * Ntok * HD];
__device__ __align__(16) __nv_bfloat16 g_ql[BH * Ntok * HD];
__device__ __align__(16) __nv_bfloat16 g_kh[BH * Ntok * HD];
__device__ __align__(16) __nv_bfloat16 g_kl[BH * Ntok * HD];
__device__ __align__(16) __nv_bfloat16 g_vth[BH * HD * Ntok];   // [b,h,hd,tok]
__device__ __align__(16) __nv_bfloat16 g_vtl[BH * HD * Ntok];
__device__ float g_attn[(size_t)BH * Ntok * Ntok];
__device__ __align__(16) __nv_bfloat16 g_oh[8192u * 768u];
__device__ __align__(16) __nv_bfloat16 g_ol[8192u * 768u];
__device__ __align__(16) float g_aff[Bsz * Ntok];

// ======================= fp32 -> bf16 hi/lo split (batched) =================
__device__ __forceinline__ void split4(float4 v, __nv_bfloat162* hi2, __nv_bfloat162* lo2)
{
    __nv_bfloat16 h0 = __float2bfloat16(v.x), h1 = __float2bfloat16(v.y);
    __nv_bfloat16 h2 = __float2bfloat16(v.z), h3 = __float2bfloat16(v.w);
    __nv_bfloat16 l0 = __float2bfloat16(v.x - __bfloat162float(h0));
    __nv_bfloat16 l1 = __float2bfloat16(v.y - __bfloat162float(h1));
    __nv_bfloat16 l2 = __float2bfloat16(v.z - __bfloat162float(h2));
    __nv_bfloat16 l3 = __float2bfloat16(v.w - __bfloat162float(h3));
    hi2[0] = __nv_bfloat162(h0, h1); hi2[1] = __nv_bfloat162(h2, h3);
    lo2[0] = __nv_bfloat162(l0, l1); lo2[1] = __nv_bfloat162(l2, l3);
}

__global__ void cvtX_kernel(const float4* __restrict__ s0, const float4* __restrict__ s1,
                            const float4* __restrict__ s2, int n4)
{
    int i = blockIdx.x * 256 + threadIdx.x;
    if (i >= n4) return;
    int z = blockIdx.z;
    const float4* src = (z == 0) ? s0 : (z == 1) ? s1 : s2;
    size_t off = (size_t)z * n4 + i;
    split4(src[i], (__nv_bfloat162*)g_xh + off * 2, (__nv_bfloat162*)g_xl + off * 2);
}
__global__ void cvtW_kernel(const float4* __restrict__ s0, const float4* __restrict__ s1,
                            const float4* __restrict__ s2, const float4* __restrict__ s3, int n4)
{
    int i = blockIdx.x * 256 + threadIdx.x;
    if (i >= n4) return;
    int z = blockIdx.z;
    const float4* src = (z == 0) ? s0 : (z == 1) ? s1 : (z == 2) ? s2 : s3;
    size_t off = (size_t)z * n4 + i;
    split4(src[i], (__nv_bfloat162*)g_wh + off * 2, (__nv_bfloat162*)g_wl + off * 2);
}

// ======================= generic mma.sync GEMM (cp.async) ===================
// C[128, BN] = Ah@Bh^T + Ah@Bl^T + Al@Bh^T. Result in SMEM stage, stride BN+1.
// 3 hi/lo terms issued TERM-OUTERMOST so consecutive MMAs hit different acc
// tiles (acc RAW chain broken; ~16-MMA reuse distance).
template <int BN>
__device__ __forceinline__ void gemm_to_stage(
    const __nv_bfloat16* __restrict__ Ah, const __nv_bfloat16* __restrict__ Al, int lda,
    const __nv_bfloat16* __restrict__ Bh, const __nv_bfloat16* __restrict__ Bl, int ldb,
    int kTotal, char* smem)
{
    constexpr int SROW = 40;
    constexpr int A_H0 = 0;
    constexpr int A_L0 = 128 * SROW;
    constexpr int B_H0 = 2 * 128 * SROW;
    constexpr int B_L0 = B_H0 + BN * SROW;
    constexpr int BUFH = B_H0 + 2 * BN * SROW;
    constexpr int WN = BN / 2;
    constexpr int NT = BN / 16;
    constexpr int NTP = NT / 2;
    constexpr int NBJ = BN / 64;

    const uint32_t sbase = smem_to_u32(smem);
    const int tid = threadIdx.x, lane = tid & 31, wid = tid >> 5;
    const int wm = wid & 3, wn = wid >> 2;

    float acc[2][NT][4];
    #pragma unroll
    for (int i = 0; i < 2; i++)
        #pragma unroll
        for (int j = 0; j < NT; j++)
            #pragma unroll
            for (int l = 0; l < 4; l++) acc[i][j][l] = 0.f;

    auto CPA = [&](int buf, int k0) {
        uint32_t p = sbase + (uint32_t)buf * BUFH * 2u;
        #pragma unroll
        for (int j = 0; j < 2; j++) {
            int i = tid + j * 256, r = i >> 2, c = (i & 3) << 3;
            CP16(p + (A_H0 + r * SROW + c) * 2, Ah + (size_t)r * lda + k0 + c);
            CP16(p + (A_L0 + r * SROW + c) * 2, Al + (size_t)r * lda + k0 + c);
        }
        #pragma unroll
        for (int j = 0; j < NBJ; j++) {
            int i = tid + j * 256, r = i >> 2, c = (i & 3) << 3;
            CP16(p + (B_H0 + r * SROW + c) * 2, Bh + (size_t)r * ldb + k0 + c);
            CP16(p + (B_L0 + r * SROW + c) * 2, Bl + (size_t)r * ldb + k0 + c);
        }
        CP_COMMIT();
    };
    auto COMPUTE = [&](int buf) {
        const uint32_t base = sbase + (uint32_t)buf * BUFH * 2;
        #pragma unroll
        for (int ks = 0; ks < 32; ks += 16) {
            uint32_t ah[2][4], al2[2][4];
            const int arow = (lane & 7) + ((lane >> 3) & 1) * 8;
            const int acol = ks + (lane >> 4) * 8;
            #pragma unroll
            for (int mt = 0; mt < 2; mt++) {
                uint32_t off = (uint32_t)((wm * 32 + mt * 16 + arow) * SROW + acol) * 2;
                LDSM4(ah[mt],  base + A_H0 * 2 + off);
                LDSM4(al2[mt], base + A_L0 * 2 + off);
            }
            uint32_t bh[NT][2], bl2[NT][2];
            const int g = lane >> 3;
            const int brow = (g >> 1) * 8 + (lane & 7);
            const int bcol = ks + (g & 1) * 8;
            #pragma unroll
            for (int np = 0; np < NTP; np++) {
                uint32_t off = (uint32_t)((wn * WN + np * 16 + brow) * SROW + bcol) * 2;
                uint32_t t[4];
                LDSM4(t, base + B_H0 * 2 + off);
                bh[2 * np][0] = t[0]; bh[2 * np][1] = t[1];
                bh[2 * np + 1][0] = t[2]; bh[2 * np + 1][1] = t[3];
                LDSM4(t, base + B_L0 * 2 + off);
                bl2[2 * np][0] = t[0]; bl2[2 * np][1] = t[1];
                bl2[2 * np + 1][0] = t[2]; bl2[2 * np + 1][1] = t[3];
            }
            // term-outer: all acc tiles touched between repeats of the same tile
            #pragma unroll
            for (int mt = 0; mt < 2; mt++)
                #pragma unroll
                for (int nt = 0; nt < NT; nt++)
                    MMA_BF16(acc[mt][nt], ah[mt], bh[nt]);
            #pragma unroll
            for (int mt = 0; mt < 2; mt++)
                #pragma unroll
                for (int nt = 0; nt < NT; nt++)
                    MMA_BF16(acc[mt][nt], ah[mt], bl2[nt]);
            #pragma unroll
            for (int mt = 0; mt < 2; mt++)
                #pragma unroll
                for (int nt = 0; nt < NT; nt++)
                    MMA_BF16(acc[mt][nt], al2[mt], bh[nt]);
        }
    };

    const int nCh = kTotal >> 5;
    CPA(0, 0);
    for (int ch = 0; ch < nCh; ch++) {
        if (ch + 1 < nCh) { CPA((ch + 1) & 1, (ch + 1) << 5); CP_WAIT(1); }
        else              { CP_WAIT(0); }
        __syncthreads();
        COMPUTE(ch & 1);
        __syncthreads();
    }

    float* stage = (float*)smem;
    const int gidr = lane >> 2, qid = lane & 3;
    #pragma unroll
    for (int mt = 0; mt < 2; mt++)
        #pragma unroll
        for (int nt = 0; nt < NT; nt++) {
            int row = wm * 32 + mt * 16 + gidr;
            int col = wn * WN + nt * 8 + qid * 2;
            stage[row * (BN + 1) + col]           = acc[mt][nt][0];
            stage[row * (BN + 1) + col + 1]       = acc[mt][nt][1];
            stage[(row + 8) * (BN + 1) + col]     = acc[mt][nt][2];
            stage[(row + 8) * (BN + 1) + col + 1] = acc[mt][nt][3];
        }
    __syncthreads();
}

// ======================= QKV projection =====================================
__global__ void __launch_bounds__(256, 2) qkv_mma()
{
    extern __shared__ char smem[];
    const int z = blockIdx.z;
    const int m0 = blockIdx.y * 128, n0 = blockIdx.x * 128;

    const __nv_bfloat16* Ah = g_xh + (size_t)z * 8192 * 768 + (size_t)m0 * 768;
    const __nv_bfloat16* Al = g_xl + (size_t)z * 8192 * 768 + (size_t)m0 * 768;
    const __nv_bfloat16* Bh = g_wh + (size_t)z * 768 * 768 + (size_t)n0 * 768;
    const __nv_bfloat16* Bl = g_wl + (size_t)z * 768 * 768 + (size_t)n0 * 768;

    gemm_to_stage<128>(Ah, Al, 768, Bh, Bl, 768, 768, smem);
    float* stage = (float*)smem;

    const int tid = threadIdx.x;
    if (z < 2) {
        __nv_bfloat16* dh = (z == 0) ? g_qh : g_kh;
        __nv_bfloat16* dl = (z == 0) ? g_ql : g_kl;
        for (int idx = tid; idx < 128 * 128; idx += 256) {
            int mr = idx >> 7, nc = idx & 127;
            int m = m0 + mr, n = n0 + nc;
            int b = m >> 10, tok = m & 1023, h = n >> 6, hd = n & 63;
            float v = stage[mr * 129 + nc];
            __nv_bfloat16 hi = __float2bfloat16(v);
            __nv_bfloat16 lo = __float2bfloat16(v - __bfloat162float(hi));
            size_t o = (((size_t)(b * Hh + h)) * Ntok + tok) * HD + hd;
            dh[o] = hi; dl[o] = lo;
        }
    } else {
        for (int idx = tid; idx < 128 * 128; idx += 256) {
            int mr = idx & 127, nc = idx >> 7;
            int m = m0 + mr, n = n0 + nc;
            int b = m >> 10, tok = m & 1023, h = n >> 6, hd = n & 63;
            float v = stage[mr * 129 + nc];
            __nv_bfloat16 hi = __float2bfloat16(v);
            __nv_bfloat16 lo = __float2bfloat16(v - __bfloat162float(hi));
            size_t o = (((size_t)(b * Hh + h)) * HD + hd) * Ntok + tok;
            g_vth[o] = hi; g_vtl[o] = lo;
        }
    }
}

// ======================= affinity gate ======================================
__global__ void aff_kernel(const float* __restrict__ et, float* __restrict__ out_aff)
{
    int warp = (blockIdx.x * blockDim.x + threadIdx.x) >> 5;
    int lane = threadIdx.x & 31;
    if (warp >= Bsz * Ntok) return;
    int b = warp >> 10, tok = warp & 1023;
    float s = 0.f;
    for (int c = lane; c < Cdim; c += 32) {
        int h = c >> 6, hd = c & 63;
        size_t o = (((size_t)(b * Hh + h)) * Ntok + tok) * HD + hd;
        float kv = __bfloat162float(g_kh[o]) + __bfloat162float(g_kl[o]);
        s += et[b * Cdim + c] * kv;
    }
    #pragma unroll
    for (int o = 16; o; o >>= 1) s += __shfl_xor_sync(0xffffffffu, s, o);
    if (lane == 0) {
        float v = 1.f / (1.f + __expf(-(SCALE / Hh) * s));
        g_aff[warp] = v;
        out_aff[warp] = v;
    }
}

// ======================= scores =============================================
__global__ void __launch_bounds__(256, 2) scores_mma()
{
    extern __shared__ char smem[];
    const int z = blockIdx.z;
    const int m0 = blockIdx.y * 128, n0 = blockIdx.x * 128;

    const __nv_bfloat16* Ah = g_qh + (size_t)z * Ntok * HD + (size_t)m0 * HD;
    const __nv_bfloat16* Al = g_ql + (size_t)z * Ntok * HD + (size_t)m0 * HD;
    const __nv_bfloat16* Bh = g_kh + (size_t)z * Ntok * HD + (size_t)n0 * HD;
    const __nv_bfloat16* Bl = g_kl + (size_t)z * Ntok * HD + (size_t)n0 * HD;

    gemm_to_stage<128>(Ah, Al, HD, Bh, Bl, HD, HD, smem);
    float* stage = (float*)smem;

    float* out = g_attn + (size_t)z * Ntok * Ntok;
    for (int idx = threadIdx.x; idx < 128 * 128; idx += 256) {
        int mr = idx >> 7, nc = idx & 127;
        out[(size_t)(m0 + mr) * Ntok + n0 + nc] = stage[mr * 129 + nc] * SCALE;
    }
}

// ======================= attn_save ==========================================
__global__ void attnsave_kernel(float* __restrict__ out_as)
{
    size_t idx = (size_t)blockIdx.x * 256 + threadIdx.x;
    int k4 = (int)(idx & 255);
    size_t bq = idx >> 8;
    int b = (int)(bq >> 10);
    float4 s = make_float4(0.f, 0.f, 0.f, 0.f);
    int q = (int)(bq & 1023);
    #pragma unroll
    for (int h = 0; h < Hh; h++) {
        const float4* p = (const float4*)(g_attn + ((size_t)(b * Hh + h) * Ntok + q) * Ntok);
        float4 v = p[k4];
        s.x += v.x; s.y += v.y; s.z += v.z; s.w += v.w;
    }
    const float inv = 1.f / Hh;
    s.x *= inv; s.y *= inv; s.z *= inv; s.w *= inv;
    ((float4*)out_as)[bq * 256 + k4] = s;
}

// ======================= fused softmax + PV (BM=64) =========================
__global__ void __launch_bounds__(256, 2) pv_fused()
{
    extern __shared__ char smem[];
    constexpr int SR = 136;
    constexpr uint32_t AH0 = 0;
    constexpr uint32_t AL0 = 64u * SR * 2u;
    constexpr uint32_t BH0 = 2u * 64u * SR * 2u;
    constexpr uint32_t BL0 = BH0 + 64u * SR * 2u;
    constexpr uint32_t RS0 = BL0 + 64u * SR * 2u;

    __nv_bfloat16* Ah_s = (__nv_bfloat16*)(smem + AH0);
    __nv_bfloat16* Al_s = (__nv_bfloat16*)(smem + AL0);
    float* rowsum_s = (float*)(smem + RS0);
    const uint32_t sbase = smem_to_u32(smem);

    const int z = blockIdx.z;
    const int m0 = blockIdx.y * 64;
    const int b = z / Hh, h = z % Hh;
    const int tid = threadIdx.x, lane = tid & 31, wid = tid >> 5;
    const int wm = wid & 1, wn = wid >> 1;

    const float* Srow = g_attn + (size_t)z * Ntok * Ntok + (size_t)m0 * Ntok;
    const __nv_bfloat16* Vh = g_vth + (size_t)z * HD * Ntok;
    const __nv_bfloat16* Vl = g_vtl + (size_t)z * HD * Ntok;
    const float* aff = g_aff + b * Ntok;

    float acc[2][2][4];
    #pragma unroll
    for (int i = 0; i < 2; i++)
        #pragma unroll
        for (int j = 0; j < 2; j++)
            #pragma unroll
            for (int l = 0; l < 4; l++) acc[i][j][l] = 0.f;
    float rowAcc = 0.f;
    const int frow = tid >> 2;
    const int fcol = (tid & 3) * 32;

    for (int ch = 0; ch < 8; ch++) {
        const int k0 = ch * 128;
        #pragma unroll
        for (int j = 0; j < 4; j++) {
            int i = tid + j * 256;
            int r = i >> 4, c = (i & 15) * 8;
            CP16(sbase + BH0 + (uint32_t)(r * SR + c) * 2, Vh + (size_t)r * Ntok + k0 + c);
            CP16(sbase + BL0 + (uint32_t)(r * SR + c) * 2, Vl + (size_t)r * Ntok + k0 + c);
        }
        CP_COMMIT();
        const float4* s4 = (const float4*)(Srow + (size_t)frow * Ntok + k0 + fcol);
        const float4* a4 = (const float4*)(aff + k0 + fcol);
        float rs = 0.f;
        #pragma unroll
        for (int j = 0; j < 8; j++) {
            float4 s = s4[j];
            float4 a = a4[j];
            float e0 = __expf(s.x), e1 = __expf(s.y), e2 = __expf(s.z), e3 = __expf(s.w);
            rs += (e0 + e1) + (e2 + e3);
            float4 p = make_float4(e0 * a.x, e1 * a.y, e2 * a.z, e3 * a.w);
            int off = frow * SR + fcol + j * 4;
            split4(p, (__nv_bfloat162*)(Ah_s + off), (__nv_bfloat162*)(Al_s + off));
        }
        rs += __shfl_xor_sync(0xffffffffu, rs, 1);
        rs += __shfl_xor_sync(0xffffffffu, rs, 2);
        rowAcc += rs;
        CP_WAIT(0);
        __syncthreads();
        #pragma unroll
        for (int ks = 0; ks < 128; ks += 16) {
            uint32_t ah[2][4], al2[2][4];
            const int arow = (lane & 7) + ((lane >> 3) & 1) * 8;
            const int acol = ks + (lane >> 4) * 8;
            #pragma unroll
            for (int mt = 0; mt < 2; mt++) {
                uint32_t off = (uint32_t)((wm * 32 + mt * 16 + arow) * SR + acol) * 2;
                LDSM4(ah[mt],  sbase + AH0 + off);
                LDSM4(al2[mt], sbase + AL0 + off);
            }
            uint32_t bh[2][2], bl2[2][2];
            const int g = lane >> 3;
            const int brow = (g >> 1) * 8 + (lane & 7);
            const int bcol = ks + (g & 1) * 8;
            {
                uint32_t off = (uint32_t)((wn * 16 + brow) * SR + bcol) * 2;
                uint32_t t[4];
                LDSM4(t, sbase + BH0 + off);
                bh[0][0] = t[0]; bh[0][1] = t[1]; bh[1][0] = t[2]; bh[1][1] = t[3];
                LDSM4(t, sbase + BL0 + off);
                bl2[0][0] = t[0]; bl2[0][1] = t[1]; bl2[1][0] = t[2]; bl2[1][1] = t[3];
            }
            // term-outer ordering (acc chain broken)
            #pragma unroll
            for (int mt = 0; mt < 2; mt++)
                #pragma unroll
                for (int nt = 0; nt < 2; nt++)
                    MMA_BF16(acc[mt][nt], ah[mt], bh[nt]);
            #pragma unroll
            for (int mt = 0; mt < 2; mt++)
                #pragma unroll
                for (int nt = 0; nt < 2; nt++)
                    MMA_BF16(acc[mt][nt], ah[mt], bl2[nt]);
            #pragma unroll
            for (int mt = 0; mt < 2; mt++)
                #pragma unroll
                for (int nt = 0; nt < 2; nt++)
                    MMA_BF16(acc[mt][nt], al2[mt], bh[nt]);
        }
        __syncthreads();
    }
    if ((tid & 3) == 0) rowsum_s[frow] = rowAcc;
    __syncthreads();

    const int gidr = lane >> 2, qid = lane & 3;
    #pragma unroll
    for (int mt = 0; mt < 2; mt++) {
        int row = wm * 32 + mt * 16 + gidr;
        float inv0 = 1.f / rowsum_s[row];
        float inv8 = 1.f / rowsum_s[row + 8];
        #pragma unroll
        for (int nt = 0; nt < 2; nt++) {
            int col = wn * 16 + nt * 8 + qid * 2;
            float x0 = acc[mt][nt][0] * inv0, x1 = acc[mt][nt][1] * inv0;
            float x2 = acc[mt][nt][2] * inv8, x3 = acc[mt][nt][3] * inv8;
            __nv_bfloat16 h0 = __float2bfloat16(x0), h1 = __float2bfloat16(x1);
            __nv_bfloat16 h2 = __float2bfloat16(x2), h3 = __float2bfloat16(x3);
            __nv_bfloat16 l0 = __float2bfloat16(x0 - __bfloat162float(h0));
            __nv_bfloat16 l1 = __float2bfloat16(x1 - __bfloat162float(h1));
            __nv_bfloat16 l2 = __float2bfloat16(x2 - __bfloat162float(h2));
            __nv_bfloat16 l3 = __float2bfloat16(x3 - __bfloat162float(h3));
            size_t o0 = ((size_t)b * Ntok + m0 + row) * Cdim + h * HD + col;
            size_t o8 = o0 + 8u * Cdim;
            *(__nv_bfloat162*)(g_oh + o0) = __nv_bfloat162(h0, h1);
            *(__nv_bfloat162*)(g_ol + o0) = __nv_bfloat162(l0, l1);
            *(__nv_bfloat162*)(g_oh + o8) = __nv_bfloat162(h2, h3);
            *(__nv_bfloat162*)(g_ol + o8) = __nv_bfloat162(l2, l3);
        }
    }
}

// ======================= output projection ==================================
__global__ void __launch_bounds__(256, 2) proj_mma(const float* __restrict__ bp,
                                                   float* __restrict__ out)
{
    extern __shared__ char smem[];
    const int m0 = blockIdx.y * 128, n0 = blockIdx.x * 128;

    const __nv_bfloat16* Ah = g_oh + (size_t)m0 * 768;
    const __nv_bfloat16* Al = g_ol + (size_t)m0 * 768;
    const __nv_bfloat16* Bh = g_wh + (size_t)3 * 768 * 768 + (size_t)n0 * 768;
    const __nv_bfloat16* Bl = g_wl + (size_t)3 * 768 * 768 + (size_t)n0 * 768;

    gemm_to_stage<128>(Ah, Al, 768, Bh, Bl, 768, 768, smem);
    float* stage = (float*)smem;

    for (int idx = threadIdx.x; idx < 128 * 128; idx += 256) {
        int mr = idx >> 7, nc = idx & 127;
        int n = n0 + nc;
        out[(size_t)(m0 + mr) * Cdim + n] = stage[mr * 129 + nc] + bp[n];
    }
}

// ============================================================================
extern "C" void kernel_launch(void* const* d_in, const int* in_sizes, int n_in,
                              void* d_out, int out_size)
{
    (void)in_sizes; (void)n_in; (void)out_size;
    const float* xq = (const float*)d_in[0];
    const float* xk = (const float*)d_in[1];
    const float* xv = (const float*)d_in[2];
    const float* et = (const float*)d_in[3];
    const float* Wq = (const float*)d_in[4];
    const float* Wk = (const float*)d_in[5];
    const float* Wv = (const float*)d_in[6];
    const float* Wp = (const float*)d_in[7];
    const float* bp = (const float*)d_in[8];

    float* out     = (float*)d_out;
    float* out_x   = out;
    float* out_as  = out + (size_t)Bsz * Ntok * Cdim;
    float* out_aff = out_as + (size_t)Bsz * Ntok * Ntok;

    const int SMEM_BIG = 81920;
    const int SMEM_PVF = 69888;
    cudaFuncSetAttribute(qkv_mma,    cudaFuncAttributeMaxDynamicSharedMemorySize, SMEM_BIG);
    cudaFuncSetAttribute(scores_mma, cudaFuncAttributeMaxDynamicSharedMemorySize, SMEM_BIG);
    cudaFuncSetAttribute(pv_fused,   cudaFuncAttributeMaxDynamicSharedMemorySize, SMEM_PVF);
    cudaFuncSetAttribute(proj_mma,   cudaFuncAttributeMaxDynamicSharedMemorySize, SMEM_BIG);

    const int NX4 = 8192 * 768 / 4, NW4 = 768 * 768 / 4;
    cvtX_kernel<<<dim3((NX4 + 255) / 256, 1, 3), 256>>>((const float4*)xq, (const float4*)xk,
                                                        (const float4*)xv, NX4);
    cvtW_kernel<<<dim3((NW4 + 255) / 256, 1, 4), 256>>>((const float4*)Wq, (const float4*)Wk,
                                                        (const float4*)Wv, (const float4*)Wp, NW4);

    qkv_mma<<<dim3(6, 64, 3), 256, SMEM_BIG>>>();
    aff_kernel<<<(Bsz * Ntok) / 8, 256>>>(et, out_aff);
    scores_mma<<<dim3(8, 8, BH), 256, SMEM_BIG>>>();
    attnsave_kernel<<<(Bsz * Ntok * Ntok / 4) / 256, 256>>>(out_as);
    pv_fused<<<dim3(1, 16, BH), 256, SMEM_PVF>>>();
    proj_mma<<<dim3(6, 64, 1), 256, SMEM_BIG>>>(bp, out_x);
}

// round 7
// speedup vs baseline: 5.6292x; 1.4852x over previous
#include <cuda_runtime.h>
#include <cuda_fp16.h>
#include <cstdint>

#define Bsz 8
#define Ntok 1024
#define Cdim 768
#define Hh 12
#define HD 64
#define BH (Bsz*Hh)
#define SCALE 0.125f

// ======================= PTX helpers (sm_80+ baseline) ======================
__device__ __forceinline__ uint32_t smem_to_u32(const void* p) {
    uint32_t a;
    asm("{ .reg .u64 t; cvta.to.shared.u64 t, %1; cvt.u32.u64 %0, t; }" : "=r"(a) : "l"(p));
    return a;
}
#define LDSM4(r, addr) \
    asm volatile("ldmatrix.sync.aligned.m8n8.x4.shared.b16 {%0,%1,%2,%3}, [%4];" \
        : "=r"((r)[0]), "=r"((r)[1]), "=r"((r)[2]), "=r"((r)[3]) : "r"(addr))
#define MMA_F16(d, a, b) \
    asm volatile("mma.sync.aligned.m16n8k16.row.col.f32.f16.f16.f32 " \
        "{%0,%1,%2,%3}, {%4,%5,%6,%7}, {%8,%9}, {%0,%1,%2,%3};" \
        : "+f"((d)[0]), "+f"((d)[1]), "+f"((d)[2]), "+f"((d)[3]) \
        : "r"((a)[0]), "r"((a)[1]), "r"((a)[2]), "r"((a)[3]), "r"((b)[0]), "r"((b)[1]))
#define CP16(dst_u32, src_ptr) \
    asm volatile("cp.async.cg.shared.global [%0], [%1], 16;" :: "r"(dst_u32), "l"(src_ptr))
#define CP_COMMIT() asm volatile("cp.async.commit_group;")
#define CP_WAIT(n)  asm volatile("cp.async.wait_group %0;" :: "n"(n))

// ======================= scratch globals ====================================
__device__ __align__(16) __half g_x[3u * 8192u * 768u];   // xq|xk|xv fp16
__device__ __align__(16) __half g_w[4u * 768u * 768u];    // Wq|Wk|Wv|Wp fp16
__device__ __align__(16) __half g_q[BH * Ntok * HD];      // [b,h,tok,hd]
__device__ __align__(16) __half g_k[BH * Ntok * HD];
__device__ __align__(16) __half g_vt[BH * HD * Ntok];     // [b,h,hd,tok]
__device__ float g_attn[(size_t)BH * Ntok * Ntok];        // fp32 scores
__device__ __align__(16) __half g_o[8192u * 768u];        // attention out fp16
__device__ __align__(16) float g_aff[Bsz * Ntok];

// ======================= fp32 -> fp16 convert ===============================
__global__ void cvtX_kernel(const float4* __restrict__ s0, const float4* __restrict__ s1,
                            const float4* __restrict__ s2, int n4)
{
    int i = blockIdx.x * 256 + threadIdx.x;
    if (i >= n4) return;
    int z = blockIdx.z;
    const float4* src = (z == 0) ? s0 : (z == 1) ? s1 : s2;
    float4 v = src[i];
    size_t off = ((size_t)z * n4 + i) * 2;
    ((__half2*)g_x)[off]     = __floats2half2_rn(v.x, v.y);
    ((__half2*)g_x)[off + 1] = __floats2half2_rn(v.z, v.w);
}
__global__ void cvtW_kernel(const float4* __restrict__ s0, const float4* __restrict__ s1,
                            const float4* __restrict__ s2, const float4* __restrict__ s3, int n4)
{
    int i = blockIdx.x * 256 + threadIdx.x;
    if (i >= n4) return;
    int z = blockIdx.z;
    const float4* src = (z == 0) ? s0 : (z == 1) ? s1 : (z == 2) ? s2 : s3;
    float4 v = src[i];
    size_t off = ((size_t)z * n4 + i) * 2;
    ((__half2*)g_w)[off]     = __floats2half2_rn(v.x, v.y);
    ((__half2*)g_w)[off + 1] = __floats2half2_rn(v.z, v.w);
}

// ======================= single-term fp16 mma.sync GEMM =====================
// C[128, BN] = A @ B^T. A [128,K] K-major, B [BN,K]. Result in SMEM stage,
// stride BN+1 floats. 256 threads, double-buffered cp.async, K-chunk 32.
template <int BN>
__device__ __forceinline__ void gemm_to_stage(
    const __half* __restrict__ A, int lda,
    const __half* __restrict__ B, int ldb,
    int kTotal, char* smem)
{
    constexpr int SROW = 40;                   // halves per row (32 + 8 pad)
    constexpr int A_0 = 0;
    constexpr int B_0 = 128 * SROW;
    constexpr int BUFH = (128 + BN) * SROW;
    constexpr int WN = BN / 2;
    constexpr int NT = BN / 16;
    constexpr int NTP = NT / 2;
    constexpr int NBJ = BN / 64;

    const uint32_t sbase = smem_to_u32(smem);
    const int tid = threadIdx.x, lane = tid & 31, wid = tid >> 5;
    const int wm = wid & 3, wn = wid >> 2;

    float acc[2][NT][4];
    #pragma unroll
    for (int i = 0; i < 2; i++)
        #pragma unroll
        for (int j = 0; j < NT; j++)
            #pragma unroll
            for (int l = 0; l < 4; l++) acc[i][j][l] = 0.f;

    auto CPA = [&](int buf, int k0) {
        uint32_t p = sbase + (uint32_t)buf * BUFH * 2u;
        #pragma unroll
        for (int j = 0; j < 2; j++) {
            int i = tid + j * 256, r = i >> 2, c = (i & 3) << 3;
            CP16(p + (A_0 + r * SROW + c) * 2, A + (size_t)r * lda + k0 + c);
        }
        #pragma unroll
        for (int j = 0; j < NBJ; j++) {
            int i = tid + j * 256, r = i >> 2, c = (i & 3) << 3;
            CP16(p + (B_0 + r * SROW + c) * 2, B + (size_t)r * ldb + k0 + c);
        }
        CP_COMMIT();
    };
    auto COMPUTE = [&](int buf) {
        const uint32_t base = sbase + (uint32_t)buf * BUFH * 2;
        #pragma unroll
        for (int ks = 0; ks < 32; ks += 16) {
            uint32_t af[2][4];
            const int arow = (lane & 7) + ((lane >> 3) & 1) * 8;
            const int acol = ks + (lane >> 4) * 8;
            #pragma unroll
            for (int mt = 0; mt < 2; mt++) {
                uint32_t off = (uint32_t)((wm * 32 + mt * 16 + arow) * SROW + acol) * 2;
                LDSM4(af[mt], base + A_0 * 2 + off);
            }
            uint32_t bf[NT][2];
            const int g = lane >> 3;
            const int brow = (g >> 1) * 8 + (lane & 7);
            const int bcol = ks + (g & 1) * 8;
            #pragma unroll
            for (int np = 0; np < NTP; np++) {
                uint32_t off = (uint32_t)((wn * WN + np * 16 + brow) * SROW + bcol) * 2;
                uint32_t t[4];
                LDSM4(t, base + B_0 * 2 + off);
                bf[2 * np][0] = t[0]; bf[2 * np][1] = t[1];
                bf[2 * np + 1][0] = t[2]; bf[2 * np + 1][1] = t[3];
            }
            #pragma unroll
            for (int mt = 0; mt < 2; mt++)
                #pragma unroll
                for (int nt = 0; nt < NT; nt++)
                    MMA_F16(acc[mt][nt], af[mt], bf[nt]);
        }
    };

    const int nCh = kTotal >> 5;
    CPA(0, 0);
    for (int ch = 0; ch < nCh; ch++) {
        if (ch + 1 < nCh) { CPA((ch + 1) & 1, (ch + 1) << 5); CP_WAIT(1); }
        else              { CP_WAIT(0); }
        __syncthreads();
        COMPUTE(ch & 1);
        __syncthreads();
    }

    float* stage = (float*)smem;
    const int gidr = lane >> 2, qid = lane & 3;
    #pragma unroll
    for (int mt = 0; mt < 2; mt++)
        #pragma unroll
        for (int nt = 0; nt < NT; nt++) {
            int row = wm * 32 + mt * 16 + gidr;
            int col = wn * WN + nt * 8 + qid * 2;
            stage[row * (BN + 1) + col]           = acc[mt][nt][0];
            stage[row * (BN + 1) + col + 1]       = acc[mt][nt][1];
            stage[(row + 8) * (BN + 1) + col]     = acc[mt][nt][2];
            stage[(row + 8) * (BN + 1) + col + 1] = acc[mt][nt][3];
        }
    __syncthreads();
}

// ======================= QKV projection =====================================
__global__ void __launch_bounds__(256, 2) qkv_mma()
{
    extern __shared__ char smem[];
    const int z = blockIdx.z;
    const int m0 = blockIdx.y * 128, n0 = blockIdx.x * 128;

    const __half* A = g_x + (size_t)z * 8192 * 768 + (size_t)m0 * 768;
    const __half* B = g_w + (size_t)z * 768 * 768 + (size_t)n0 * 768;

    gemm_to_stage<128>(A, 768, B, 768, 768, smem);
    float* stage = (float*)smem;

    const int tid = threadIdx.x;
    if (z < 2) {
        __half* dst = (z == 0) ? g_q : g_k;
        for (int idx = tid; idx < 128 * 128; idx += 256) {
            int mr = idx >> 7, nc = idx & 127;
            int m = m0 + mr, n = n0 + nc;
            int b = m >> 10, tok = m & 1023, h = n >> 6, hd = n & 63;
            size_t o = (((size_t)(b * Hh + h)) * Ntok + tok) * HD + hd;
            dst[o] = __float2half(stage[mr * 129 + nc]);
        }
    } else {
        for (int idx = tid; idx < 128 * 128; idx += 256) {
            int mr = idx & 127, nc = idx >> 7;
            int m = m0 + mr, n = n0 + nc;
            int b = m >> 10, tok = m & 1023, h = n >> 6, hd = n & 63;
            size_t o = (((size_t)(b * Hh + h)) * HD + hd) * Ntok + tok;
            g_vt[o] = __float2half(stage[mr * 129 + nc]);
        }
    }
}

// ======================= affinity gate ======================================
__global__ void aff_kernel(const float* __restrict__ et, float* __restrict__ out_aff)
{
    int warp = (blockIdx.x * blockDim.x + threadIdx.x) >> 5;
    int lane = threadIdx.x & 31;
    if (warp >= Bsz * Ntok) return;
    int b = warp >> 10, tok = warp & 1023;
    float s = 0.f;
    for (int c = lane; c < Cdim; c += 32) {
        int h = c >> 6, hd = c & 63;
        size_t o = (((size_t)(b * Hh + h)) * Ntok + tok) * HD + hd;
        s += et[b * Cdim + c] * __half2float(g_k[o]);
    }
    #pragma unroll
    for (int o = 16; o; o >>= 1) s += __shfl_xor_sync(0xffffffffu, s, o);
    if (lane == 0) {
        float v = 1.f / (1.f + __expf(-(SCALE / Hh) * s));
        g_aff[warp] = v;
        out_aff[warp] = v;
    }
}

// ======================= scores =============================================
__global__ void __launch_bounds__(256, 2) scores_mma()
{
    extern __shared__ char smem[];
    const int z = blockIdx.z;
    const int m0 = blockIdx.y * 128, n0 = blockIdx.x * 128;

    const __half* A = g_q + (size_t)z * Ntok * HD + (size_t)m0 * HD;
    const __half* B = g_k + (size_t)z * Ntok * HD + (size_t)n0 * HD;

    gemm_to_stage<128>(A, HD, B, HD, HD, smem);
    float* stage = (float*)smem;

    float* out = g_attn + (size_t)z * Ntok * Ntok;
    for (int idx = threadIdx.x; idx < 128 * 128; idx += 256) {
        int mr = idx >> 7, nc = idx & 127;
        out[(size_t)(m0 + mr) * Ntok + n0 + nc] = stage[mr * 129 + nc] * SCALE;
    }
}

// ======================= attn_save ==========================================
__global__ void attnsave_kernel(float* __restrict__ out_as)
{
    size_t idx = (size_t)blockIdx.x * 256 + threadIdx.x;
    int k4 = (int)(idx & 255);
    size_t bq = idx >> 8;
    int b = (int)(bq >> 10);
    float4 s = make_float4(0.f, 0.f, 0.f, 0.f);
    int q = (int)(bq & 1023);
    #pragma unroll
    for (int h = 0; h < Hh; h++) {
        const float4* p = (const float4*)(g_attn + ((size_t)(b * Hh + h) * Ntok + q) * Ntok);
        float4 v = p[k4];
        s.x += v.x; s.y += v.y; s.z += v.z; s.w += v.w;
    }
    const float inv = 1.f / Hh;
    s.x *= inv; s.y *= inv; s.z *= inv; s.w *= inv;
    ((float4*)out_as)[bq * 256 + k4] = s;
}

// ======================= fused softmax + PV (BM=64) =========================
__global__ void __launch_bounds__(256, 2) pv_fused()
{
    extern __shared__ char smem[];
    constexpr int SR = 136;
    constexpr uint32_t A_0 = 0;
    constexpr uint32_t B_0 = 64u * SR * 2u;        // 17408
    constexpr uint32_t RS0 = 2u * 64u * SR * 2u;   // 34816

    __half* A_s = (__half*)(smem + A_0);
    float* rowsum_s = (float*)(smem + RS0);
    const uint32_t sbase = smem_to_u32(smem);

    const int z = blockIdx.z;
    const int m0 = blockIdx.y * 64;
    const int b = z / Hh, h = z % Hh;
    const int tid = threadIdx.x, lane = tid & 31, wid = tid >> 5;
    const int wm = wid & 1, wn = wid >> 1;

    const float* Srow = g_attn + (size_t)z * Ntok * Ntok + (size_t)m0 * Ntok;
    const __half* V = g_vt + (size_t)z * HD * Ntok;
    const float* aff = g_aff + b * Ntok;

    float acc[2][2][4];
    #pragma unroll
    for (int i = 0; i < 2; i++)
        #pragma unroll
        for (int j = 0; j < 2; j++)
            #pragma unroll
            for (int l = 0; l < 4; l++) acc[i][j][l] = 0.f;
    float rowAcc = 0.f;
    const int frow = tid >> 2;
    const int fcol = (tid & 3) * 32;

    for (int ch = 0; ch < 8; ch++) {
        const int k0 = ch * 128;
        // B tile (V^T 64x128) via cp.async, overlapping the exp A-fill
        #pragma unroll
        for (int j = 0; j < 4; j++) {
            int i = tid + j * 256;
            int r = i >> 4, c = (i & 15) * 8;
            CP16(sbase + B_0 + (uint32_t)(r * SR + c) * 2, V + (size_t)r * Ntok + k0 + c);
        }
        CP_COMMIT();
        // A operand: exp(S)*aff -> fp16
        const float4* s4 = (const float4*)(Srow + (size_t)frow * Ntok + k0 + fcol);
        const float4* a4 = (const float4*)(aff + k0 + fcol);
        float rs = 0.f;
        #pragma unroll
        for (int j = 0; j < 8; j++) {
            float4 s = s4[j];
            float4 a = a4[j];
            float e0 = __expf(s.x), e1 = __expf(s.y), e2 = __expf(s.z), e3 = __expf(s.w);
            rs += (e0 + e1) + (e2 + e3);
            int off = frow * SR + fcol + j * 4;
            *(__half2*)(A_s + off)     = __floats2half2_rn(e0 * a.x, e1 * a.y);
            *(__half2*)(A_s + off + 2) = __floats2half2_rn(e2 * a.z, e3 * a.w);
        }
        rs += __shfl_xor_sync(0xffffffffu, rs, 1);
        rs += __shfl_xor_sync(0xffffffffu, rs, 2);
        rowAcc += rs;
        CP_WAIT(0);
        __syncthreads();
        #pragma unroll
        for (int ks = 0; ks < 128; ks += 16) {
            uint32_t af[2][4];
            const int arow = (lane & 7) + ((lane >> 3) & 1) * 8;
            const int acol = ks + (lane >> 4) * 8;
            #pragma unroll
            for (int mt = 0; mt < 2; mt++) {
                uint32_t off = (uint32_t)((wm * 32 + mt * 16 + arow) * SR + acol) * 2;
                LDSM4(af[mt], sbase + A_0 + off);
            }
            uint32_t bf[2][2];
            const int g = lane >> 3;
            const int brow = (g >> 1) * 8 + (lane & 7);
            const int bcol = ks + (g & 1) * 8;
            {
                uint32_t off = (uint32_t)((wn * 16 + brow) * SR + bcol) * 2;
                uint32_t t[4];
                LDSM4(t, sbase + B_0 + off);
                bf[0][0] = t[0]; bf[0][1] = t[1]; bf[1][0] = t[2]; bf[1][1] = t[3];
            }
            #pragma unroll
            for (int mt = 0; mt < 2; mt++)
                #pragma unroll
                for (int nt = 0; nt < 2; nt++)
                    MMA_F16(acc[mt][nt], af[mt], bf[nt]);
        }
        __syncthreads();
    }
    if ((tid & 3) == 0) rowsum_s[frow] = rowAcc;
    __syncthreads();

    const int gidr = lane >> 2, qid = lane & 3;
    #pragma unroll
    for (int mt = 0; mt < 2; mt++) {
        int row = wm * 32 + mt * 16 + gidr;
        float inv0 = 1.f / rowsum_s[row];
        float inv8 = 1.f / rowsum_s[row + 8];
        #pragma unroll
        for (int nt = 0; nt < 2; nt++) {
            int col = wn * 16 + nt * 8 + qid * 2;
            size_t o0 = ((size_t)b * Ntok + m0 + row) * Cdim + h * HD + col;
            size_t o8 = o0 + 8u * Cdim;
            *(__half2*)(g_o + o0) = __floats2half2_rn(acc[mt][nt][0] * inv0, acc[mt][nt][1] * inv0);
            *(__half2*)(g_o + o8) = __floats2half2_rn(acc[mt][nt][2] * inv8, acc[mt][nt][3] * inv8);
        }
    }
}

// ======================= output projection ==================================
__global__ void __launch_bounds__(256, 2) proj_mma(const float* __restrict__ bp,
                                                   float* __restrict__ out)
{
    extern __shared__ char smem[];
    const int m0 = blockIdx.y * 128, n0 = blockIdx.x * 128;

    const __half* A = g_o + (size_t)m0 * 768;
    const __half* B = g_w + (size_t)3 * 768 * 768 + (size_t)n0 * 768;

    gemm_to_stage<128>(A, 768, B, 768, 768, smem);
    float* stage = (float*)smem;

    for (int idx = threadIdx.x; idx < 128 * 128; idx += 256) {
        int mr = idx >> 7, nc = idx & 127;
        int n = n0 + nc;
        out[(size_t)(m0 + mr) * Cdim + n] = stage[mr * 129 + nc] + bp[n];
    }
}

// ============================================================================
extern "C" void kernel_launch(void* const* d_in, const int* in_sizes, int n_in,
                              void* d_out, int out_size)
{
    (void)in_sizes; (void)n_in; (void)out_size;
    const float* xq = (const float*)d_in[0];
    const float* xk = (const float*)d_in[1];
    const float* xv = (const float*)d_in[2];
    const float* et = (const float*)d_in[3];
    const float* Wq = (const float*)d_in[4];
    const float* Wk = (const float*)d_in[5];
    const float* Wv = (const float*)d_in[6];
    const float* Wp = (const float*)d_in[7];
    const float* bp = (const float*)d_in[8];

    float* out     = (float*)d_out;
    float* out_x   = out;
    float* out_as  = out + (size_t)Bsz * Ntok * Cdim;
    float* out_aff = out_as + (size_t)Bsz * Ntok * Ntok;

    const int SMEM_BIG = 66048;   // stage 128x129 fp32 dominates (bufs: 40960)
    const int SMEM_PVF = 35072;
    cudaFuncSetAttribute(qkv_mma,    cudaFuncAttributeMaxDynamicSharedMemorySize, SMEM_BIG);
    cudaFuncSetAttribute(scores_mma, cudaFuncAttributeMaxDynamicSharedMemorySize, SMEM_BIG);
    cudaFuncSetAttribute(pv_fused,   cudaFuncAttributeMaxDynamicSharedMemorySize, SMEM_PVF);
    cudaFuncSetAttribute(proj_mma,   cudaFuncAttributeMaxDynamicSharedMemorySize, SMEM_BIG);

    const int NX4 = 8192 * 768 / 4, NW4 = 768 * 768 / 4;
    cvtX_kernel<<<dim3((NX4 + 255) / 256, 1, 3), 256>>>((const float4*)xq, (const float4*)xk,
                                                        (const float4*)xv, NX4);
    cvtW_kernel<<<dim3((NW4 + 255) / 256, 1, 4), 256>>>((const float4*)Wq, (const float4*)Wk,
                                                        (const float4*)Wv, (const float4*)Wp, NW4);

    qkv_mma<<<dim3(6, 64, 3), 256, SMEM_BIG>>>();
    aff_kernel<<<(Bsz * Ntok) / 8, 256>>>(et, out_aff);
    scores_mma<<<dim3(8, 8, BH), 256, SMEM_BIG>>>();
    attnsave_kernel<<<(Bsz * Ntok * Ntok / 4) / 256, 256>>>(out_as);
    pv_fused<<<dim3(1, 16, BH), 256, SMEM_PVF>>>();
    proj_mma<<<dim3(6, 64, 1), 256, SMEM_BIG>>>(bp, out_x);
}

// round 8
// speedup vs baseline: 6.9708x; 1.2383x over previous
#include <cuda_runtime.h>
#include <cuda_fp16.h>
#include <cstdint>

#define Bsz 8
#define Ntok 1024
#define Cdim 768
#define Hh 12
#define HD 64
#define BH (Bsz*Hh)
#define SCALE 0.125f

// ======================= PTX helpers (sm_80+ baseline) ======================
__device__ __forceinline__ uint32_t smem_to_u32(const void* p) {
    uint32_t a;
    asm("{ .reg .u64 t; cvta.to.shared.u64 t, %1; cvt.u32.u64 %0, t; }" : "=r"(a) : "l"(p));
    return a;
}
#define LDSM4(r, addr) \
    asm volatile("ldmatrix.sync.aligned.m8n8.x4.shared.b16 {%0,%1,%2,%3}, [%4];" \
        : "=r"((r)[0]), "=r"((r)[1]), "=r"((r)[2]), "=r"((r)[3]) : "r"(addr))
#define MMA_F16(d, a, b) \
    asm volatile("mma.sync.aligned.m16n8k16.row.col.f32.f16.f16.f32 " \
        "{%0,%1,%2,%3}, {%4,%5,%6,%7}, {%8,%9}, {%0,%1,%2,%3};" \
        : "+f"((d)[0]), "+f"((d)[1]), "+f"((d)[2]), "+f"((d)[3]) \
        : "r"((a)[0]), "r"((a)[1]), "r"((a)[2]), "r"((a)[3]), "r"((b)[0]), "r"((b)[1]))
#define CP16(dst_u32, src_ptr) \
    asm volatile("cp.async.cg.shared.global [%0], [%1], 16;" :: "r"(dst_u32), "l"(src_ptr))
#define CP_COMMIT() asm volatile("cp.async.commit_group;")
#define CP_WAIT(n)  asm volatile("cp.async.wait_group %0;" :: "n"(n))

// ======================= scratch globals ====================================
__device__ __align__(16) __half g_x[3u * 8192u * 768u];   // xq|xk|xv fp16
__device__ __align__(16) __half g_w[4u * 768u * 768u];    // Wq|Wk|Wv|Wp fp16
__device__ __align__(16) __half g_q[BH * Ntok * HD];      // [b,h,tok,hd]
__device__ __align__(16) __half g_k[BH * Ntok * HD];
__device__ __align__(16) __half g_vt[BH * HD * Ntok];     // [b,h,hd,tok]
__device__ __align__(16) __half g_s16[(size_t)BH * Ntok * Ntok];  // fp16 scaled scores
__device__ __align__(16) __half g_o[8192u * 768u];        // attention out fp16
__device__ __align__(16) float g_aff[Bsz * Ntok];

// ======================= fp32 -> fp16 convert ===============================
__global__ void cvtX_kernel(const float4* __restrict__ s0, const float4* __restrict__ s1,
                            const float4* __restrict__ s2, int n4)
{
    int i = blockIdx.x * 256 + threadIdx.x;
    if (i >= n4) return;
    int z = blockIdx.z;
    const float4* src = (z == 0) ? s0 : (z == 1) ? s1 : s2;
    float4 v = src[i];
    size_t off = ((size_t)z * n4 + i) * 2;
    ((__half2*)g_x)[off]     = __floats2half2_rn(v.x, v.y);
    ((__half2*)g_x)[off + 1] = __floats2half2_rn(v.z, v.w);
}
__global__ void cvtW_kernel(const float4* __restrict__ s0, const float4* __restrict__ s1,
                            const float4* __restrict__ s2, const float4* __restrict__ s3, int n4)
{
    int i = blockIdx.x * 256 + threadIdx.x;
    if (i >= n4) return;
    int z = blockIdx.z;
    const float4* src = (z == 0) ? s0 : (z == 1) ? s1 : (z == 2) ? s2 : s3;
    float4 v = src[i];
    size_t off = ((size_t)z * n4 + i) * 2;
    ((__half2*)g_w)[off]     = __floats2half2_rn(v.x, v.y);
    ((__half2*)g_w)[off + 1] = __floats2half2_rn(v.z, v.w);
}

// ======================= single-term fp16 mma.sync GEMM =====================
// C[128, BN] = A @ B^T. A [128,K] K-major, B [BN,K]. Result in SMEM stage,
// stride BN+1 floats. 256 threads, double-buffered cp.async, K-chunk 32.
template <int BN>
__device__ __forceinline__ void gemm_to_stage(
    const __half* __restrict__ A, int lda,
    const __half* __restrict__ B, int ldb,
    int kTotal, char* smem)
{
    constexpr int SROW = 40;                   // halves per row (32 + 8 pad)
    constexpr int A_0 = 0;
    constexpr int B_0 = 128 * SROW;
    constexpr int BUFH = (128 + BN) * SROW;
    constexpr int WN = BN / 2;
    constexpr int NT = BN / 16;
    constexpr int NTP = NT / 2;
    constexpr int NBJ = BN / 64;

    const uint32_t sbase = smem_to_u32(smem);
    const int tid = threadIdx.x, lane = tid & 31, wid = tid >> 5;
    const int wm = wid & 3, wn = wid >> 2;

    float acc[2][NT][4];
    #pragma unroll
    for (int i = 0; i < 2; i++)
        #pragma unroll
        for (int j = 0; j < NT; j++)
            #pragma unroll
            for (int l = 0; l < 4; l++) acc[i][j][l] = 0.f;

    auto CPA = [&](int buf, int k0) {
        uint32_t p = sbase + (uint32_t)buf * BUFH * 2u;
        #pragma unroll
        for (int j = 0; j < 2; j++) {
            int i = tid + j * 256, r = i >> 2, c = (i & 3) << 3;
            CP16(p + (A_0 + r * SROW + c) * 2, A + (size_t)r * lda + k0 + c);
        }
        #pragma unroll
        for (int j = 0; j < NBJ; j++) {
            int i = tid + j * 256, r = i >> 2, c = (i & 3) << 3;
            CP16(p + (B_0 + r * SROW + c) * 2, B + (size_t)r * ldb + k0 + c);
        }
        CP_COMMIT();
    };
    auto COMPUTE = [&](int buf) {
        const uint32_t base = sbase + (uint32_t)buf * BUFH * 2;
        #pragma unroll
        for (int ks = 0; ks < 32; ks += 16) {
            uint32_t af[2][4];
            const int arow = (lane & 7) + ((lane >> 3) & 1) * 8;
            const int acol = ks + (lane >> 4) * 8;
            #pragma unroll
            for (int mt = 0; mt < 2; mt++) {
                uint32_t off = (uint32_t)((wm * 32 + mt * 16 + arow) * SROW + acol) * 2;
                LDSM4(af[mt], base + A_0 * 2 + off);
            }
            uint32_t bf[NT][2];
            const int g = lane >> 3;
            const int brow = (g >> 1) * 8 + (lane & 7);
            const int bcol = ks + (g & 1) * 8;
            #pragma unroll
            for (int np = 0; np < NTP; np++) {
                uint32_t off = (uint32_t)((wn * WN + np * 16 + brow) * SROW + bcol) * 2;
                uint32_t t[4];
                LDSM4(t, base + B_0 * 2 + off);
                bf[2 * np][0] = t[0]; bf[2 * np][1] = t[1];
                bf[2 * np + 1][0] = t[2]; bf[2 * np + 1][1] = t[3];
            }
            #pragma unroll
            for (int mt = 0; mt < 2; mt++)
                #pragma unroll
                for (int nt = 0; nt < NT; nt++)
                    MMA_F16(acc[mt][nt], af[mt], bf[nt]);
        }
    };

    const int nCh = kTotal >> 5;
    CPA(0, 0);
    for (int ch = 0; ch < nCh; ch++) {
        if (ch + 1 < nCh) { CPA((ch + 1) & 1, (ch + 1) << 5); CP_WAIT(1); }
        else              { CP_WAIT(0); }
        __syncthreads();
        COMPUTE(ch & 1);
        __syncthreads();
    }

    float* stage = (float*)smem;
    const int gidr = lane >> 2, qid = lane & 3;
    #pragma unroll
    for (int mt = 0; mt < 2; mt++)
        #pragma unroll
        for (int nt = 0; nt < NT; nt++) {
            int row = wm * 32 + mt * 16 + gidr;
            int col = wn * WN + nt * 8 + qid * 2;
            stage[row * (BN + 1) + col]           = acc[mt][nt][0];
            stage[row * (BN + 1) + col + 1]       = acc[mt][nt][1];
            stage[(row + 8) * (BN + 1) + col]     = acc[mt][nt][2];
            stage[(row + 8) * (BN + 1) + col + 1] = acc[mt][nt][3];
        }
    __syncthreads();
}

// ======================= QKV projection =====================================
__global__ void __launch_bounds__(256, 2) qkv_mma()
{
    extern __shared__ char smem[];
    const int z = blockIdx.z;
    const int m0 = blockIdx.y * 128, n0 = blockIdx.x * 128;

    const __half* A = g_x + (size_t)z * 8192 * 768 + (size_t)m0 * 768;
    const __half* B = g_w + (size_t)z * 768 * 768 + (size_t)n0 * 768;

    gemm_to_stage<128>(A, 768, B, 768, 768, smem);
    float* stage = (float*)smem;

    const int tid = threadIdx.x;
    if (z < 2) {
        __half* dst = (z == 0) ? g_q : g_k;
        for (int idx = tid; idx < 128 * 128; idx += 256) {
            int mr = idx >> 7, nc = idx & 127;
            int m = m0 + mr, n = n0 + nc;
            int b = m >> 10, tok = m & 1023, h = n >> 6, hd = n & 63;
            size_t o = (((size_t)(b * Hh + h)) * Ntok + tok) * HD + hd;
            dst[o] = __float2half(stage[mr * 129 + nc]);
        }
    } else {
        for (int idx = tid; idx < 128 * 128; idx += 256) {
            int mr = idx & 127, nc = idx >> 7;
            int m = m0 + mr, n = n0 + nc;
            int b = m >> 10, tok = m & 1023, h = n >> 6, hd = n & 63;
            size_t o = (((size_t)(b * Hh + h)) * HD + hd) * Ntok + tok;
            g_vt[o] = __float2half(stage[mr * 129 + nc]);
        }
    }
}

// ======================= affinity gate ======================================
__global__ void aff_kernel(const float* __restrict__ et, float* __restrict__ out_aff)
{
    int warp = (blockIdx.x * blockDim.x + threadIdx.x) >> 5;
    int lane = threadIdx.x & 31;
    if (warp >= Bsz * Ntok) return;
    int b = warp >> 10, tok = warp & 1023;
    float s = 0.f;
    for (int c = lane; c < Cdim; c += 32) {
        int h = c >> 6, hd = c & 63;
        size_t o = (((size_t)(b * Hh + h)) * Ntok + tok) * HD + hd;
        s += et[b * Cdim + c] * __half2float(g_k[o]);
    }
    #pragma unroll
    for (int o = 16; o; o >>= 1) s += __shfl_xor_sync(0xffffffffu, s, o);
    if (lane == 0) {
        float v = 1.f / (1.f + __expf(-(SCALE / Hh) * s));
        g_aff[warp] = v;
        out_aff[warp] = v;
    }
}

// ======================= scores (fp16 output, staged) =======================
__global__ void __launch_bounds__(256, 2) scores_mma()
{
    extern __shared__ char smem[];
    const int z = blockIdx.z;
    const int m0 = blockIdx.y * 128, n0 = blockIdx.x * 128;

    const __half* A = g_q + (size_t)z * Ntok * HD + (size_t)m0 * HD;
    const __half* B = g_k + (size_t)z * Ntok * HD + (size_t)n0 * HD;

    gemm_to_stage<128>(A, HD, B, HD, HD, smem);
    float* stage = (float*)smem;

    __half2* out = (__half2*)(g_s16 + (size_t)z * Ntok * Ntok);
    for (int idx = threadIdx.x; idx < 128 * 64; idx += 256) {
        int mr = idx >> 6, nc = idx & 63;
        out[((size_t)(m0 + mr) * Ntok + n0) / 2 + nc] =
            __floats2half2_rn(stage[mr * 129 + nc * 2] * SCALE,
                              stage[mr * 129 + nc * 2 + 1] * SCALE);
    }
}

// ======================= attn_save (fp16 read, fp32 sum) ====================
__global__ void attnsave_kernel(float* __restrict__ out_as)
{
    size_t idx = (size_t)blockIdx.x * 256 + threadIdx.x;
    int k4 = (int)(idx & 255);
    size_t bq = idx >> 8;
    int b = (int)(bq >> 10);
    int q = (int)(bq & 1023);
    float4 s = make_float4(0.f, 0.f, 0.f, 0.f);
    #pragma unroll
    for (int h = 0; h < Hh; h++) {
        const __half2* p = (const __half2*)(g_s16 + ((size_t)(b * Hh + h) * Ntok + q) * Ntok);
        __half2 a = p[k4 * 2], c = p[k4 * 2 + 1];
        float2 fa = __half22float2(a), fc = __half22float2(c);
        s.x += fa.x; s.y += fa.y; s.z += fc.x; s.w += fc.y;
    }
    const float inv = 1.f / Hh;
    s.x *= inv; s.y *= inv; s.z *= inv; s.w *= inv;
    ((float4*)out_as)[bq * 256 + k4] = s;
}

// ======================= fused softmax + PV (BM=64) =========================
__global__ void __launch_bounds__(256, 2) pv_fused()
{
    extern __shared__ char smem[];
    constexpr int SR = 136;
    constexpr uint32_t A_0 = 0;
    constexpr uint32_t B_0 = 64u * SR * 2u;        // 17408
    constexpr uint32_t RS0 = 2u * 64u * SR * 2u;   // 34816

    __half* A_s = (__half*)(smem + A_0);
    float* rowsum_s = (float*)(smem + RS0);
    const uint32_t sbase = smem_to_u32(smem);

    const int z = blockIdx.z;
    const int m0 = blockIdx.y * 64;
    const int b = z / Hh, h = z % Hh;
    const int tid = threadIdx.x, lane = tid & 31, wid = tid >> 5;
    const int wm = wid & 1, wn = wid >> 1;

    const __half* Srow = g_s16 + (size_t)z * Ntok * Ntok + (size_t)m0 * Ntok;
    const __half* V = g_vt + (size_t)z * HD * Ntok;
    const float* aff = g_aff + b * Ntok;

    float acc[2][2][4];
    #pragma unroll
    for (int i = 0; i < 2; i++)
        #pragma unroll
        for (int j = 0; j < 2; j++)
            #pragma unroll
            for (int l = 0; l < 4; l++) acc[i][j][l] = 0.f;
    float rowAcc = 0.f;
    const int frow = tid >> 2;
    const int fcol = (tid & 3) * 32;

    for (int ch = 0; ch < 8; ch++) {
        const int k0 = ch * 128;
        // B tile (V^T 64x128) via cp.async, overlapping the exp A-fill
        #pragma unroll
        for (int j = 0; j < 4; j++) {
            int i = tid + j * 256;
            int r = i >> 4, c = (i & 15) * 8;
            CP16(sbase + B_0 + (uint32_t)(r * SR + c) * 2, V + (size_t)r * Ntok + k0 + c);
        }
        CP_COMMIT();
        // A operand: exp(S16)*aff -> fp16
        const __half2* s2 = (const __half2*)(Srow + (size_t)frow * Ntok + k0 + fcol);
        const float4* a4 = (const float4*)(aff + k0 + fcol);
        float rs = 0.f;
        #pragma unroll
        for (int j = 0; j < 8; j++) {
            float2 f0 = __half22float2(s2[j * 2]);
            float2 f1 = __half22float2(s2[j * 2 + 1]);
            float4 a = a4[j];
            float e0 = __expf(f0.x), e1 = __expf(f0.y), e2 = __expf(f1.x), e3 = __expf(f1.y);
            rs += (e0 + e1) + (e2 + e3);
            int off = frow * SR + fcol + j * 4;
            *(__half2*)(A_s + off)     = __floats2half2_rn(e0 * a.x, e1 * a.y);
            *(__half2*)(A_s + off + 2) = __floats2half2_rn(e2 * a.z, e3 * a.w);
        }
        rs += __shfl_xor_sync(0xffffffffu, rs, 1);
        rs += __shfl_xor_sync(0xffffffffu, rs, 2);
        rowAcc += rs;
        CP_WAIT(0);
        __syncthreads();
        #pragma unroll
        for (int ks = 0; ks < 128; ks += 16) {
            uint32_t af[2][4];
            const int arow = (lane & 7) + ((lane >> 3) & 1) * 8;
            const int acol = ks + (lane >> 4) * 8;
            #pragma unroll
            for (int mt = 0; mt < 2; mt++) {
                uint32_t off = (uint32_t)((wm * 32 + mt * 16 + arow) * SR + acol) * 2;
                LDSM4(af[mt], sbase + A_0 + off);
            }
            uint32_t bf[2][2];
            const int g = lane >> 3;
            const int brow = (g >> 1) * 8 + (lane & 7);
            const int bcol = ks + (g & 1) * 8;
            {
                uint32_t off = (uint32_t)((wn * 16 + brow) * SR + bcol) * 2;
                uint32_t t[4];
                LDSM4(t, sbase + B_0 + off);
                bf[0][0] = t[0]; bf[0][1] = t[1]; bf[1][0] = t[2]; bf[1][1] = t[3];
            }
            #pragma unroll
            for (int mt = 0; mt < 2; mt++)
                #pragma unroll
                for (int nt = 0; nt < 2; nt++)
                    MMA_F16(acc[mt][nt], af[mt], bf[nt]);
        }
        __syncthreads();
    }
    if ((tid & 3) == 0) rowsum_s[frow] = rowAcc;
    __syncthreads();

    const int gidr = lane >> 2, qid = lane & 3;
    #pragma unroll
    for (int mt = 0; mt < 2; mt++) {
        int row = wm * 32 + mt * 16 + gidr;
        float inv0 = 1.f / rowsum_s[row];
        float inv8 = 1.f / rowsum_s[row + 8];
        #pragma unroll
        for (int nt = 0; nt < 2; nt++) {
            int col = wn * 16 + nt * 8 + qid * 2;
            size_t o0 = ((size_t)b * Ntok + m0 + row) * Cdim + h * HD + col;
            size_t o8 = o0 + 8u * Cdim;
            *(__half2*)(g_o + o0) = __floats2half2_rn(acc[mt][nt][0] * inv0, acc[mt][nt][1] * inv0);
            *(__half2*)(g_o + o8) = __floats2half2_rn(acc[mt][nt][2] * inv8, acc[mt][nt][3] * inv8);
        }
    }
}

// ======================= output projection ==================================
__global__ void __launch_bounds__(256, 2) proj_mma(const float* __restrict__ bp,
                                                   float* __restrict__ out)
{
    extern __shared__ char smem[];
    const int m0 = blockIdx.y * 128, n0 = blockIdx.x * 128;

    const __half* A = g_o + (size_t)m0 * 768;
    const __half* B = g_w + (size_t)3 * 768 * 768 + (size_t)n0 * 768;

    gemm_to_stage<128>(A, 768, B, 768, 768, smem);
    float* stage = (float*)smem;

    for (int idx = threadIdx.x; idx < 128 * 128; idx += 256) {
        int mr = idx >> 7, nc = idx & 127;
        int n = n0 + nc;
        out[(size_t)(m0 + mr) * Cdim + n] = stage[mr * 129 + nc] + bp[n];
    }
}

// ============================================================================
extern "C" void kernel_launch(void* const* d_in, const int* in_sizes, int n_in,
                              void* d_out, int out_size)
{
    (void)in_sizes; (void)n_in; (void)out_size;
    const float* xq = (const float*)d_in[0];
    const float* xk = (const float*)d_in[1];
    const float* xv = (const float*)d_in[2];
    const float* et = (const float*)d_in[3];
    const float* Wq = (const float*)d_in[4];
    const float* Wk = (const float*)d_in[5];
    const float* Wv = (const float*)d_in[6];
    const float* Wp = (const float*)d_in[7];
    const float* bp = (const float*)d_in[8];

    float* out     = (float*)d_out;
    float* out_x   = out;
    float* out_as  = out + (size_t)Bsz * Ntok * Cdim;
    float* out_aff = out_as + (size_t)Bsz * Ntok * Ntok;

    const int SMEM_BIG = 66048;   // stage 128x129 fp32 dominates (bufs: 40960)
    const int SMEM_PVF = 35072;
    cudaFuncSetAttribute(qkv_mma,    cudaFuncAttributeMaxDynamicSharedMemorySize, SMEM_BIG);
    cudaFuncSetAttribute(scores_mma, cudaFuncAttributeMaxDynamicSharedMemorySize, SMEM_BIG);
    cudaFuncSetAttribute(pv_fused,   cudaFuncAttributeMaxDynamicSharedMemorySize, SMEM_PVF);
    cudaFuncSetAttribute(proj_mma,   cudaFuncAttributeMaxDynamicSharedMemorySize, SMEM_BIG);

    const int NX4 = 8192 * 768 / 4, NW4 = 768 * 768 / 4;
    cvtX_kernel<<<dim3((NX4 + 255) / 256, 1, 3), 256>>>((const float4*)xq, (const float4*)xk,
                                                        (const float4*)xv, NX4);
    cvtW_kernel<<<dim3((NW4 + 255) / 256, 1, 4), 256>>>((const float4*)Wq, (const float4*)Wk,
                                                        (const float4*)Wv, (const float4*)Wp, NW4);

    qkv_mma<<<dim3(6, 64, 3), 256, SMEM_BIG>>>();
    aff_kernel<<<(Bsz * Ntok) / 8, 256>>>(et, out_aff);
    scores_mma<<<dim3(8, 8, BH), 256, SMEM_BIG>>>();
    attnsave_kernel<<<(Bsz * Ntok * Ntok / 4) / 256, 256>>>(out_as);
    pv_fused<<<dim3(1, 16, BH), 256, SMEM_PVF>>>();
    proj_mma<<<dim3(6, 64, 1), 256, SMEM_BIG>>>(bp, out_x);
}

// round 9
// speedup vs baseline: 8.6888x; 1.2465x over previous
#include <cuda_runtime.h>
#include <cuda_fp16.h>
#include <cstdint>

#define Bsz 8
#define Ntok 1024
#define Cdim 768
#define Hh 12
#define HD 64
#define BH (Bsz*Hh)
#define SCALE 0.125f

// ======================= PTX helpers (sm_80+ baseline) ======================
__device__ __forceinline__ uint32_t smem_to_u32(const void* p) {
    uint32_t a;
    asm("{ .reg .u64 t; cvta.to.shared.u64 t, %1; cvt.u32.u64 %0, t; }" : "=r"(a) : "l"(p));
    return a;
}
#define LDSM4(r, addr) \
    asm volatile("ldmatrix.sync.aligned.m8n8.x4.shared.b16 {%0,%1,%2,%3}, [%4];" \
        : "=r"((r)[0]), "=r"((r)[1]), "=r"((r)[2]), "=r"((r)[3]) : "r"(addr))
#define MMA_F16(d, a, b) \
    asm volatile("mma.sync.aligned.m16n8k16.row.col.f32.f16.f16.f32 " \
        "{%0,%1,%2,%3}, {%4,%5,%6,%7}, {%8,%9}, {%0,%1,%2,%3};" \
        : "+f"((d)[0]), "+f"((d)[1]), "+f"((d)[2]), "+f"((d)[3]) \
        : "r"((a)[0]), "r"((a)[1]), "r"((a)[2]), "r"((a)[3]), "r"((b)[0]), "r"((b)[1]))
#define CP16(dst_u32, src_ptr) \
    asm volatile("cp.async.cg.shared.global [%0], [%1], 16;" :: "r"(dst_u32), "l"(src_ptr))
#define CP_COMMIT() asm volatile("cp.async.commit_group;")
#define CP_WAIT(n)  asm volatile("cp.async.wait_group %0;" :: "n"(n))

// ======================= scratch globals ====================================
__device__ __align__(16) __half g_x[3u * 8192u * 768u];   // xq|xk|xv fp16
__device__ __align__(16) __half g_w[4u * 768u * 768u];    // Wq|Wk|Wv|Wp fp16
__device__ __align__(16) __half g_q[8192u * 768u];        // flat [b*N+tok, c]
__device__ __align__(16) __half g_k[8192u * 768u];        // flat [b*N+tok, c]
__device__ __align__(16) __half g_vt[BH * HD * Ntok];     // [b,h,hd,tok]
__device__ __align__(16) __half g_o[8192u * 768u];        // attention out fp16
__device__ __align__(16) float g_aff[Bsz * Ntok];

// ======================= fp32 -> fp16 convert ===============================
__global__ void cvtX_kernel(const float4* __restrict__ s0, const float4* __restrict__ s1,
                            const float4* __restrict__ s2, int n4)
{
    int i = blockIdx.x * 256 + threadIdx.x;
    if (i >= n4) return;
    int z = blockIdx.z;
    const float4* src = (z == 0) ? s0 : (z == 1) ? s1 : s2;
    float4 v = src[i];
    size_t off = ((size_t)z * n4 + i) * 2;
    ((__half2*)g_x)[off]     = __floats2half2_rn(v.x, v.y);
    ((__half2*)g_x)[off + 1] = __floats2half2_rn(v.z, v.w);
}
__global__ void cvtW_kernel(const float4* __restrict__ s0, const float4* __restrict__ s1,
                            const float4* __restrict__ s2, const float4* __restrict__ s3, int n4)
{
    int i = blockIdx.x * 256 + threadIdx.x;
    if (i >= n4) return;
    int z = blockIdx.z;
    const float4* src = (z == 0) ? s0 : (z == 1) ? s1 : (z == 2) ? s2 : s3;
    float4 v = src[i];
    size_t off = ((size_t)z * n4 + i) * 2;
    ((__half2*)g_w)[off]     = __floats2half2_rn(v.x, v.y);
    ((__half2*)g_w)[off + 1] = __floats2half2_rn(v.z, v.w);
}

// ======================= single-term fp16 mma.sync GEMM =====================
// C[128, BN] = A @ B^T. Result in SMEM stage, stride BN+1 floats. 256 threads.
template <int BN>
__device__ __forceinline__ void gemm_to_stage(
    const __half* __restrict__ A, int lda,
    const __half* __restrict__ B, int ldb,
    int kTotal, char* smem)
{
    constexpr int SROW = 40;
    constexpr int A_0 = 0;
    constexpr int B_0 = 128 * SROW;
    constexpr int BUFH = (128 + BN) * SROW;
    constexpr int WN = BN / 2;
    constexpr int NT = BN / 16;
    constexpr int NTP = NT / 2;
    constexpr int NBJ = BN / 64;

    const uint32_t sbase = smem_to_u32(smem);
    const int tid = threadIdx.x, lane = tid & 31, wid = tid >> 5;
    const int wm = wid & 3, wn = wid >> 2;

    float acc[2][NT][4];
    #pragma unroll
    for (int i = 0; i < 2; i++)
        #pragma unroll
        for (int j = 0; j < NT; j++)
            #pragma unroll
            for (int l = 0; l < 4; l++) acc[i][j][l] = 0.f;

    auto CPA = [&](int buf, int k0) {
        uint32_t p = sbase + (uint32_t)buf * BUFH * 2u;
        #pragma unroll
        for (int j = 0; j < 2; j++) {
            int i = tid + j * 256, r = i >> 2, c = (i & 3) << 3;
            CP16(p + (A_0 + r * SROW + c) * 2, A + (size_t)r * lda + k0 + c);
        }
        #pragma unroll
        for (int j = 0; j < NBJ; j++) {
            int i = tid + j * 256, r = i >> 2, c = (i & 3) << 3;
            CP16(p + (B_0 + r * SROW + c) * 2, B + (size_t)r * ldb + k0 + c);
        }
        CP_COMMIT();
    };
    auto COMPUTE = [&](int buf) {
        const uint32_t base = sbase + (uint32_t)buf * BUFH * 2;
        #pragma unroll
        for (int ks = 0; ks < 32; ks += 16) {
            uint32_t af[2][4];
            const int arow = (lane & 7) + ((lane >> 3) & 1) * 8;
            const int acol = ks + (lane >> 4) * 8;
            #pragma unroll
            for (int mt = 0; mt < 2; mt++) {
                uint32_t off = (uint32_t)((wm * 32 + mt * 16 + arow) * SROW + acol) * 2;
                LDSM4(af[mt], base + A_0 * 2 + off);
            }
            uint32_t bf[NT][2];
            const int g = lane >> 3;
            const int brow = (g >> 1) * 8 + (lane & 7);
            const int bcol = ks + (g & 1) * 8;
            #pragma unroll
            for (int np = 0; np < NTP; np++) {
                uint32_t off = (uint32_t)((wn * WN + np * 16 + brow) * SROW + bcol) * 2;
                uint32_t t[4];
                LDSM4(t, base + B_0 * 2 + off);
                bf[2 * np][0] = t[0]; bf[2 * np][1] = t[1];
                bf[2 * np + 1][0] = t[2]; bf[2 * np + 1][1] = t[3];
            }
            #pragma unroll
            for (int mt = 0; mt < 2; mt++)
                #pragma unroll
                for (int nt = 0; nt < NT; nt++)
                    MMA_F16(acc[mt][nt], af[mt], bf[nt]);
        }
    };

    const int nCh = kTotal >> 5;
    CPA(0, 0);
    for (int ch = 0; ch < nCh; ch++) {
        if (ch + 1 < nCh) { CPA((ch + 1) & 1, (ch + 1) << 5); CP_WAIT(1); }
        else              { CP_WAIT(0); }
        __syncthreads();
        COMPUTE(ch & 1);
        __syncthreads();
    }

    float* stage = (float*)smem;
    const int gidr = lane >> 2, qid = lane & 3;
    #pragma unroll
    for (int mt = 0; mt < 2; mt++)
        #pragma unroll
        for (int nt = 0; nt < NT; nt++) {
            int row = wm * 32 + mt * 16 + gidr;
            int col = wn * WN + nt * 8 + qid * 2;
            stage[row * (BN + 1) + col]           = acc[mt][nt][0];
            stage[row * (BN + 1) + col + 1]       = acc[mt][nt][1];
            stage[(row + 8) * (BN + 1) + col]     = acc[mt][nt][2];
            stage[(row + 8) * (BN + 1) + col + 1] = acc[mt][nt][3];
        }
    __syncthreads();
}

// ======================= QKV projection =====================================
__global__ void __launch_bounds__(256, 2) qkv_mma()
{
    extern __shared__ char smem[];
    const int z = blockIdx.z;
    const int m0 = blockIdx.y * 128, n0 = blockIdx.x * 128;

    const __half* A = g_x + (size_t)z * 8192 * 768 + (size_t)m0 * 768;
    const __half* B = g_w + (size_t)z * 768 * 768 + (size_t)n0 * 768;

    gemm_to_stage<128>(A, 768, B, 768, 768, smem);
    float* stage = (float*)smem;

    const int tid = threadIdx.x;
    if (z < 2) {
        // flat [m, 768] fp16 store, coalesced half2
        __half* dst = (z == 0) ? g_q : g_k;
        for (int idx = tid; idx < 128 * 64; idx += 256) {
            int mr = idx >> 6, nc = (idx & 63) * 2;
            *(__half2*)(dst + (size_t)(m0 + mr) * 768 + n0 + nc) =
                __floats2half2_rn(stage[mr * 129 + nc], stage[mr * 129 + nc + 1]);
        }
    } else {
        // v transposed: [b,h,hd,tok]
        for (int idx = tid; idx < 128 * 128; idx += 256) {
            int mr = idx & 127, nc = idx >> 7;
            int m = m0 + mr, n = n0 + nc;
            int b = m >> 10, tok = m & 1023, h = n >> 6, hd = n & 63;
            size_t o = (((size_t)(b * Hh + h)) * HD + hd) * Ntok + tok;
            g_vt[o] = __float2half(stage[mr * 129 + nc]);
        }
    }
}

// ======================= affinity gate ======================================
__global__ void aff_kernel(const float* __restrict__ et, float* __restrict__ out_aff)
{
    int warp = (blockIdx.x * blockDim.x + threadIdx.x) >> 5;
    int lane = threadIdx.x & 31;
    if (warp >= Bsz * Ntok) return;
    int b = warp >> 10;
    float s = 0.f;
    const __half* krow = g_k + (size_t)warp * 768;
    const float* erow = et + b * Cdim;
    for (int c = lane; c < Cdim; c += 32)
        s += erow[c] * __half2float(krow[c]);
    #pragma unroll
    for (int o = 16; o; o >>= 1) s += __shfl_xor_sync(0xffffffffu, s, o);
    if (lane == 0) {
        float v = 1.f / (1.f + __expf(-(SCALE / Hh) * s));
        g_aff[warp] = v;
        out_aff[warp] = v;
    }
}

// ======================= attn_save = (SCALE/H) * Qflat @ Kflat^T ============
__global__ void __launch_bounds__(256, 2) attnsave_mma(float* __restrict__ out_as)
{
    extern __shared__ char smem[];
    const int b = blockIdx.z;
    const int m0 = blockIdx.y * 128, n0 = blockIdx.x * 128;

    const __half* A = g_q + ((size_t)b * 1024 + m0) * 768;
    const __half* B = g_k + ((size_t)b * 1024 + n0) * 768;

    gemm_to_stage<128>(A, 768, B, 768, 768, smem);
    float* stage = (float*)smem;

    const float sc = SCALE / Hh;
    for (int idx = threadIdx.x; idx < 128 * 128; idx += 256) {
        int mr = idx >> 7, nc = idx & 127;
        out_as[((size_t)b * 1024 + m0 + mr) * 1024 + n0 + nc] = stage[mr * 129 + nc] * sc;
    }
}

// ======================= flash attention: S in-CTA, exp, PV =================
// Per CTA: 64 q-rows of one (b,h). 8 warps, 256 threads, 2 CTA/SM.
__global__ void __launch_bounds__(256, 2) flash_fused()
{
    extern __shared__ char smem[];
    constexpr int SRQ = 72;    // halves/row for q,k tiles (64 + 8 pad)
    constexpr int SRP = 136;   // halves/row for P, V^T tiles (128 + 8 pad)
    constexpr uint32_t Q_0 = 0;                      // 64*72*2  = 9216
    constexpr uint32_t K_0 = 9216;                   // 2 bufs * 128*72*2 = 36864
    constexpr uint32_t KBUF = 128u * SRQ * 2u;       // 18432
    constexpr uint32_t V_0 = 46080;                  // 64*136*2 = 17408
    constexpr uint32_t P_0 = 63488;                  // 64*136*2 = 17408
    constexpr uint32_t RS0 = 80896;                  // 64 floats

    const uint32_t sbase = smem_to_u32(smem);
    __half* P_s = (__half*)(smem + P_0);
    float* rowsum_s = (float*)(smem + RS0);

    const int z = blockIdx.y;               // b*12+h
    const int m0 = blockIdx.x * 64;
    const int b = z / Hh, h = z % Hh;
    const int tid = threadIdx.x, lane = tid & 31, wid = tid >> 5;
    const int gidr = lane >> 2, qid = lane & 3;
    const int wmS = wid & 1, wnS = wid >> 1;   // S: M 2x32, N 4x32
    const int wm2 = wid & 1, wn2 = wid >> 1;   // PV: M 2x32, N 4x16

    const __half* Qg = g_q + ((size_t)b * 1024 + m0) * 768 + h * 64;
    const __half* Kg = g_k + (size_t)b * 1024 * 768 + h * 64;
    const __half* Vg = g_vt + (size_t)z * HD * Ntok;
    const float* aff = g_aff + b * 1024;

    // q tile: 64 rows x 64 halves = 512 CP16 -> 2/thread
    {
        int i = tid, r = i >> 3, c = (i & 7) << 3;
        CP16(sbase + Q_0 + (uint32_t)(r * SRQ + c) * 2, Qg + (size_t)r * 768 + c);
        i = tid + 256; r = i >> 3; c = (i & 7) << 3;
        CP16(sbase + Q_0 + (uint32_t)(r * SRQ + c) * 2, Qg + (size_t)r * 768 + c);
    }
    // k chunk 0: 128 rows x 64 halves = 1024 CP16 -> 4/thread
    #pragma unroll
    for (int j = 0; j < 4; j++) {
        int i = tid + j * 256, r = i >> 3, c = (i & 7) << 3;
        CP16(sbase + K_0 + (uint32_t)(r * SRQ + c) * 2, Kg + (size_t)r * 768 + c);
    }
    // V chunk 0: 64 rows x 128 halves = 1024 CP16 -> 4/thread
    #pragma unroll
    for (int j = 0; j < 4; j++) {
        int i = tid + j * 256, r = i >> 4, c = (i & 15) << 3;
        CP16(sbase + V_0 + (uint32_t)(r * SRP + c) * 2, Vg + (size_t)r * 1024 + c);
    }
    CP_COMMIT();
    if (tid < 64) rowsum_s[tid] = 0.f;

    float acc_o[2][2][4];
    #pragma unroll
    for (int i = 0; i < 2; i++)
        #pragma unroll
        for (int j = 0; j < 2; j++)
            #pragma unroll
            for (int l = 0; l < 4; l++) acc_o[i][j][l] = 0.f;

    for (int ch = 0; ch < 8; ch++) {
        const int k0 = ch * 128;
        const int kb = ch & 1;
        CP_WAIT(0);
        __syncthreads();

        // prefetch next k chunk into other buffer
        if (ch + 1 < 8) {
            #pragma unroll
            for (int j = 0; j < 4; j++) {
                int i = tid + j * 256, r = i >> 3, c = (i & 7) << 3;
                CP16(sbase + K_0 + (kb ^ 1) * KBUF + (uint32_t)(r * SRQ + c) * 2,
                     Kg + (size_t)(k0 + 128 + r) * 768 + c);
            }
            CP_COMMIT();
        }

        // ---- S = q @ k^T  (M=64, N=128, K=64), fp32 acc ----
        float acc_s[2][4][4];
        #pragma unroll
        for (int i = 0; i < 2; i++)
            #pragma unroll
            for (int j = 0; j < 4; j++)
                #pragma unroll
                for (int l = 0; l < 4; l++) acc_s[i][j][l] = 0.f;

        const uint32_t kbase = sbase + K_0 + kb * KBUF;
        #pragma unroll
        for (int ks = 0; ks < 64; ks += 16) {
            uint32_t af[2][4];
            const int arow = (lane & 7) + ((lane >> 3) & 1) * 8;
            const int acol = ks + (lane >> 4) * 8;
            #pragma unroll
            for (int mt = 0; mt < 2; mt++) {
                uint32_t off = (uint32_t)((wmS * 32 + mt * 16 + arow) * SRQ + acol) * 2;
                LDSM4(af[mt], sbase + Q_0 + off);
            }
            uint32_t bf[4][2];
            const int g = lane >> 3;
            const int brow = (g >> 1) * 8 + (lane & 7);
            const int bcol = ks + (g & 1) * 8;
            #pragma unroll
            for (int np = 0; np < 2; np++) {
                uint32_t off = (uint32_t)((wnS * 32 + np * 16 + brow) * SRQ + bcol) * 2;
                uint32_t t[4];
                LDSM4(t, kbase + off);
                bf[2 * np][0] = t[0]; bf[2 * np][1] = t[1];
                bf[2 * np + 1][0] = t[2]; bf[2 * np + 1][1] = t[3];
            }
            #pragma unroll
            for (int mt = 0; mt < 2; mt++)
                #pragma unroll
                for (int nt = 0; nt < 4; nt++)
                    MMA_F16(acc_s[mt][nt], af[mt], bf[nt]);
        }

        // ---- exp(S*SCALE), gate, rowsum, store P ----
        float2 af2[4];
        #pragma unroll
        for (int nt = 0; nt < 4; nt++)
            af2[nt] = *(const float2*)(aff + k0 + wnS * 32 + nt * 8 + qid * 2);
        #pragma unroll
        for (int mt = 0; mt < 2; mt++) {
            int row0 = wmS * 32 + mt * 16 + gidr;
            float rs0 = 0.f, rs1 = 0.f;
            #pragma unroll
            for (int nt = 0; nt < 4; nt++) {
                float e0 = __expf(acc_s[mt][nt][0] * SCALE);
                float e1 = __expf(acc_s[mt][nt][1] * SCALE);
                float e2 = __expf(acc_s[mt][nt][2] * SCALE);
                float e3 = __expf(acc_s[mt][nt][3] * SCALE);
                rs0 += e0 + e1; rs1 += e2 + e3;
                int col = wnS * 32 + nt * 8 + qid * 2;
                *(__half2*)(P_s + row0 * SRP + col)       = __floats2half2_rn(e0 * af2[nt].x, e1 * af2[nt].y);
                *(__half2*)(P_s + (row0 + 8) * SRP + col) = __floats2half2_rn(e2 * af2[nt].x, e3 * af2[nt].y);
            }
            rs0 += __shfl_xor_sync(0xffffffffu, rs0, 1);
            rs0 += __shfl_xor_sync(0xffffffffu, rs0, 2);
            rs1 += __shfl_xor_sync(0xffffffffu, rs1, 1);
            rs1 += __shfl_xor_sync(0xffffffffu, rs1, 2);
            if (qid == 0) {
                atomicAdd(&rowsum_s[row0], rs0);
                atomicAdd(&rowsum_s[row0 + 8], rs1);
            }
        }
        __syncthreads();   // P complete, V still valid

        // ---- O += P @ V^T  (M=64, N=64, K=128) ----
        #pragma unroll
        for (int ks = 0; ks < 128; ks += 16) {
            uint32_t af[2][4];
            const int arow = (lane & 7) + ((lane >> 3) & 1) * 8;
            const int acol = ks + (lane >> 4) * 8;
            #pragma unroll
            for (int mt = 0; mt < 2; mt++) {
                uint32_t off = (uint32_t)((wm2 * 32 + mt * 16 + arow) * SRP + acol) * 2;
                LDSM4(af[mt], sbase + P_0 + off);
            }
            uint32_t bf[2][2];
            const int g = lane >> 3;
            const int brow = (g >> 1) * 8 + (lane & 7);
            const int bcol = ks + (g & 1) * 8;
            {
                uint32_t off = (uint32_t)((wn2 * 16 + brow) * SRP + bcol) * 2;
                uint32_t t[4];
                LDSM4(t, sbase + V_0 + off);
                bf[0][0] = t[0]; bf[0][1] = t[1]; bf[1][0] = t[2]; bf[1][1] = t[3];
            }
            #pragma unroll
            for (int mt = 0; mt < 2; mt++)
                #pragma unroll
                for (int nt = 0; nt < 2; nt++)
                    MMA_F16(acc_o[mt][nt], af[mt], bf[nt]);
        }
        __syncthreads();   // V, P consumed

        // V for next chunk (single buffer, now safe to overwrite)
        if (ch + 1 < 8) {
            #pragma unroll
            for (int j = 0; j < 4; j++) {
                int i = tid + j * 256, r = i >> 4, c = (i & 15) << 3;
                CP16(sbase + V_0 + (uint32_t)(r * SRP + c) * 2, Vg + (size_t)r * 1024 + k0 + 128 + c);
            }
            CP_COMMIT();
        }
    }

    // ---- epilogue: normalize, store fp16 to flat [m, 768] ----
    #pragma unroll
    for (int mt = 0; mt < 2; mt++) {
        int row = wm2 * 32 + mt * 16 + gidr;
        float inv0 = 1.f / rowsum_s[row];
        float inv8 = 1.f / rowsum_s[row + 8];
        #pragma unroll
        for (int nt = 0; nt < 2; nt++) {
            int col = wn2 * 16 + nt * 8 + qid * 2;
            size_t o0 = ((size_t)b * 1024 + m0 + row) * 768 + h * 64 + col;
            size_t o8 = o0 + 8u * 768u;
            *(__half2*)(g_o + o0) = __floats2half2_rn(acc_o[mt][nt][0] * inv0, acc_o[mt][nt][1] * inv0);
            *(__half2*)(g_o + o8) = __floats2half2_rn(acc_o[mt][nt][2] * inv8, acc_o[mt][nt][3] * inv8);
        }
    }
}

// ======================= output projection ==================================
__global__ void __launch_bounds__(256, 2) proj_mma(const float* __restrict__ bp,
                                                   float* __restrict__ out)
{
    extern __shared__ char smem[];
    const int m0 = blockIdx.y * 128, n0 = blockIdx.x * 128;

    const __half* A = g_o + (size_t)m0 * 768;
    const __half* B = g_w + (size_t)3 * 768 * 768 + (size_t)n0 * 768;

    gemm_to_stage<128>(A, 768, B, 768, 768, smem);
    float* stage = (float*)smem;

    for (int idx = threadIdx.x; idx < 128 * 128; idx += 256) {
        int mr = idx >> 7, nc = idx & 127;
        int n = n0 + nc;
        out[(size_t)(m0 + mr) * Cdim + n] = stage[mr * 129 + nc] + bp[n];
    }
}

// ============================================================================
extern "C" void kernel_launch(void* const* d_in, const int* in_sizes, int n_in,
                              void* d_out, int out_size)
{
    (void)in_sizes; (void)n_in; (void)out_size;
    const float* xq = (const float*)d_in[0];
    const float* xk = (const float*)d_in[1];
    const float* xv = (const float*)d_in[2];
    const float* et = (const float*)d_in[3];
    const float* Wq = (const float*)d_in[4];
    const float* Wk = (const float*)d_in[5];
    const float* Wv = (const float*)d_in[6];
    const float* Wp = (const float*)d_in[7];
    const float* bp = (const float*)d_in[8];

    float* out     = (float*)d_out;
    float* out_x   = out;
    float* out_as  = out + (size_t)Bsz * Ntok * Cdim;
    float* out_aff = out_as + (size_t)Bsz * Ntok * Ntok;

    const int SMEM_BIG = 66048;
    const int SMEM_FLASH = 81152;
    cudaFuncSetAttribute(qkv_mma,      cudaFuncAttributeMaxDynamicSharedMemorySize, SMEM_BIG);
    cudaFuncSetAttribute(attnsave_mma, cudaFuncAttributeMaxDynamicSharedMemorySize, SMEM_BIG);
    cudaFuncSetAttribute(flash_fused,  cudaFuncAttributeMaxDynamicSharedMemorySize, SMEM_FLASH);
    cudaFuncSetAttribute(proj_mma,     cudaFuncAttributeMaxDynamicSharedMemorySize, SMEM_BIG);

    const int NX4 = 8192 * 768 / 4, NW4 = 768 * 768 / 4;
    cvtX_kernel<<<dim3((NX4 + 255) / 256, 1, 3), 256>>>((const float4*)xq, (const float4*)xk,
                                                        (const float4*)xv, NX4);
    cvtW_kernel<<<dim3((NW4 + 255) / 256, 1, 4), 256>>>((const float4*)Wq, (const float4*)Wk,
                                                        (const float4*)Wv, (const float4*)Wp, NW4);

    qkv_mma<<<dim3(6, 64, 3), 256, SMEM_BIG>>>();
    aff_kernel<<<(Bsz * Ntok) / 8, 256>>>(et, out_aff);
    attnsave_mma<<<dim3(8, 8, Bsz), 256, SMEM_BIG>>>(out_as);
    flash_fused<<<dim3(16, BH), 256, SMEM_FLASH>>>();
    proj_mma<<<dim3(6, 64, 1), 256, SMEM_BIG>>>(bp, out_x);
}

// round 10
// speedup vs baseline: 9.0511x; 1.0417x over previous
#include <cuda_runtime.h>
#include <cuda_fp16.h>
#include <cstdint>

#define Bsz 8
#define Ntok 1024
#define Cdim 768
#define Hh 12
#define HD 64
#define BH (Bsz*Hh)
#define SCALE 0.125f

// ======================= PTX helpers (sm_80+ baseline) ======================
__device__ __forceinline__ uint32_t smem_to_u32(const void* p) {
    uint32_t a;
    asm("{ .reg .u64 t; cvta.to.shared.u64 t, %1; cvt.u32.u64 %0, t; }" : "=r"(a) : "l"(p));
    return a;
}
#define LDSM4(r, addr) \
    asm volatile("ldmatrix.sync.aligned.m8n8.x4.shared.b16 {%0,%1,%2,%3}, [%4];" \
        : "=r"((r)[0]), "=r"((r)[1]), "=r"((r)[2]), "=r"((r)[3]) : "r"(addr))
#define MMA_F16(d, a, b) \
    asm volatile("mma.sync.aligned.m16n8k16.row.col.f32.f16.f16.f32 " \
        "{%0,%1,%2,%3}, {%4,%5,%6,%7}, {%8,%9}, {%0,%1,%2,%3};" \
        : "+f"((d)[0]), "+f"((d)[1]), "+f"((d)[2]), "+f"((d)[3]) \
        : "r"((a)[0]), "r"((a)[1]), "r"((a)[2]), "r"((a)[3]), "r"((b)[0]), "r"((b)[1]))
#define CP16(dst_u32, src_ptr) \
    asm volatile("cp.async.cg.shared.global [%0], [%1], 16;" :: "r"(dst_u32), "l"(src_ptr))
#define CP_COMMIT() asm volatile("cp.async.commit_group;")
#define CP_WAIT(n)  asm volatile("cp.async.wait_group %0;" :: "n"(n))

// ======================= scratch globals ====================================
__device__ __align__(16) __half g_x[3u * 8192u * 768u];   // xq|xk|xv fp16
__device__ __align__(16) __half g_w[4u * 768u * 768u];    // Wq|Wk|Wv|Wp fp16
__device__ __align__(16) __half g_q[8192u * 768u];        // flat [b*N+tok, c]
__device__ __align__(16) __half g_k[8192u * 768u];        // flat [b*N+tok, c]
__device__ __align__(16) __half g_vt[BH * HD * Ntok];     // [b,h,hd,tok]
__device__ __align__(16) __half g_o[8192u * 768u];        // attention out fp16
__device__ __align__(16) float g_aff[Bsz * Ntok];

// ======================= fp32 -> fp16 convert ===============================
__global__ void cvtX_kernel(const float4* __restrict__ s0, const float4* __restrict__ s1,
                            const float4* __restrict__ s2, int n4)
{
    int i = blockIdx.x * 256 + threadIdx.x;
    if (i >= n4) return;
    int z = blockIdx.z;
    const float4* src = (z == 0) ? s0 : (z == 1) ? s1 : s2;
    float4 v = src[i];
    size_t off = ((size_t)z * n4 + i) * 2;
    ((__half2*)g_x)[off]     = __floats2half2_rn(v.x, v.y);
    ((__half2*)g_x)[off + 1] = __floats2half2_rn(v.z, v.w);
}
__global__ void cvtW_kernel(const float4* __restrict__ s0, const float4* __restrict__ s1,
                            const float4* __restrict__ s2, const float4* __restrict__ s3, int n4)
{
    int i = blockIdx.x * 256 + threadIdx.x;
    if (i >= n4) return;
    int z = blockIdx.z;
    const float4* src = (z == 0) ? s0 : (z == 1) ? s1 : (z == 2) ? s2 : s3;
    float4 v = src[i];
    size_t off = ((size_t)z * n4 + i) * 2;
    ((__half2*)g_w)[off]     = __floats2half2_rn(v.x, v.y);
    ((__half2*)g_w)[off + 1] = __floats2half2_rn(v.z, v.w);
}

// ======================= single-term fp16 mma.sync GEMM =====================
// C[128, BN] = A @ B^T. Result in SMEM stage, stride BN+1 floats. 256 threads.
template <int BN>
__device__ __forceinline__ void gemm_to_stage(
    const __half* __restrict__ A, int lda,
    const __half* __restrict__ B, int ldb,
    int kTotal, char* smem)
{
    constexpr int SROW = 40;
    constexpr int A_0 = 0;
    constexpr int B_0 = 128 * SROW;
    constexpr int BUFH = (128 + BN) * SROW;
    constexpr int WN = BN / 2;
    constexpr int NT = BN / 16;
    constexpr int NTP = NT / 2;
    constexpr int NBJ = BN / 64;

    const uint32_t sbase = smem_to_u32(smem);
    const int tid = threadIdx.x, lane = tid & 31, wid = tid >> 5;
    const int wm = wid & 3, wn = wid >> 2;

    float acc[2][NT][4];
    #pragma unroll
    for (int i = 0; i < 2; i++)
        #pragma unroll
        for (int j = 0; j < NT; j++)
            #pragma unroll
            for (int l = 0; l < 4; l++) acc[i][j][l] = 0.f;

    auto CPA = [&](int buf, int k0) {
        uint32_t p = sbase + (uint32_t)buf * BUFH * 2u;
        #pragma unroll
        for (int j = 0; j < 2; j++) {
            int i = tid + j * 256, r = i >> 2, c = (i & 3) << 3;
            CP16(p + (A_0 + r * SROW + c) * 2, A + (size_t)r * lda + k0 + c);
        }
        #pragma unroll
        for (int j = 0; j < NBJ; j++) {
            int i = tid + j * 256, r = i >> 2, c = (i & 3) << 3;
            CP16(p + (B_0 + r * SROW + c) * 2, B + (size_t)r * ldb + k0 + c);
        }
        CP_COMMIT();
    };
    auto COMPUTE = [&](int buf) {
        const uint32_t base = sbase + (uint32_t)buf * BUFH * 2;
        #pragma unroll
        for (int ks = 0; ks < 32; ks += 16) {
            uint32_t af[2][4];
            const int arow = (lane & 7) + ((lane >> 3) & 1) * 8;
            const int acol = ks + (lane >> 4) * 8;
            #pragma unroll
            for (int mt = 0; mt < 2; mt++) {
                uint32_t off = (uint32_t)((wm * 32 + mt * 16 + arow) * SROW + acol) * 2;
                LDSM4(af[mt], base + A_0 * 2 + off);
            }
            uint32_t bf[NT][2];
            const int g = lane >> 3;
            const int brow = (g >> 1) * 8 + (lane & 7);
            const int bcol = ks + (g & 1) * 8;
            #pragma unroll
            for (int np = 0; np < NTP; np++) {
                uint32_t off = (uint32_t)((wn * WN + np * 16 + brow) * SROW + bcol) * 2;
                uint32_t t[4];
                LDSM4(t, base + B_0 * 2 + off);
                bf[2 * np][0] = t[0]; bf[2 * np][1] = t[1];
                bf[2 * np + 1][0] = t[2]; bf[2 * np + 1][1] = t[3];
            }
            #pragma unroll
            for (int mt = 0; mt < 2; mt++)
                #pragma unroll
                for (int nt = 0; nt < NT; nt++)
                    MMA_F16(acc[mt][nt], af[mt], bf[nt]);
        }
    };

    const int nCh = kTotal >> 5;
    CPA(0, 0);
    for (int ch = 0; ch < nCh; ch++) {
        if (ch + 1 < nCh) { CPA((ch + 1) & 1, (ch + 1) << 5); CP_WAIT(1); }
        else              { CP_WAIT(0); }
        __syncthreads();
        COMPUTE(ch & 1);
        __syncthreads();
    }

    float* stage = (float*)smem;
    const int gidr = lane >> 2, qid = lane & 3;
    #pragma unroll
    for (int mt = 0; mt < 2; mt++)
        #pragma unroll
        for (int nt = 0; nt < NT; nt++) {
            int row = wm * 32 + mt * 16 + gidr;
            int col = wn * WN + nt * 8 + qid * 2;
            stage[row * (BN + 1) + col]           = acc[mt][nt][0];
            stage[row * (BN + 1) + col + 1]       = acc[mt][nt][1];
            stage[(row + 8) * (BN + 1) + col]     = acc[mt][nt][2];
            stage[(row + 8) * (BN + 1) + col + 1] = acc[mt][nt][3];
        }
    __syncthreads();
}

// ======================= QKV projection =====================================
__global__ void __launch_bounds__(256, 2) qkv_mma()
{
    extern __shared__ char smem[];
    const int z = blockIdx.z;
    const int m0 = blockIdx.y * 128, n0 = blockIdx.x * 128;

    const __half* A = g_x + (size_t)z * 8192 * 768 + (size_t)m0 * 768;
    const __half* B = g_w + (size_t)z * 768 * 768 + (size_t)n0 * 768;

    gemm_to_stage<128>(A, 768, B, 768, 768, smem);
    float* stage = (float*)smem;

    const int tid = threadIdx.x;
    if (z < 2) {
        // flat [m, 768] fp16 store, coalesced half2
        __half* dst = (z == 0) ? g_q : g_k;
        for (int idx = tid; idx < 128 * 64; idx += 256) {
            int mr = idx >> 6, nc = (idx & 63) * 2;
            *(__half2*)(dst + (size_t)(m0 + mr) * 768 + n0 + nc) =
                __floats2half2_rn(stage[mr * 129 + nc], stage[mr * 129 + nc + 1]);
        }
    } else {
        // v transposed: [b,h,hd,tok]; pair tok -> coalesced half2 stores
        for (int idx = tid; idx < 128 * 64; idx += 256) {
            int t2 = idx & 63, nc = idx >> 6;       // nc = col (h*64+hd within tile)
            int mr = t2 * 2;                        // tok pair
            int m = m0 + mr, n = n0 + nc;
            int b = m >> 10, tok = m & 1023, h = n >> 6, hd = n & 63;
            size_t o = (((size_t)(b * Hh + h)) * HD + hd) * Ntok + tok;
            *(__half2*)(g_vt + o) =
                __floats2half2_rn(stage[mr * 129 + nc], stage[(mr + 1) * 129 + nc]);
        }
    }
}

// ======================= affinity gate ======================================
__global__ void aff_kernel(const float* __restrict__ et, float* __restrict__ out_aff)
{
    int warp = (blockIdx.x * blockDim.x + threadIdx.x) >> 5;
    int lane = threadIdx.x & 31;
    if (warp >= Bsz * Ntok) return;
    int b = warp >> 10;
    float s = 0.f;
    const __half* krow = g_k + (size_t)warp * 768;
    const float* erow = et + b * Cdim;
    for (int c = lane; c < Cdim; c += 32)
        s += erow[c] * __half2float(krow[c]);
    #pragma unroll
    for (int o = 16; o; o >>= 1) s += __shfl_xor_sync(0xffffffffu, s, o);
    if (lane == 0) {
        float v = 1.f / (1.f + __expf(-(SCALE / Hh) * s));
        g_aff[warp] = v;
        out_aff[warp] = v;
    }
}

// ======================= attn_save = (SCALE/H) * Qflat @ Kflat^T ============
__global__ void __launch_bounds__(256, 2) attnsave_mma(float* __restrict__ out_as)
{
    extern __shared__ char smem[];
    const int b = blockIdx.z;
    const int m0 = blockIdx.y * 128, n0 = blockIdx.x * 128;

    const __half* A = g_q + ((size_t)b * 1024 + m0) * 768;
    const __half* B = g_k + ((size_t)b * 1024 + n0) * 768;

    gemm_to_stage<128>(A, 768, B, 768, 768, smem);
    float* stage = (float*)smem;

    const float sc = SCALE / Hh;
    for (int idx = threadIdx.x; idx < 128 * 128; idx += 256) {
        int mr = idx >> 7, nc = idx & 127;
        out_as[((size_t)b * 1024 + m0 + mr) * 1024 + n0 + nc] = stage[mr * 129 + nc] * sc;
    }
}

// ======================= flash attention: S in-CTA, exp, PV =================
// Per CTA: 64 q-rows of one (b,h). 8 warps, 256 threads, 2 CTA/SM.
__global__ void __launch_bounds__(256, 2) flash_fused()
{
    extern __shared__ char smem[];
    constexpr int SRQ = 72;    // halves/row for q,k tiles (64 + 8 pad)
    constexpr int SRP = 136;   // halves/row for P, V^T tiles (128 + 8 pad)
    constexpr uint32_t Q_0 = 0;                      // 64*72*2  = 9216
    constexpr uint32_t K_0 = 9216;                   // 2 bufs * 128*72*2 = 36864
    constexpr uint32_t KBUF = 128u * SRQ * 2u;       // 18432
    constexpr uint32_t V_0 = 46080;                  // 64*136*2 = 17408
    constexpr uint32_t P_0 = 63488;                  // 64*136*2 = 17408
    constexpr uint32_t RS0 = 80896;                  // 64 floats

    const uint32_t sbase = smem_to_u32(smem);
    __half* P_s = (__half*)(smem + P_0);
    float* rowsum_s = (float*)(smem + RS0);

    const int z = blockIdx.y;               // b*12+h
    const int m0 = blockIdx.x * 64;
    const int b = z / Hh, h = z % Hh;
    const int tid = threadIdx.x, lane = tid & 31, wid = tid >> 5;
    const int gidr = lane >> 2, qid = lane & 3;
    const int wmS = wid & 1, wnS = wid >> 1;   // S: M 2x32, N 4x32
    const int wm2 = wid & 1, wn2 = wid >> 1;   // PV: M 2x32, N 4x16

    const __half* Qg = g_q + ((size_t)b * 1024 + m0) * 768 + h * 64;
    const __half* Kg = g_k + (size_t)b * 1024 * 768 + h * 64;
    const __half* Vg = g_vt + (size_t)z * HD * Ntok;
    const float* aff = g_aff + b * 1024;

    // q tile: 64 rows x 64 halves = 512 CP16 -> 2/thread
    {
        int i = tid, r = i >> 3, c = (i & 7) << 3;
        CP16(sbase + Q_0 + (uint32_t)(r * SRQ + c) * 2, Qg + (size_t)r * 768 + c);
        i = tid + 256; r = i >> 3; c = (i & 7) << 3;
        CP16(sbase + Q_0 + (uint32_t)(r * SRQ + c) * 2, Qg + (size_t)r * 768 + c);
    }
    // k chunk 0: 128 rows x 64 halves = 1024 CP16 -> 4/thread
    #pragma unroll
    for (int j = 0; j < 4; j++) {
        int i = tid + j * 256, r = i >> 3, c = (i & 7) << 3;
        CP16(sbase + K_0 + (uint32_t)(r * SRQ + c) * 2, Kg + (size_t)r * 768 + c);
    }
    // V chunk 0: 64 rows x 128 halves = 1024 CP16 -> 4/thread
    #pragma unroll
    for (int j = 0; j < 4; j++) {
        int i = tid + j * 256, r = i >> 4, c = (i & 15) << 3;
        CP16(sbase + V_0 + (uint32_t)(r * SRP + c) * 2, Vg + (size_t)r * 1024 + c);
    }
    CP_COMMIT();
    if (tid < 64) rowsum_s[tid] = 0.f;

    float acc_o[2][2][4];
    #pragma unroll
    for (int i = 0; i < 2; i++)
        #pragma unroll
        for (int j = 0; j < 2; j++)
            #pragma unroll
            for (int l = 0; l < 4; l++) acc_o[i][j][l] = 0.f;

    for (int ch = 0; ch < 8; ch++) {
        const int k0 = ch * 128;
        const int kb = ch & 1;
        CP_WAIT(0);
        __syncthreads();

        // prefetch next k chunk into other buffer
        if (ch + 1 < 8) {
            #pragma unroll
            for (int j = 0; j < 4; j++) {
                int i = tid + j * 256, r = i >> 3, c = (i & 7) << 3;
                CP16(sbase + K_0 + (kb ^ 1) * KBUF + (uint32_t)(r * SRQ + c) * 2,
                     Kg + (size_t)(k0 + 128 + r) * 768 + c);
            }
            CP_COMMIT();
        }

        // ---- S = q @ k^T  (M=64, N=128, K=64), fp32 acc ----
        float acc_s[2][4][4];
        #pragma unroll
        for (int i = 0; i < 2; i++)
            #pragma unroll
            for (int j = 0; j < 4; j++)
                #pragma unroll
                for (int l = 0; l < 4; l++) acc_s[i][j][l] = 0.f;

        const uint32_t kbase = sbase + K_0 + kb * KBUF;
        #pragma unroll
        for (int ks = 0; ks < 64; ks += 16) {
            uint32_t af[2][4];
            const int arow = (lane & 7) + ((lane >> 3) & 1) * 8;
            const int acol = ks + (lane >> 4) * 8;
            #pragma unroll
            for (int mt = 0; mt < 2; mt++) {
                uint32_t off = (uint32_t)((wmS * 32 + mt * 16 + arow) * SRQ + acol) * 2;
                LDSM4(af[mt], sbase + Q_0 + off);
            }
            uint32_t bf[4][2];
            const int g = lane >> 3;
            const int brow = (g >> 1) * 8 + (lane & 7);
            const int bcol = ks + (g & 1) * 8;
            #pragma unroll
            for (int np = 0; np < 2; np++) {
                uint32_t off = (uint32_t)((wnS * 32 + np * 16 + brow) * SRQ + bcol) * 2;
                uint32_t t[4];
                LDSM4(t, kbase + off);
                bf[2 * np][0] = t[0]; bf[2 * np][1] = t[1];
                bf[2 * np + 1][0] = t[2]; bf[2 * np + 1][1] = t[3];
            }
            #pragma unroll
            for (int mt = 0; mt < 2; mt++)
                #pragma unroll
                for (int nt = 0; nt < 4; nt++)
                    MMA_F16(acc_s[mt][nt], af[mt], bf[nt]);
        }

        // ---- exp(S*SCALE), gate, rowsum, store P ----
        float2 af2[4];
        #pragma unroll
        for (int nt = 0; nt < 4; nt++)
            af2[nt] = *(const float2*)(aff + k0 + wnS * 32 + nt * 8 + qid * 2);
        #pragma unroll
        for (int mt = 0; mt < 2; mt++) {
            int row0 = wmS * 32 + mt * 16 + gidr;
            float rs0 = 0.f, rs1 = 0.f;
            #pragma unroll
            for (int nt = 0; nt < 4; nt++) {
                float e0 = __expf(acc_s[mt][nt][0] * SCALE);
                float e1 = __expf(acc_s[mt][nt][1] * SCALE);
                float e2 = __expf(acc_s[mt][nt][2] * SCALE);
                float e3 = __expf(acc_s[mt][nt][3] * SCALE);
                rs0 += e0 + e1; rs1 += e2 + e3;
                int col = wnS * 32 + nt * 8 + qid * 2;
                *(__half2*)(P_s + row0 * SRP + col)       = __floats2half2_rn(e0 * af2[nt].x, e1 * af2[nt].y);
                *(__half2*)(P_s + (row0 + 8) * SRP + col) = __floats2half2_rn(e2 * af2[nt].x, e3 * af2[nt].y);
            }
            rs0 += __shfl_xor_sync(0xffffffffu, rs0, 1);
            rs0 += __shfl_xor_sync(0xffffffffu, rs0, 2);
            rs1 += __shfl_xor_sync(0xffffffffu, rs1, 1);
            rs1 += __shfl_xor_sync(0xffffffffu, rs1, 2);
            if (qid == 0) {
                atomicAdd(&rowsum_s[row0], rs0);
                atomicAdd(&rowsum_s[row0 + 8], rs1);
            }
        }
        __syncthreads();   // P complete, V still valid

        // ---- O += P @ V^T  (M=64, N=64, K=128) ----
        #pragma unroll
        for (int ks = 0; ks < 128; ks += 16) {
            uint32_t af[2][4];
            const int arow = (lane & 7) + ((lane >> 3) & 1) * 8;
            const int acol = ks + (lane >> 4) * 8;
            #pragma unroll
            for (int mt = 0; mt < 2; mt++) {
                uint32_t off = (uint32_t)((wm2 * 32 + mt * 16 + arow) * SRP + acol) * 2;
                LDSM4(af[mt], sbase + P_0 + off);
            }
            uint32_t bf[2][2];
            const int g = lane >> 3;
            const int brow = (g >> 1) * 8 + (lane & 7);
            const int bcol = ks + (g & 1) * 8;
            {
                uint32_t off = (uint32_t)((wn2 * 16 + brow) * SRP + bcol) * 2;
                uint32_t t[4];
                LDSM4(t, sbase + V_0 + off);
                bf[0][0] = t[0]; bf[0][1] = t[1]; bf[1][0] = t[2]; bf[1][1] = t[3];
            }
            #pragma unroll
            for (int mt = 0; mt < 2; mt++)
                #pragma unroll
                for (int nt = 0; nt < 2; nt++)
                    MMA_F16(acc_o[mt][nt], af[mt], bf[nt]);
        }
        __syncthreads();   // V, P consumed

        // V for next chunk (single buffer, now safe to overwrite)
        if (ch + 1 < 8) {
            #pragma unroll
            for (int j = 0; j < 4; j++) {
                int i = tid + j * 256, r = i >> 4, c = (i & 15) << 3;
                CP16(sbase + V_0 + (uint32_t)(r * SRP + c) * 2, Vg + (size_t)r * 1024 + k0 + 128 + c);
            }
            CP_COMMIT();
        }
    }

    // ---- epilogue: normalize, store fp16 to flat [m, 768] ----
    #pragma unroll
    for (int mt = 0; mt < 2; mt++) {
        int row = wm2 * 32 + mt * 16 + gidr;
        float inv0 = 1.f / rowsum_s[row];
        float inv8 = 1.f / rowsum_s[row + 8];
        #pragma unroll
        for (int nt = 0; nt < 2; nt++) {
            int col = wn2 * 16 + nt * 8 + qid * 2;
            size_t o0 = ((size_t)b * 1024 + m0 + row) * 768 + h * 64 + col;
            size_t o8 = o0 + 8u * 768u;
            *(__half2*)(g_o + o0) = __floats2half2_rn(acc_o[mt][nt][0] * inv0, acc_o[mt][nt][1] * inv0);
            *(__half2*)(g_o + o8) = __floats2half2_rn(acc_o[mt][nt][2] * inv8, acc_o[mt][nt][3] * inv8);
        }
    }
}

// ======================= output projection ==================================
__global__ void __launch_bounds__(256, 2) proj_mma(const float* __restrict__ bp,
                                                   float* __restrict__ out)
{
    extern __shared__ char smem[];
    const int m0 = blockIdx.y * 128, n0 = blockIdx.x * 128;

    const __half* A = g_o + (size_t)m0 * 768;
    const __half* B = g_w + (size_t)3 * 768 * 768 + (size_t)n0 * 768;

    gemm_to_stage<128>(A, 768, B, 768, 768, smem);
    float* stage = (float*)smem;

    for (int idx = threadIdx.x; idx < 128 * 128; idx += 256) {
        int mr = idx >> 7, nc = idx & 127;
        int n = n0 + nc;
        out[(size_t)(m0 + mr) * Cdim + n] = stage[mr * 129 + nc] + bp[n];
    }
}

// ============================================================================
extern "C" void kernel_launch(void* const* d_in, const int* in_sizes, int n_in,
                              void* d_out, int out_size)
{
    (void)in_sizes; (void)n_in; (void)out_size;
    const float* xq = (const float*)d_in[0];
    const float* xk = (const float*)d_in[1];
    const float* xv = (const float*)d_in[2];
    const float* et = (const float*)d_in[3];
    const float* Wq = (const float*)d_in[4];
    const float* Wk = (const float*)d_in[5];
    const float* Wv = (const float*)d_in[6];
    const float* Wp = (const float*)d_in[7];
    const float* bp = (const float*)d_in[8];

    float* out     = (float*)d_out;
    float* out_x   = out;
    float* out_as  = out + (size_t)Bsz * Ntok * Cdim;
    float* out_aff = out_as + (size_t)Bsz * Ntok * Ntok;

    const int SMEM_BIG = 66048;
    const int SMEM_FLASH = 81152;
    cudaFuncSetAttribute(qkv_mma,      cudaFuncAttributeMaxDynamicSharedMemorySize, SMEM_BIG);
    cudaFuncSetAttribute(attnsave_mma, cudaFuncAttributeMaxDynamicSharedMemorySize, SMEM_BIG);
    cudaFuncSetAttribute(flash_fused,  cudaFuncAttributeMaxDynamicSharedMemorySize, SMEM_FLASH);
    cudaFuncSetAttribute(proj_mma,     cudaFuncAttributeMaxDynamicSharedMemorySize, SMEM_BIG);

    // side stream + events (created once; graph topology identical every call)
    static cudaStream_t s1 = nullptr;
    static cudaEvent_t eQ = nullptr, eA = nullptr;
    if (!s1) {
        cudaStreamCreateWithFlags(&s1, cudaStreamNonBlocking);
        cudaEventCreateWithFlags(&eQ, cudaEventDisableTiming);
        cudaEventCreateWithFlags(&eA, cudaEventDisableTiming);
    }

    const int NX4 = 8192 * 768 / 4, NW4 = 768 * 768 / 4;
    cvtX_kernel<<<dim3((NX4 + 255) / 256, 1, 3), 256>>>((const float4*)xq, (const float4*)xk,
                                                        (const float4*)xv, NX4);
    cvtW_kernel<<<dim3((NW4 + 255) / 256, 1, 4), 256>>>((const float4*)Wq, (const float4*)Wk,
                                                        (const float4*)Wv, (const float4*)Wp, NW4);

    qkv_mma<<<dim3(6, 64, 3), 256, SMEM_BIG>>>();

    // fork: attnsave (independent of aff/flash/proj) on side stream
    cudaEventRecord(eQ, 0);
    cudaStreamWaitEvent(s1, eQ, 0);
    attnsave_mma<<<dim3(8, 8, Bsz), 256, SMEM_BIG, s1>>>(out_as);
    cudaEventRecord(eA, s1);

    aff_kernel<<<(Bsz * Ntok) / 8, 256>>>(et, out_aff);
    flash_fused<<<dim3(16, BH), 256, SMEM_FLASH>>>();
    proj_mma<<<dim3(6, 64, 1), 256, SMEM_BIG>>>(bp, out_x);

    // join before returning control to the harness
    cudaStreamWaitEvent(0, eA, 0);
}

// round 11
// speedup vs baseline: 10.0127x; 1.1062x over previous
#include <cuda_runtime.h>
#include <cuda_fp16.h>
#include <cstdint>

#define Bsz 8
#define Ntok 1024
#define Cdim 768
#define Hh 12
#define HD 64
#define BH (Bsz*Hh)
#define SCALE 0.125f

// ======================= PTX helpers (sm_80+ baseline) ======================
__device__ __forceinline__ uint32_t smem_to_u32(const void* p) {
    uint32_t a;
    asm("{ .reg .u64 t; cvta.to.shared.u64 t, %1; cvt.u32.u64 %0, t; }" : "=r"(a) : "l"(p));
    return a;
}
#define LDSM4(r, addr) \
    asm volatile("ldmatrix.sync.aligned.m8n8.x4.shared.b16 {%0,%1,%2,%3}, [%4];" \
        : "=r"((r)[0]), "=r"((r)[1]), "=r"((r)[2]), "=r"((r)[3]) : "r"(addr))
#define MMA_F16(d, a, b) \
    asm volatile("mma.sync.aligned.m16n8k16.row.col.f32.f16.f16.f32 " \
        "{%0,%1,%2,%3}, {%4,%5,%6,%7}, {%8,%9}, {%0,%1,%2,%3};" \
        : "+f"((d)[0]), "+f"((d)[1]), "+f"((d)[2]), "+f"((d)[3]) \
        : "r"((a)[0]), "r"((a)[1]), "r"((a)[2]), "r"((a)[3]), "r"((b)[0]), "r"((b)[1]))
#define CP16(dst_u32, src_ptr) \
    asm volatile("cp.async.cg.shared.global [%0], [%1], 16;" :: "r"(dst_u32), "l"(src_ptr))
#define CP_COMMIT() asm volatile("cp.async.commit_group;")
#define CP_WAIT(n)  asm volatile("cp.async.wait_group %0;" :: "n"(n))

// ======================= scratch globals ====================================
__device__ __align__(16) __half g_x[3u * 8192u * 768u];   // xq|xk|xv fp16
__device__ __align__(16) __half g_w[4u * 768u * 768u];    // Wq|Wk|Wv|Wp fp16
__device__ __align__(16) __half g_q[8192u * 768u];        // flat [b*N+tok, c]
__device__ __align__(16) __half g_k[8192u * 768u];        // flat [b*N+tok, c]
__device__ __align__(16) __half g_vt[BH * HD * Ntok];     // [b,h,hd,tok]
__device__ __align__(16) __half g_o[8192u * 768u];        // attention out fp16
__device__ __align__(16) float g_aff[Bsz * Ntok];

// ======================= fp32 -> fp16 convert ===============================
__global__ void cvtX_kernel(const float4* __restrict__ s0, const float4* __restrict__ s1,
                            const float4* __restrict__ s2, int n4)
{
    int i = blockIdx.x * 256 + threadIdx.x;
    if (i >= n4) return;
    int z = blockIdx.z;
    const float4* src = (z == 0) ? s0 : (z == 1) ? s1 : s2;
    float4 v = src[i];
    size_t off = ((size_t)z * n4 + i) * 2;
    ((__half2*)g_x)[off]     = __floats2half2_rn(v.x, v.y);
    ((__half2*)g_x)[off + 1] = __floats2half2_rn(v.z, v.w);
}
__global__ void cvtW_kernel(const float4* __restrict__ s0, const float4* __restrict__ s1,
                            const float4* __restrict__ s2, const float4* __restrict__ s3, int n4)
{
    int i = blockIdx.x * 256 + threadIdx.x;
    if (i >= n4) return;
    int z = blockIdx.z;
    const float4* src = (z == 0) ? s0 : (z == 1) ? s1 : (z == 2) ? s2 : s3;
    float4 v = src[i];
    size_t off = ((size_t)z * n4 + i) * 2;
    ((__half2*)g_w)[off]     = __floats2half2_rn(v.x, v.y);
    ((__half2*)g_w)[off + 1] = __floats2half2_rn(v.z, v.w);
}

// ======================= single-term fp16 mma.sync GEMM (KC=64) =============
// C[128, BN] = A @ B^T. Result in SMEM stage, stride BN+1 floats. 256 threads.
template <int BN>
__device__ __forceinline__ void gemm_to_stage(
    const __half* __restrict__ A, int lda,
    const __half* __restrict__ B, int ldb,
    int kTotal, char* smem)
{
    constexpr int SROW = 72;                    // halves per row (64 + 8 pad)
    constexpr int A_0 = 0;
    constexpr int B_0 = 128 * SROW;
    constexpr int BUFH = (128 + BN) * SROW;
    constexpr int WN = BN / 2;
    constexpr int NT = BN / 16;
    constexpr int NTP = NT / 2;
    constexpr int NBJ = BN / 32;                // B CP16 per thread

    const uint32_t sbase = smem_to_u32(smem);
    const int tid = threadIdx.x, lane = tid & 31, wid = tid >> 5;
    const int wm = wid & 3, wn = wid >> 2;

    float acc[2][NT][4];
    #pragma unroll
    for (int i = 0; i < 2; i++)
        #pragma unroll
        for (int j = 0; j < NT; j++)
            #pragma unroll
            for (int l = 0; l < 4; l++) acc[i][j][l] = 0.f;

    auto CPA = [&](int buf, int k0) {
        uint32_t p = sbase + (uint32_t)buf * BUFH * 2u;
        #pragma unroll
        for (int j = 0; j < 4; j++) {
            int i = tid + j * 256, r = i >> 3, c = (i & 7) << 3;
            CP16(p + (A_0 + r * SROW + c) * 2, A + (size_t)r * lda + k0 + c);
        }
        #pragma unroll
        for (int j = 0; j < NBJ; j++) {
            int i = tid + j * 256, r = i >> 3, c = (i & 7) << 3;
            CP16(p + (B_0 + r * SROW + c) * 2, B + (size_t)r * ldb + k0 + c);
        }
        CP_COMMIT();
    };
    auto COMPUTE = [&](int buf) {
        const uint32_t base = sbase + (uint32_t)buf * BUFH * 2;
        #pragma unroll
        for (int ks = 0; ks < 64; ks += 16) {
            uint32_t af[2][4];
            const int arow = (lane & 7) + ((lane >> 3) & 1) * 8;
            const int acol = ks + (lane >> 4) * 8;
            #pragma unroll
            for (int mt = 0; mt < 2; mt++) {
                uint32_t off = (uint32_t)((wm * 32 + mt * 16 + arow) * SROW + acol) * 2;
                LDSM4(af[mt], base + A_0 * 2 + off);
            }
            uint32_t bf[NT][2];
            const int g = lane >> 3;
            const int brow = (g >> 1) * 8 + (lane & 7);
            const int bcol = ks + (g & 1) * 8;
            #pragma unroll
            for (int np = 0; np < NTP; np++) {
                uint32_t off = (uint32_t)((wn * WN + np * 16 + brow) * SROW + bcol) * 2;
                uint32_t t[4];
                LDSM4(t, base + B_0 * 2 + off);
                bf[2 * np][0] = t[0]; bf[2 * np][1] = t[1];
                bf[2 * np + 1][0] = t[2]; bf[2 * np + 1][1] = t[3];
            }
            #pragma unroll
            for (int mt = 0; mt < 2; mt++)
                #pragma unroll
                for (int nt = 0; nt < NT; nt++)
                    MMA_F16(acc[mt][nt], af[mt], bf[nt]);
        }
    };

    const int nCh = kTotal >> 6;
    CPA(0, 0);
    for (int ch = 0; ch < nCh; ch++) {
        if (ch + 1 < nCh) { CPA((ch + 1) & 1, (ch + 1) << 6); CP_WAIT(1); }
        else              { CP_WAIT(0); }
        __syncthreads();
        COMPUTE(ch & 1);
        __syncthreads();
    }

    float* stage = (float*)smem;
    const int gidr = lane >> 2, qid = lane & 3;
    #pragma unroll
    for (int mt = 0; mt < 2; mt++)
        #pragma unroll
        for (int nt = 0; nt < NT; nt++) {
            int row = wm * 32 + mt * 16 + gidr;
            int col = wn * WN + nt * 8 + qid * 2;
            stage[row * (BN + 1) + col]           = acc[mt][nt][0];
            stage[row * (BN + 1) + col + 1]       = acc[mt][nt][1];
            stage[(row + 8) * (BN + 1) + col]     = acc[mt][nt][2];
            stage[(row + 8) * (BN + 1) + col + 1] = acc[mt][nt][3];
        }
    __syncthreads();
}

// ======================= QKV projection (zoff selects q/k vs v) =============
__global__ void __launch_bounds__(256, 2) qkv_mma(int zoff)
{
    extern __shared__ char smem[];
    const int z = blockIdx.z + zoff;
    const int m0 = blockIdx.y * 128, n0 = blockIdx.x * 128;

    const __half* A = g_x + (size_t)z * 8192 * 768 + (size_t)m0 * 768;
    const __half* B = g_w + (size_t)z * 768 * 768 + (size_t)n0 * 768;

    gemm_to_stage<128>(A, 768, B, 768, 768, smem);
    float* stage = (float*)smem;

    const int tid = threadIdx.x;
    if (z < 2) {
        __half* dst = (z == 0) ? g_q : g_k;
        for (int idx = tid; idx < 128 * 64; idx += 256) {
            int mr = idx >> 6, nc = (idx & 63) * 2;
            *(__half2*)(dst + (size_t)(m0 + mr) * 768 + n0 + nc) =
                __floats2half2_rn(stage[mr * 129 + nc], stage[mr * 129 + nc + 1]);
        }
    } else {
        for (int idx = tid; idx < 128 * 64; idx += 256) {
            int t2 = idx & 63, nc = idx >> 6;
            int mr = t2 * 2;
            int m = m0 + mr, n = n0 + nc;
            int b = m >> 10, tok = m & 1023, h = n >> 6, hd = n & 63;
            size_t o = (((size_t)(b * Hh + h)) * HD + hd) * Ntok + tok;
            *(__half2*)(g_vt + o) =
                __floats2half2_rn(stage[mr * 129 + nc], stage[(mr + 1) * 129 + nc]);
        }
    }
}

// ======================= affinity gate ======================================
__global__ void aff_kernel(const float* __restrict__ et, float* __restrict__ out_aff)
{
    int warp = (blockIdx.x * blockDim.x + threadIdx.x) >> 5;
    int lane = threadIdx.x & 31;
    if (warp >= Bsz * Ntok) return;
    int b = warp >> 10;
    float s = 0.f;
    const __half* krow = g_k + (size_t)warp * 768;
    const float* erow = et + b * Cdim;
    for (int c = lane; c < Cdim; c += 32)
        s += erow[c] * __half2float(krow[c]);
    #pragma unroll
    for (int o = 16; o; o >>= 1) s += __shfl_xor_sync(0xffffffffu, s, o);
    if (lane == 0) {
        float v = 1.f / (1.f + __expf(-(SCALE / Hh) * s));
        g_aff[warp] = v;
        out_aff[warp] = v;
    }
}

// ======================= attn_save = (SCALE/H) * Qflat @ Kflat^T ============
__global__ void __launch_bounds__(256, 2) attnsave_mma(float* __restrict__ out_as)
{
    extern __shared__ char smem[];
    const int b = blockIdx.z;
    const int m0 = blockIdx.y * 128, n0 = blockIdx.x * 128;

    const __half* A = g_q + ((size_t)b * 1024 + m0) * 768;
    const __half* B = g_k + ((size_t)b * 1024 + n0) * 768;

    gemm_to_stage<128>(A, 768, B, 768, 768, smem);
    float* stage = (float*)smem;

    const float sc = SCALE / Hh;
    for (int idx = threadIdx.x; idx < 128 * 128; idx += 256) {
        int mr = idx >> 7, nc = idx & 127;
        out_as[((size_t)b * 1024 + m0 + mr) * 1024 + n0 + nc] = stage[mr * 129 + nc] * sc;
    }
}

// ======================= flash attention: S in-CTA, exp, PV =================
__global__ void __launch_bounds__(256, 2) flash_fused()
{
    extern __shared__ char smem[];
    constexpr int SRQ = 72;
    constexpr int SRP = 136;
    constexpr uint32_t Q_0 = 0;
    constexpr uint32_t K_0 = 9216;
    constexpr uint32_t KBUF = 128u * SRQ * 2u;
    constexpr uint32_t V_0 = 46080;
    constexpr uint32_t P_0 = 63488;
    constexpr uint32_t RS0 = 80896;

    const uint32_t sbase = smem_to_u32(smem);
    __half* P_s = (__half*)(smem + P_0);
    float* rowsum_s = (float*)(smem + RS0);

    const int z = blockIdx.y;
    const int m0 = blockIdx.x * 64;
    const int b = z / Hh, h = z % Hh;
    const int tid = threadIdx.x, lane = tid & 31, wid = tid >> 5;
    const int gidr = lane >> 2, qid = lane & 3;
    const int wmS = wid & 1, wnS = wid >> 1;
    const int wm2 = wid & 1, wn2 = wid >> 1;

    const __half* Qg = g_q + ((size_t)b * 1024 + m0) * 768 + h * 64;
    const __half* Kg = g_k + (size_t)b * 1024 * 768 + h * 64;
    const __half* Vg = g_vt + (size_t)z * HD * Ntok;
    const float* aff = g_aff + b * 1024;

    {
        int i = tid, r = i >> 3, c = (i & 7) << 3;
        CP16(sbase + Q_0 + (uint32_t)(r * SRQ + c) * 2, Qg + (size_t)r * 768 + c);
        i = tid + 256; r = i >> 3; c = (i & 7) << 3;
        CP16(sbase + Q_0 + (uint32_t)(r * SRQ + c) * 2, Qg + (size_t)r * 768 + c);
    }
    #pragma unroll
    for (int j = 0; j < 4; j++) {
        int i = tid + j * 256, r = i >> 3, c = (i & 7) << 3;
        CP16(sbase + K_0 + (uint32_t)(r * SRQ + c) * 2, Kg + (size_t)r * 768 + c);
    }
    #pragma unroll
    for (int j = 0; j < 4; j++) {
        int i = tid + j * 256, r = i >> 4, c = (i & 15) << 3;
        CP16(sbase + V_0 + (uint32_t)(r * SRP + c) * 2, Vg + (size_t)r * 1024 + c);
    }
    CP_COMMIT();
    if (tid < 64) rowsum_s[tid] = 0.f;

    float acc_o[2][2][4];
    #pragma unroll
    for (int i = 0; i < 2; i++)
        #pragma unroll
        for (int j = 0; j < 2; j++)
            #pragma unroll
            for (int l = 0; l < 4; l++) acc_o[i][j][l] = 0.f;

    for (int ch = 0; ch < 8; ch++) {
        const int k0 = ch * 128;
        const int kb = ch & 1;
        CP_WAIT(0);
        __syncthreads();

        if (ch + 1 < 8) {
            #pragma unroll
            for (int j = 0; j < 4; j++) {
                int i = tid + j * 256, r = i >> 3, c = (i & 7) << 3;
                CP16(sbase + K_0 + (kb ^ 1) * KBUF + (uint32_t)(r * SRQ + c) * 2,
                     Kg + (size_t)(k0 + 128 + r) * 768 + c);
            }
            CP_COMMIT();
        }

        float acc_s[2][4][4];
        #pragma unroll
        for (int i = 0; i < 2; i++)
            #pragma unroll
            for (int j = 0; j < 4; j++)
                #pragma unroll
                for (int l = 0; l < 4; l++) acc_s[i][j][l] = 0.f;

        const uint32_t kbase = sbase + K_0 + kb * KBUF;
        #pragma unroll
        for (int ks = 0; ks < 64; ks += 16) {
            uint32_t af[2][4];
            const int arow = (lane & 7) + ((lane >> 3) & 1) * 8;
            const int acol = ks + (lane >> 4) * 8;
            #pragma unroll
            for (int mt = 0; mt < 2; mt++) {
                uint32_t off = (uint32_t)((wmS * 32 + mt * 16 + arow) * SRQ + acol) * 2;
                LDSM4(af[mt], sbase + Q_0 + off);
            }
            uint32_t bf[4][2];
            const int g = lane >> 3;
            const int brow = (g >> 1) * 8 + (lane & 7);
            const int bcol = ks + (g & 1) * 8;
            #pragma unroll
            for (int np = 0; np < 2; np++) {
                uint32_t off = (uint32_t)((wnS * 32 + np * 16 + brow) * SRQ + bcol) * 2;
                uint32_t t[4];
                LDSM4(t, kbase + off);
                bf[2 * np][0] = t[0]; bf[2 * np][1] = t[1];
                bf[2 * np + 1][0] = t[2]; bf[2 * np + 1][1] = t[3];
            }
            #pragma unroll
            for (int mt = 0; mt < 2; mt++)
                #pragma unroll
                for (int nt = 0; nt < 4; nt++)
                    MMA_F16(acc_s[mt][nt], af[mt], bf[nt]);
        }

        float2 af2[4];
        #pragma unroll
        for (int nt = 0; nt < 4; nt++)
            af2[nt] = *(const float2*)(aff + k0 + wnS * 32 + nt * 8 + qid * 2);
        #pragma unroll
        for (int mt = 0; mt < 2; mt++) {
            int row0 = wmS * 32 + mt * 16 + gidr;
            float rs0 = 0.f, rs1 = 0.f;
            #pragma unroll
            for (int nt = 0; nt < 4; nt++) {
                float e0 = __expf(acc_s[mt][nt][0] * SCALE);
                float e1 = __expf(acc_s[mt][nt][1] * SCALE);
                float e2 = __expf(acc_s[mt][nt][2] * SCALE);
                float e3 = __expf(acc_s[mt][nt][3] * SCALE);
                rs0 += e0 + e1; rs1 += e2 + e3;
                int col = wnS * 32 + nt * 8 + qid * 2;
                *(__half2*)(P_s + row0 * SRP + col)       = __floats2half2_rn(e0 * af2[nt].x, e1 * af2[nt].y);
                *(__half2*)(P_s + (row0 + 8) * SRP + col) = __floats2half2_rn(e2 * af2[nt].x, e3 * af2[nt].y);
            }
            rs0 += __shfl_xor_sync(0xffffffffu, rs0, 1);
            rs0 += __shfl_xor_sync(0xffffffffu, rs0, 2);
            rs1 += __shfl_xor_sync(0xffffffffu, rs1, 1);
            rs1 += __shfl_xor_sync(0xffffffffu, rs1, 2);
            if (qid == 0) {
                atomicAdd(&rowsum_s[row0], rs0);
                atomicAdd(&rowsum_s[row0 + 8], rs1);
            }
        }
        __syncthreads();

        #pragma unroll
        for (int ks = 0; ks < 128; ks += 16) {
            uint32_t af[2][4];
            const int arow = (lane & 7) + ((lane >> 3) & 1) * 8;
            const int acol = ks + (lane >> 4) * 8;
            #pragma unroll
            for (int mt = 0; mt < 2; mt++) {
                uint32_t off = (uint32_t)((wm2 * 32 + mt * 16 + arow) * SRP + acol) * 2;
                LDSM4(af[mt], sbase + P_0 + off);
            }
            uint32_t bf[2][2];
            const int g = lane >> 3;
            const int brow = (g >> 1) * 8 + (lane & 7);
            const int bcol = ks + (g & 1) * 8;
            {
                uint32_t off = (uint32_t)((wn2 * 16 + brow) * SRP + bcol) * 2;
                uint32_t t[4];
                LDSM4(t, sbase + V_0 + off);
                bf[0][0] = t[0]; bf[0][1] = t[1]; bf[1][0] = t[2]; bf[1][1] = t[3];
            }
            #pragma unroll
            for (int mt = 0; mt < 2; mt++)
                #pragma unroll
                for (int nt = 0; nt < 2; nt++)
                    MMA_F16(acc_o[mt][nt], af[mt], bf[nt]);
        }
        __syncthreads();

        if (ch + 1 < 8) {
            #pragma unroll
            for (int j = 0; j < 4; j++) {
                int i = tid + j * 256, r = i >> 4, c = (i & 15) << 3;
                CP16(sbase + V_0 + (uint32_t)(r * SRP + c) * 2, Vg + (size_t)r * 1024 + k0 + 128 + c);
            }
            CP_COMMIT();
        }
    }

    #pragma unroll
    for (int mt = 0; mt < 2; mt++) {
        int row = wm2 * 32 + mt * 16 + gidr;
        float inv0 = 1.f / rowsum_s[row];
        float inv8 = 1.f / rowsum_s[row + 8];
        #pragma unroll
        for (int nt = 0; nt < 2; nt++) {
            int col = wn2 * 16 + nt * 8 + qid * 2;
            size_t o0 = ((size_t)b * 1024 + m0 + row) * 768 + h * 64 + col;
            size_t o8 = o0 + 8u * 768u;
            *(__half2*)(g_o + o0) = __floats2half2_rn(acc_o[mt][nt][0] * inv0, acc_o[mt][nt][1] * inv0);
            *(__half2*)(g_o + o8) = __floats2half2_rn(acc_o[mt][nt][2] * inv8, acc_o[mt][nt][3] * inv8);
        }
    }
}

// ======================= output projection ==================================
__global__ void __launch_bounds__(256, 2) proj_mma(const float* __restrict__ bp,
                                                   float* __restrict__ out)
{
    extern __shared__ char smem[];
    const int m0 = blockIdx.y * 128, n0 = blockIdx.x * 128;

    const __half* A = g_o + (size_t)m0 * 768;
    const __half* B = g_w + (size_t)3 * 768 * 768 + (size_t)n0 * 768;

    gemm_to_stage<128>(A, 768, B, 768, 768, smem);
    float* stage = (float*)smem;

    for (int idx = threadIdx.x; idx < 128 * 128; idx += 256) {
        int mr = idx >> 7, nc = idx & 127;
        int n = n0 + nc;
        out[(size_t)(m0 + mr) * Cdim + n] = stage[mr * 129 + nc] + bp[n];
    }
}

// ============================================================================
extern "C" void kernel_launch(void* const* d_in, const int* in_sizes, int n_in,
                              void* d_out, int out_size)
{
    (void)in_sizes; (void)n_in; (void)out_size;
    const float* xq = (const float*)d_in[0];
    const float* xk = (const float*)d_in[1];
    const float* xv = (const float*)d_in[2];
    const float* et = (const float*)d_in[3];
    const float* Wq = (const float*)d_in[4];
    const float* Wk = (const float*)d_in[5];
    const float* Wv = (const float*)d_in[6];
    const float* Wp = (const float*)d_in[7];
    const float* bp = (const float*)d_in[8];

    float* out     = (float*)d_out;
    float* out_x   = out;
    float* out_as  = out + (size_t)Bsz * Ntok * Cdim;
    float* out_aff = out_as + (size_t)Bsz * Ntok * Ntok;

    const int SMEM_BIG = 73728;   // 2 x (128+128)*72*2 bufs; stage 66048 fits
    const int SMEM_FLASH = 81152;
    cudaFuncSetAttribute(qkv_mma,      cudaFuncAttributeMaxDynamicSharedMemorySize, SMEM_BIG);
    cudaFuncSetAttribute(attnsave_mma, cudaFuncAttributeMaxDynamicSharedMemorySize, SMEM_BIG);
    cudaFuncSetAttribute(flash_fused,  cudaFuncAttributeMaxDynamicSharedMemorySize, SMEM_FLASH);
    cudaFuncSetAttribute(proj_mma,     cudaFuncAttributeMaxDynamicSharedMemorySize, SMEM_BIG);

    static cudaStream_t s1 = nullptr;
    static cudaEvent_t eQK = nullptr, eAff = nullptr, eA = nullptr;
    if (!s1) {
        cudaStreamCreateWithFlags(&s1, cudaStreamNonBlocking);
        cudaEventCreateWithFlags(&eQK, cudaEventDisableTiming);
        cudaEventCreateWithFlags(&eAff, cudaEventDisableTiming);
        cudaEventCreateWithFlags(&eA, cudaEventDisableTiming);
    }

    const int NX4 = 8192 * 768 / 4, NW4 = 768 * 768 / 4;
    cvtX_kernel<<<dim3((NX4 + 255) / 256, 1, 3), 256>>>((const float4*)xq, (const float4*)xk,
                                                        (const float4*)xv, NX4);
    cvtW_kernel<<<dim3((NW4 + 255) / 256, 1, 4), 256>>>((const float4*)Wq, (const float4*)Wk,
                                                        (const float4*)Wv, (const float4*)Wp, NW4);

    // q,k projections first
    qkv_mma<<<dim3(6, 64, 2), 256, SMEM_BIG>>>(0);
    cudaEventRecord(eQK, 0);

    // side stream: aff (needed by flash) then attnsave (independent)
    cudaStreamWaitEvent(s1, eQK, 0);
    aff_kernel<<<(Bsz * Ntok) / 8, 256, 0, s1>>>(et, out_aff);
    cudaEventRecord(eAff, s1);
    attnsave_mma<<<dim3(8, 8, Bsz), 256, SMEM_BIG, s1>>>(out_as);
    cudaEventRecord(eA, s1);

    // main stream: v projection overlaps aff/attnsave
    qkv_mma<<<dim3(6, 64, 1), 256, SMEM_BIG>>>(2);
    cudaStreamWaitEvent(0, eAff, 0);
    flash_fused<<<dim3(16, BH), 256, SMEM_FLASH>>>();
    proj_mma<<<dim3(6, 64, 1), 256, SMEM_BIG>>>(bp, out_x);

    cudaStreamWaitEvent(0, eA, 0);
}